// round 1
// baseline (speedup 1.0000x reference)
#include <cuda_runtime.h>
#include <math.h>

#define BSZ     2
#define SEQ     512
#define DMODEL  768
#define DINNER  1536
#define DSTATE  64
#define NHEADS  24
#define HEADDIM 64
#define CONVDIM 1664            // DINNER + 2*DSTATE
#define DINPROJ 3224            // 2*DINNER + 2*DSTATE + NHEADS
#define NTOK    (BSZ*SEQ)       // 1024
#define DFF     3072
#define LN_EPS  1e-5f

// ---------------- scratch (static device globals; no allocation) ----------------
__device__ float g_xn  [NTOK*DMODEL];
__device__ float g_zx  [NTOK*DINPROJ];
__device__ float g_xBC [2*NTOK*CONVDIM];
__device__ float g_dt  [NTOK*NHEADS];
__device__ float g_dA  [NTOK*NHEADS];
__device__ float g_y   [2*NTOK*DINNER];
__device__ float g_gsum[NTOK*DINNER];
__device__ float g_s   [NTOK*DMODEL];
__device__ float g_m   [NTOK*DMODEL];
__device__ float g_ff1 [NTOK*DFF];

// ---------------- block reduce (256 threads, two values) ----------------
__device__ __forceinline__ void blockReduce2_256(float& a, float& b) {
    __shared__ float sa[8], sb[8];
    #pragma unroll
    for (int o = 16; o > 0; o >>= 1) {
        a += __shfl_xor_sync(0xffffffffu, a, o);
        b += __shfl_xor_sync(0xffffffffu, b, o);
    }
    int w = threadIdx.x >> 5, l = threadIdx.x & 31;
    if (l == 0) { sa[w] = a; sb[w] = b; }
    __syncthreads();
    if (w == 0) {
        a = (l < 8) ? sa[l] : 0.f;
        b = (l < 8) ? sb[l] : 0.f;
        #pragma unroll
        for (int o = 4; o > 0; o >>= 1) {
            a += __shfl_xor_sync(0xffffffffu, a, o);
            b += __shfl_xor_sync(0xffffffffu, b, o);
        }
        if (l == 0) { sa[0] = a; sb[0] = b; }
    }
    __syncthreads();
    a = sa[0]; b = sb[0];
}

// ---------------- layernorm: one block per row ----------------
__global__ void ln_kernel(const float* __restrict__ x, const float* __restrict__ w,
                          const float* __restrict__ b, float* __restrict__ out, int D) {
    int row = blockIdx.x;
    const float* xr = x + (size_t)row * D;
    float s = 0.f, ss = 0.f;
    for (int c = threadIdx.x; c < D; c += 256) { float v = xr[c]; s += v; ss += v * v; }
    blockReduce2_256(s, ss);
    float mean = s / D;
    float var  = ss / D - mean * mean;
    float r = rsqrtf(var + LN_EPS);
    float* orow = out + (size_t)row * D;
    for (int c = threadIdx.x; c < D; c += 256)
        orow[c] = (xr[c] - mean) * r * w[c] + b[c];
}

// ---------------- GEMM: C[M,N] = A[M,K] @ B[N,K]^T (+bias, act, +resid) ----------------
// act: 0 = none, 1 = exact GELU
#define BM 128
#define BN 128
#define BK 8
__global__ __launch_bounds__(256) void gemm_tn(
    const float* __restrict__ A, const float* __restrict__ B, float* __restrict__ C,
    int M, int N, int K,
    const float* __restrict__ bias, const float* __restrict__ resid, int act)
{
    __shared__ float As[BK][BM];
    __shared__ float Bs[BK][BN];
    int tid = threadIdx.x;
    int m0 = blockIdx.y * BM, n0 = blockIdx.x * BN;
    int tx = tid & 15, ty = tid >> 4;
    int lRow = tid >> 1;            // 0..127
    int lK   = (tid & 1) * 4;       // 0 or 4

    bool bValid = (n0 + lRow) < N;
    const float* Aptr = A + (size_t)(m0 + lRow) * K + lK;
    const float* Bptr = B + (size_t)(bValid ? (n0 + lRow) : 0) * K + lK;

    float4 aReg = *(const float4*)Aptr;
    float4 bReg = bValid ? *(const float4*)Bptr : make_float4(0.f, 0.f, 0.f, 0.f);

    float acc[8][8];
    #pragma unroll
    for (int i = 0; i < 8; i++)
        #pragma unroll
        for (int j = 0; j < 8; j++) acc[i][j] = 0.f;

    int KT = K / BK;
    for (int kt = 0; kt < KT; kt++) {
        As[lK + 0][lRow] = aReg.x; As[lK + 1][lRow] = aReg.y;
        As[lK + 2][lRow] = aReg.z; As[lK + 3][lRow] = aReg.w;
        Bs[lK + 0][lRow] = bReg.x; Bs[lK + 1][lRow] = bReg.y;
        Bs[lK + 2][lRow] = bReg.z; Bs[lK + 3][lRow] = bReg.w;
        __syncthreads();
        if (kt + 1 < KT) {
            aReg = *(const float4*)(Aptr + (size_t)(kt + 1) * BK);
            bReg = bValid ? *(const float4*)(Bptr + (size_t)(kt + 1) * BK)
                          : make_float4(0.f, 0.f, 0.f, 0.f);
        }
        #pragma unroll
        for (int k = 0; k < BK; k++) {
            float4 a0 = *(const float4*)&As[k][ty * 8];
            float4 a1 = *(const float4*)&As[k][ty * 8 + 4];
            float4 b0 = *(const float4*)&Bs[k][tx * 8];
            float4 b1 = *(const float4*)&Bs[k][tx * 8 + 4];
            float av[8] = {a0.x, a0.y, a0.z, a0.w, a1.x, a1.y, a1.z, a1.w};
            float bv[8] = {b0.x, b0.y, b0.z, b0.w, b1.x, b1.y, b1.z, b1.w};
            #pragma unroll
            for (int i = 0; i < 8; i++)
                #pragma unroll
                for (int j = 0; j < 8; j++)
                    acc[i][j] = fmaf(av[i], bv[j], acc[i][j]);
        }
        __syncthreads();
    }

    #pragma unroll
    for (int i = 0; i < 8; i++) {
        int m = m0 + ty * 8 + i;
        #pragma unroll
        for (int j = 0; j < 8; j++) {
            int n = n0 + tx * 8 + j;
            if (n < N) {
                float v = acc[i][j];
                if (bias)  v += bias[n];
                if (act == 1) v = 0.5f * v * (1.f + erff(v * 0.70710678118654752f));
                if (resid) v += resid[(size_t)m * N + n];
                C[(size_t)m * N + n] = v;
            }
        }
    }
}

// ---------------- dt / dA (shared between directions) ----------------
__global__ void dtproc_kernel(const float* __restrict__ dt_bias,
                              const float* __restrict__ A_log) {
    int idx = blockIdx.x * blockDim.x + threadIdx.x;
    if (idx >= NTOK * NHEADS) return;
    int row = idx / NHEADS, h = idx % NHEADS;
    float x = g_zx[(size_t)row * DINPROJ + (2 * DINNER + 2 * DSTATE - DINNER) + 0]; // placeholder; real below
    // dt raw lives at channel [DINNER + CONVDIM + h] = [3200 + h]
    x = g_zx[(size_t)row * DINPROJ + DINNER + CONVDIM + h] + dt_bias[h];
    float sp = (x > 20.f) ? x : log1pf(expf(x));
    g_dt[idx] = sp;
    g_dA[idx] = expf(-expf(A_log[h]) * sp);
}

// ---------------- conv (causal fwd / anti-causal bwd) + SiLU ----------------
__global__ void conv_silu_kernel(const float* __restrict__ w, const float* __restrict__ cb) {
    int idx = blockIdx.x * blockDim.x + threadIdx.x;
    if (idx >= 2 * NTOK * CONVDIM) return;
    int c   = idx % CONVDIM;
    int rem = idx / CONVDIM;       // dir*NTOK + row
    int row = rem % NTOK;
    int dir = rem / NTOK;
    int t = row % SEQ, b = row / SEQ;
    const float* base = g_zx + (size_t)(b * SEQ) * DINPROJ + DINNER + c;
    float s = cb[c];
    #pragma unroll
    for (int k = 0; k < 4; k++) {
        int tt = (dir == 0) ? (t - 3 + k) : (t + 3 - k);
        if (tt >= 0 && tt < SEQ)
            s = fmaf(w[c * 4 + k], base[(size_t)tt * DINPROJ], s);
    }
    g_xBC[idx] = s / (1.f + expf(-s));
}

// ---------------- selective scan: one block per (h, b, dir) ----------------
__global__ __launch_bounds__(256) void scan_kernel(const float* __restrict__ D_param) {
    int h = blockIdx.x, b = blockIdx.y, dir = blockIdx.z;
    const float* xbc  = g_xBC + (size_t)(dir * NTOK + b * SEQ) * CONVDIM;
    float*       yout = g_y   + (size_t)(dir * NTOK + b * SEQ) * DINNER;
    int tid = threadIdx.x;
    int p = tid >> 2, q = tid & 3, nbase = q * 16;

    __shared__ float sx[64], sB[64], sC[64], sscal[2];

    float hreg[16];
    #pragma unroll
    for (int i = 0; i < 16; i++) hreg[i] = 0.f;
    float Dp = D_param[h];

    // stage first timestep into a register (role-based)
    auto load_for = [&](int t) -> float {
        const float* r = xbc + (size_t)t * CONVDIM;
        if (tid < 64)        return r[h * 64 + tid];
        else if (tid < 128)  return r[DINNER + (tid - 64)];
        else if (tid < 192)  return r[DINNER + DSTATE + (tid - 128)];
        else if (tid == 192) return g_dt[(size_t)(b * SEQ + t) * NHEADS + h];
        else if (tid == 193) return g_dA[(size_t)(b * SEQ + t) * NHEADS + h];
        return 0.f;
    };

    float staged = load_for(dir ? (SEQ - 1) : 0);

    for (int s = 0; s < SEQ; s++) {
        int t = dir ? (SEQ - 1 - s) : s;
        if (tid < 64)        sx[tid]       = staged;
        else if (tid < 128)  sB[tid - 64]  = staged;
        else if (tid < 192)  sC[tid - 128] = staged;
        else if (tid == 192) sscal[0]      = staged;
        else if (tid == 193) sscal[1]      = staged;
        __syncthreads();
        if (s + 1 < SEQ) staged = load_for(dir ? (SEQ - 2 - s) : (s + 1));

        float xp  = sx[p];
        float dtv = sscal[0];
        float dAv = sscal[1];
        float bx  = dtv * xp;
        float acc = 0.f;
        #pragma unroll
        for (int i = 0; i < 16; i++) {
            int n = nbase + i;
            hreg[i] = fmaf(dAv, hreg[i], bx * sB[n]);
            acc = fmaf(hreg[i], sC[n], acc);
        }
        acc += __shfl_xor_sync(0xffffffffu, acc, 1);
        acc += __shfl_xor_sync(0xffffffffu, acc, 2);
        if (q == 0) yout[(size_t)t * DINNER + h * 64 + p] = fmaf(Dp, xp, acc);
        __syncthreads();
    }
}

// ---------------- gate with SiLU(z), per-direction RMSNorm, sum dirs ----------------
__global__ void gate_rms_kernel(const float* __restrict__ norm_w) {
    int row = blockIdx.x;
    __shared__ float gf[DINNER];
    __shared__ float gb[DINNER];
    const float* zr = g_zx + (size_t)row * DINPROJ;           // z = channels [0,1536)
    const float* yf = g_y  + (size_t)row * DINNER;
    const float* yb = g_y  + (size_t)(NTOK + row) * DINNER;
    float ssf = 0.f, ssb = 0.f;
    for (int c = threadIdx.x; c < DINNER; c += 256) {
        float zc = zr[c];
        float sz = zc / (1.f + expf(-zc));
        float a  = yf[c] * sz;
        float bb = yb[c] * sz;
        gf[c] = a; gb[c] = bb;
        ssf += a * a; ssb += bb * bb;
    }
    blockReduce2_256(ssf, ssb);
    float rf = rsqrtf(ssf / DINNER + LN_EPS);
    float rb = rsqrtf(ssb / DINNER + LN_EPS);
    float* orow = g_gsum + (size_t)row * DINNER;
    for (int c = threadIdx.x; c < DINNER; c += 256)
        orow[c] = (gf[c] * rf + gb[c] * rb) * norm_w[c];
}

// ---------------- launch ----------------
extern "C" void kernel_launch(void* const* d_in, const int* in_sizes, int n_in,
                              void* d_out, int out_size) {
    const float* x         = (const float*)d_in[0];
    const float* in_proj_w = (const float*)d_in[1];
    const float* conv_w    = (const float*)d_in[2];
    const float* conv_b    = (const float*)d_in[3];
    const float* dt_bias   = (const float*)d_in[4];
    const float* A_log     = (const float*)d_in[5];
    const float* D_param   = (const float*)d_in[6];
    const float* norm_w    = (const float*)d_in[7];
    const float* out_proj_w= (const float*)d_in[8];
    const float* ln1_w     = (const float*)d_in[9];
    const float* ln1_b     = (const float*)d_in[10];
    const float* ln2_w     = (const float*)d_in[11];
    const float* ln2_b     = (const float*)d_in[12];
    const float* ff_w1     = (const float*)d_in[13];
    const float* ff_b1     = (const float*)d_in[14];
    const float* ff_w2     = (const float*)d_in[15];
    const float* ff_b2     = (const float*)d_in[16];
    float* out = (float*)d_out;

    void *p_xn, *p_zx, *p_gsum, *p_s, *p_m, *p_ff1;
    cudaGetSymbolAddress(&p_xn,   g_xn);
    cudaGetSymbolAddress(&p_zx,   g_zx);
    cudaGetSymbolAddress(&p_gsum, g_gsum);
    cudaGetSymbolAddress(&p_s,    g_s);
    cudaGetSymbolAddress(&p_m,    g_m);
    cudaGetSymbolAddress(&p_ff1,  g_ff1);

    // 1) LN1
    ln_kernel<<<NTOK, 256>>>(x, ln1_w, ln1_b, (float*)p_xn, DMODEL);

    // 2) in_proj GEMM (shared between directions): (1024,768)x(3224,768)^T
    gemm_tn<<<dim3((DINPROJ + BN - 1) / BN, NTOK / BM), 256>>>(
        (const float*)p_xn, in_proj_w, (float*)p_zx,
        NTOK, DINPROJ, DMODEL, nullptr, nullptr, 0);

    // 3) dt / dA
    dtproc_kernel<<<(NTOK * NHEADS + 255) / 256, 256>>>(dt_bias, A_log);

    // 4) conv + SiLU for both directions
    conv_silu_kernel<<<(2 * NTOK * CONVDIM + 255) / 256, 256>>>(conv_w, conv_b);

    // 5) selective scan (both directions)
    scan_kernel<<<dim3(NHEADS, BSZ, 2), 256>>>(D_param);

    // 6) gate + RMSNorm + direction-sum
    gate_rms_kernel<<<NTOK, 256>>>(norm_w);

    // 7) out_proj GEMM: (1024,1536)x(768,1536)^T
    gemm_tn<<<dim3(DMODEL / BN, NTOK / BM), 256>>>(
        (const float*)p_gsum, out_proj_w, (float*)p_s,
        NTOK, DMODEL, DINNER, nullptr, nullptr, 0);

    // 8) LN2
    ln_kernel<<<NTOK, 256>>>((const float*)p_s, ln2_w, ln2_b, (float*)p_m, DMODEL);

    // 9) FF1 + GELU: (1024,768)x(3072,768)^T
    gemm_tn<<<dim3(DFF / BN, NTOK / BM), 256>>>(
        (const float*)p_m, ff_w1, (float*)p_ff1,
        NTOK, DFF, DMODEL, ff_b1, nullptr, 1);

    // 10) FF2 + bias + residual -> out: (1024,3072)x(768,3072)^T
    gemm_tn<<<dim3(DMODEL / BN, NTOK / BM), 256>>>(
        (const float*)p_ff1, ff_w2, out,
        NTOK, DMODEL, DFF, ff_b2, x, 0);
}

// round 2
// speedup vs baseline: 2.8892x; 2.8892x over previous
#include <cuda_runtime.h>
#include <cuda_fp16.h>
#include <math.h>
#include <stdint.h>

#define BSZ     2
#define SEQ     512
#define DMODEL  768
#define DINNER  1536
#define DSTATE  64
#define NHEADS  24
#define HEADDIM 64
#define CONVDIM 1664            // DINNER + 2*DSTATE
#define DINPROJ 3224            // 2*DINNER + 2*DSTATE + NHEADS
#define NTOK    (BSZ*SEQ)       // 1024
#define DFF     3072
#define LN_EPS  1e-5f

// ---------------- scratch (static device globals; no allocation) ----------------
__device__ float  g_zx  [NTOK*DINPROJ];
__device__ float  g_xBC [2*NTOK*CONVDIM];
__device__ float  g_dt  [NTOK*NHEADS];
__device__ float  g_dA  [NTOK*NHEADS];
__device__ float  g_y   [2*NTOK*DINNER];
__device__ float  g_s   [NTOK*DMODEL];
// fp16 activations / weights
__device__ __half g_xnh   [NTOK*DMODEL];
__device__ __half g_gsumh [NTOK*DINNER];
__device__ __half g_mh    [NTOK*DMODEL];
__device__ __half g_ff1h  [NTOK*DFF];
__device__ __half g_w_inproj_h [DINPROJ*DMODEL];
__device__ __half g_w_outproj_h[DMODEL*DINNER];
__device__ __half g_w_ff1_h    [DFF*DMODEL];
__device__ __half g_w_ff2_h    [DMODEL*DFF];

// ---------------- helpers ----------------
__device__ __forceinline__ uint32_t sptr(const void* p) {
    return (uint32_t)__cvta_generic_to_shared(p);
}
__device__ __forceinline__ void ldsm4(uint32_t* r, uint32_t addr) {
    asm volatile("ldmatrix.sync.aligned.m8n8.x4.shared.b16 {%0,%1,%2,%3}, [%4];"
                 : "=r"(r[0]), "=r"(r[1]), "=r"(r[2]), "=r"(r[3]) : "r"(addr));
}
__device__ __forceinline__ void mma16816(float* c, const uint32_t* a, const uint32_t* b) {
    asm volatile("mma.sync.aligned.m16n8k16.row.col.f32.f16.f16.f32 "
                 "{%0,%1,%2,%3}, {%4,%5,%6,%7}, {%8,%9}, {%0,%1,%2,%3};"
                 : "+f"(c[0]), "+f"(c[1]), "+f"(c[2]), "+f"(c[3])
                 : "r"(a[0]), "r"(a[1]), "r"(a[2]), "r"(a[3]), "r"(b[0]), "r"(b[1]));
}

// ---------------- fp32 -> fp16 convert ----------------
__global__ void f2h_kernel(const float* __restrict__ in, __half* __restrict__ out, int n2) {
    int i = blockIdx.x * blockDim.x + threadIdx.x;
    if (i < n2) {
        float2 v = ((const float2*)in)[i];
        ((__half2*)out)[i] = __floats2half2_rn(v.x, v.y);
    }
}

// ---------------- block reduce (256 threads, two values) ----------------
__device__ __forceinline__ void blockReduce2_256(float& a, float& b) {
    __shared__ float sa[8], sb[8];
    #pragma unroll
    for (int o = 16; o > 0; o >>= 1) {
        a += __shfl_xor_sync(0xffffffffu, a, o);
        b += __shfl_xor_sync(0xffffffffu, b, o);
    }
    int w = threadIdx.x >> 5, l = threadIdx.x & 31;
    if (l == 0) { sa[w] = a; sb[w] = b; }
    __syncthreads();
    if (w == 0) {
        a = (l < 8) ? sa[l] : 0.f;
        b = (l < 8) ? sb[l] : 0.f;
        #pragma unroll
        for (int o = 4; o > 0; o >>= 1) {
            a += __shfl_xor_sync(0xffffffffu, a, o);
            b += __shfl_xor_sync(0xffffffffu, b, o);
        }
        if (l == 0) { sa[0] = a; sb[0] = b; }
    }
    __syncthreads();
    a = sa[0]; b = sb[0];
}

// ---------------- layernorm (fp32 in, fp16 out) ----------------
__global__ void ln_kernel(const float* __restrict__ x, const float* __restrict__ w,
                          const float* __restrict__ b, __half* __restrict__ out, int D) {
    int row = blockIdx.x;
    const float* xr = x + (size_t)row * D;
    float s = 0.f, ss = 0.f;
    for (int c = threadIdx.x; c < D; c += 256) { float v = xr[c]; s += v; ss += v * v; }
    blockReduce2_256(s, ss);
    float mean = s / D;
    float var  = ss / D - mean * mean;
    float r = rsqrtf(var + LN_EPS);
    __half* orow = out + (size_t)row * D;
    for (int c = threadIdx.x; c < D; c += 256)
        orow[c] = __float2half((xr[c] - mean) * r * w[c] + b[c]);
}

// ---------------- fp16 tensor-core GEMM: C[M,N] = A[M,K] @ B[N,K]^T ----------------
// 128x128 block tile, BK=32, 8 warps (2x4), warp tile 64x32, m16n8k16 HMMA.
// Epilogue: optional bias, exact GELU (act==1), residual add; optional fp32 and
// fp16 outputs.
#define SSTR 40   // padded half stride per smem row (32 data + 8 pad)
__global__ __launch_bounds__(256) void hgemm(
    const __half* __restrict__ A, const __half* __restrict__ B,
    int M, int N, int K,
    float* __restrict__ Cf, __half* __restrict__ Ch,
    const float* __restrict__ bias, const float* __restrict__ resid, int act)
{
    __shared__ __half As[2][128 * SSTR];
    __shared__ __half Bs[2][128 * SSTR];

    int tid = threadIdx.x;
    int m0 = blockIdx.y * 128, n0 = blockIdx.x * 128;
    int lane = tid & 31, wid = tid >> 5;
    int wm = wid >> 2, wn = wid & 3;   // warp grid 2 (m) x 4 (n)

    float c[4][4][4];
    #pragma unroll
    for (int mi = 0; mi < 4; mi++)
        #pragma unroll
        for (int ni = 0; ni < 4; ni++)
            #pragma unroll
            for (int r = 0; r < 4; r++) c[mi][ni][r] = 0.f;

    int KT = K / 32;

    auto load_stage = [&](int kt, int buf) {
        int k0 = kt * 32;
        #pragma unroll
        for (int i = 0; i < 2; i++) {
            int ch = tid + i * 256;            // 0..511
            int row = ch >> 2, cx = ch & 3;    // row 0..127, 16B chunk 0..3
            // A (always valid: M multiple of 128)
            uint32_t da = sptr(&As[buf][row * SSTR + cx * 8]);
            const __half* sa = A + (size_t)(m0 + row) * K + k0 + cx * 8;
            asm volatile("cp.async.cg.shared.global [%0], [%1], 16;\n"
                         :: "r"(da), "l"(sa));
            // B (predicated on n < N, zero-fill otherwise)
            int gn = n0 + row;
            int valid = gn < N;
            uint32_t db = sptr(&Bs[buf][row * SSTR + cx * 8]);
            const __half* sb = B + (size_t)(valid ? gn : 0) * K + k0 + cx * 8;
            int sz = valid ? 16 : 0;
            asm volatile("cp.async.cg.shared.global [%0], [%1], 16, %2;\n"
                         :: "r"(db), "l"(sb), "r"(sz));
        }
    };

    load_stage(0, 0);
    asm volatile("cp.async.commit_group;\n");

    for (int kt = 0; kt < KT; kt++) {
        int buf = kt & 1;
        if (kt + 1 < KT) load_stage(kt + 1, (kt + 1) & 1);
        asm volatile("cp.async.commit_group;\n");
        asm volatile("cp.async.wait_group 1;\n");
        __syncthreads();

        #pragma unroll
        for (int ks = 0; ks < 2; ks++) {
            uint32_t a[4][4];
            #pragma unroll
            for (int mi = 0; mi < 4; mi++) {
                int row = wm * 64 + mi * 16 + (lane & 15);
                int ko  = ks * 16 + (lane >> 4) * 8;
                ldsm4(a[mi], sptr(&As[buf][row * SSTR + ko]));
            }
            uint32_t b[4][2];
            #pragma unroll
            for (int np = 0; np < 2; np++) {
                uint32_t t[4];
                int row = wn * 32 + np * 16 + (lane & 7) + ((lane >> 4) & 1) * 8;
                int ko  = ks * 16 + ((lane >> 3) & 1) * 8;
                ldsm4(t, sptr(&Bs[buf][row * SSTR + ko]));
                b[np * 2][0] = t[0]; b[np * 2][1] = t[1];
                b[np * 2 + 1][0] = t[2]; b[np * 2 + 1][1] = t[3];
            }
            #pragma unroll
            for (int mi = 0; mi < 4; mi++)
                #pragma unroll
                for (int ni = 0; ni < 4; ni++)
                    mma16816(c[mi][ni], a[mi], b[ni]);
        }
        __syncthreads();
    }

    // epilogue
    int gr = lane >> 2, tc = (lane & 3) * 2;
    #pragma unroll
    for (int mi = 0; mi < 4; mi++) {
        #pragma unroll
        for (int ni = 0; ni < 4; ni++) {
            int n = n0 + wn * 32 + ni * 8 + tc;
            if (n < N) {
                #pragma unroll
                for (int h = 0; h < 2; h++) {
                    int m = m0 + wm * 64 + mi * 16 + gr + h * 8;
                    float v0 = c[mi][ni][h * 2];
                    float v1 = c[mi][ni][h * 2 + 1];
                    if (bias) { v0 += bias[n]; v1 += bias[n + 1]; }
                    if (act == 1) {
                        v0 = 0.5f * v0 * (1.f + erff(v0 * 0.70710678118654752f));
                        v1 = 0.5f * v1 * (1.f + erff(v1 * 0.70710678118654752f));
                    }
                    if (resid) {
                        v0 += resid[(size_t)m * N + n];
                        v1 += resid[(size_t)m * N + n + 1];
                    }
                    if (Cf) { float2 o = make_float2(v0, v1); *(float2*)&Cf[(size_t)m * N + n] = o; }
                    if (Ch) { *(__half2*)&Ch[(size_t)m * N + n] = __floats2half2_rn(v0, v1); }
                }
            }
        }
    }
}

// ---------------- dt / dA (shared between directions) ----------------
__global__ void dtproc_kernel(const float* __restrict__ dt_bias,
                              const float* __restrict__ A_log) {
    int idx = blockIdx.x * blockDim.x + threadIdx.x;
    if (idx >= NTOK * NHEADS) return;
    int row = idx / NHEADS, h = idx % NHEADS;
    float x = g_zx[(size_t)row * DINPROJ + DINNER + CONVDIM + h] + dt_bias[h];
    float sp = (x > 20.f) ? x : log1pf(expf(x));
    g_dt[idx] = sp;
    g_dA[idx] = expf(-expf(A_log[h]) * sp);
}

// ---------------- conv (causal fwd / anti-causal bwd) + SiLU ----------------
__global__ void conv_silu_kernel(const float* __restrict__ w, const float* __restrict__ cb) {
    int idx = blockIdx.x * blockDim.x + threadIdx.x;
    if (idx >= 2 * NTOK * CONVDIM) return;
    int c   = idx % CONVDIM;
    int rem = idx / CONVDIM;
    int row = rem % NTOK;
    int dir = rem / NTOK;
    int t = row % SEQ, b = row / SEQ;
    const float* base = g_zx + (size_t)(b * SEQ) * DINPROJ + DINNER + c;
    float s = cb[c];
    #pragma unroll
    for (int k = 0; k < 4; k++) {
        int tt = (dir == 0) ? (t - 3 + k) : (t + 3 - k);
        if (tt >= 0 && tt < SEQ)
            s = fmaf(w[c * 4 + k], base[(size_t)tt * DINPROJ], s);
    }
    g_xBC[idx] = s / (1.f + expf(-s));
}

// ---------------- selective scan: one block per (h, b, dir) ----------------
__global__ __launch_bounds__(256) void scan_kernel(const float* __restrict__ D_param) {
    int h = blockIdx.x, b = blockIdx.y, dir = blockIdx.z;
    const float* xbc  = g_xBC + (size_t)(dir * NTOK + b * SEQ) * CONVDIM;
    float*       yout = g_y   + (size_t)(dir * NTOK + b * SEQ) * DINNER;
    int tid = threadIdx.x;
    int p = tid >> 2, q = tid & 3, nbase = q * 16;

    __shared__ float sx[64], sB[64], sC[64], sscal[2];

    float hreg[16];
    #pragma unroll
    for (int i = 0; i < 16; i++) hreg[i] = 0.f;
    float Dp = D_param[h];

    auto load_for = [&](int t) -> float {
        const float* r = xbc + (size_t)t * CONVDIM;
        if (tid < 64)        return r[h * 64 + tid];
        else if (tid < 128)  return r[DINNER + (tid - 64)];
        else if (tid < 192)  return r[DINNER + DSTATE + (tid - 128)];
        else if (tid == 192) return g_dt[(size_t)(b * SEQ + t) * NHEADS + h];
        else if (tid == 193) return g_dA[(size_t)(b * SEQ + t) * NHEADS + h];
        return 0.f;
    };

    float staged = load_for(dir ? (SEQ - 1) : 0);

    for (int s = 0; s < SEQ; s++) {
        int t = dir ? (SEQ - 1 - s) : s;
        if (tid < 64)        sx[tid]       = staged;
        else if (tid < 128)  sB[tid - 64]  = staged;
        else if (tid < 192)  sC[tid - 128] = staged;
        else if (tid == 192) sscal[0]      = staged;
        else if (tid == 193) sscal[1]      = staged;
        __syncthreads();
        if (s + 1 < SEQ) staged = load_for(dir ? (SEQ - 2 - s) : (s + 1));

        float xp  = sx[p];
        float dtv = sscal[0];
        float dAv = sscal[1];
        float bx  = dtv * xp;
        float acc = 0.f;
        #pragma unroll
        for (int i = 0; i < 16; i++) {
            int n = nbase + i;
            hreg[i] = fmaf(dAv, hreg[i], bx * sB[n]);
            acc = fmaf(hreg[i], sC[n], acc);
        }
        acc += __shfl_xor_sync(0xffffffffu, acc, 1);
        acc += __shfl_xor_sync(0xffffffffu, acc, 2);
        if (q == 0) yout[(size_t)t * DINNER + h * 64 + p] = fmaf(Dp, xp, acc);
        __syncthreads();
    }
}

// ---------------- gate with SiLU(z), per-direction RMSNorm, sum dirs (fp16 out) ----------------
__global__ void gate_rms_kernel(const float* __restrict__ norm_w) {
    int row = blockIdx.x;
    __shared__ float gf[DINNER];
    __shared__ float gb[DINNER];
    const float* zr = g_zx + (size_t)row * DINPROJ;
    const float* yf = g_y  + (size_t)row * DINNER;
    const float* yb = g_y  + (size_t)(NTOK + row) * DINNER;
    float ssf = 0.f, ssb = 0.f;
    for (int c = threadIdx.x; c < DINNER; c += 256) {
        float zc = zr[c];
        float sz = zc / (1.f + expf(-zc));
        float a  = yf[c] * sz;
        float bb = yb[c] * sz;
        gf[c] = a; gb[c] = bb;
        ssf += a * a; ssb += bb * bb;
    }
    blockReduce2_256(ssf, ssb);
    float rf = rsqrtf(ssf / DINNER + LN_EPS);
    float rb = rsqrtf(ssb / DINNER + LN_EPS);
    __half* orow = g_gsumh + (size_t)row * DINNER;
    for (int c = threadIdx.x; c < DINNER; c += 256)
        orow[c] = __float2half((gf[c] * rf + gb[c] * rb) * norm_w[c]);
}

// ---------------- launch ----------------
extern "C" void kernel_launch(void* const* d_in, const int* in_sizes, int n_in,
                              void* d_out, int out_size) {
    const float* x         = (const float*)d_in[0];
    const float* in_proj_w = (const float*)d_in[1];
    const float* conv_w    = (const float*)d_in[2];
    const float* conv_b    = (const float*)d_in[3];
    const float* dt_bias   = (const float*)d_in[4];
    const float* A_log     = (const float*)d_in[5];
    const float* D_param   = (const float*)d_in[6];
    const float* norm_w    = (const float*)d_in[7];
    const float* out_proj_w= (const float*)d_in[8];
    const float* ln1_w     = (const float*)d_in[9];
    const float* ln1_b     = (const float*)d_in[10];
    const float* ln2_w     = (const float*)d_in[11];
    const float* ln2_b     = (const float*)d_in[12];
    const float* ff_w1     = (const float*)d_in[13];
    const float* ff_b1     = (const float*)d_in[14];
    const float* ff_w2     = (const float*)d_in[15];
    const float* ff_b2     = (const float*)d_in[16];
    float* out = (float*)d_out;

    void *p_zx, *p_s, *p_xnh, *p_gsumh, *p_mh, *p_ff1h;
    void *p_wi, *p_wo, *p_w1, *p_w2;
    cudaGetSymbolAddress(&p_zx,    g_zx);
    cudaGetSymbolAddress(&p_s,     g_s);
    cudaGetSymbolAddress(&p_xnh,   g_xnh);
    cudaGetSymbolAddress(&p_gsumh, g_gsumh);
    cudaGetSymbolAddress(&p_mh,    g_mh);
    cudaGetSymbolAddress(&p_ff1h,  g_ff1h);
    cudaGetSymbolAddress(&p_wi,    g_w_inproj_h);
    cudaGetSymbolAddress(&p_wo,    g_w_outproj_h);
    cudaGetSymbolAddress(&p_w1,    g_w_ff1_h);
    cudaGetSymbolAddress(&p_w2,    g_w_ff2_h);

    // 0) weight conversions to fp16
    {
        int n2;
        n2 = DINPROJ * DMODEL / 2;
        f2h_kernel<<<(n2 + 255) / 256, 256>>>(in_proj_w, (__half*)p_wi, n2);
        n2 = DMODEL * DINNER / 2;
        f2h_kernel<<<(n2 + 255) / 256, 256>>>(out_proj_w, (__half*)p_wo, n2);
        n2 = DFF * DMODEL / 2;
        f2h_kernel<<<(n2 + 255) / 256, 256>>>(ff_w1, (__half*)p_w1, n2);
        n2 = DMODEL * DFF / 2;
        f2h_kernel<<<(n2 + 255) / 256, 256>>>(ff_w2, (__half*)p_w2, n2);
    }

    // 1) LN1 -> fp16 xn
    ln_kernel<<<NTOK, 256>>>(x, ln1_w, ln1_b, (__half*)p_xnh, DMODEL);

    // 2) in_proj GEMM (shared between directions): (1024,768)x(3224,768)^T -> fp32
    hgemm<<<dim3((DINPROJ + 127) / 128, NTOK / 128), 256>>>(
        (const __half*)p_xnh, (const __half*)p_wi,
        NTOK, DINPROJ, DMODEL, (float*)p_zx, nullptr, nullptr, nullptr, 0);

    // 3) dt / dA
    dtproc_kernel<<<(NTOK * NHEADS + 255) / 256, 256>>>(dt_bias, A_log);

    // 4) conv + SiLU (both directions)
    conv_silu_kernel<<<(2 * NTOK * CONVDIM + 255) / 256, 256>>>(conv_w, conv_b);

    // 5) selective scan (both directions)
    scan_kernel<<<dim3(NHEADS, BSZ, 2), 256>>>(D_param);

    // 6) gate + RMSNorm + direction-sum -> fp16
    gate_rms_kernel<<<NTOK, 256>>>(norm_w);

    // 7) out_proj GEMM: (1024,1536)x(768,1536)^T -> fp32 g_s
    hgemm<<<dim3(DMODEL / 128, NTOK / 128), 256>>>(
        (const __half*)p_gsumh, (const __half*)p_wo,
        NTOK, DMODEL, DINNER, (float*)p_s, nullptr, nullptr, nullptr, 0);

    // 8) LN2 -> fp16 m
    ln_kernel<<<NTOK, 256>>>((const float*)p_s, ln2_w, ln2_b, (__half*)p_mh, DMODEL);

    // 9) FF1 + bias + GELU -> fp16
    hgemm<<<dim3(DFF / 128, NTOK / 128), 256>>>(
        (const __half*)p_mh, (const __half*)p_w1,
        NTOK, DFF, DMODEL, nullptr, (__half*)p_ff1h, ff_b1, nullptr, 1);

    // 10) FF2 + bias + residual -> fp32 out
    hgemm<<<dim3(DMODEL / 128, NTOK / 128), 256>>>(
        (const __half*)p_ff1h, (const __half*)p_w2,
        NTOK, DMODEL, DFF, out, nullptr, ff_b2, x, 0);
}

// round 3
// speedup vs baseline: 3.3893x; 1.1731x over previous
#include <cuda_runtime.h>
#include <cuda_fp16.h>
#include <math.h>
#include <stdint.h>

#define BSZ     2
#define SEQ     512
#define DMODEL  768
#define DINNER  1536
#define DSTATE  64
#define NHEADS  24
#define HEADDIM 64
#define CONVDIM 1664            // DINNER + 2*DSTATE
#define DINPROJ 3224            // 2*DINNER + 2*DSTATE + NHEADS
#define NTOK    (BSZ*SEQ)       // 1024
#define DFF     3072
#define LN_EPS  1e-5f

typedef unsigned long long ull;

// ---------------- scratch (static device globals; no allocation) ----------------
__device__ float  g_zx  [NTOK*DINPROJ];
__device__ float  g_xBC [2*NTOK*CONVDIM];
__device__ float  g_dt  [NTOK*NHEADS];
__device__ float  g_dA  [NTOK*NHEADS];
__device__ float  g_y   [2*NTOK*DINNER];
__device__ float  g_s   [NTOK*DMODEL];
// fp16 activations / weights
__device__ __half g_xnh   [NTOK*DMODEL];
__device__ __half g_gsumh [NTOK*DINNER];
__device__ __half g_mh    [NTOK*DMODEL];
__device__ __half g_ff1h  [NTOK*DFF];
__device__ __half g_w_inproj_h [DINPROJ*DMODEL];
__device__ __half g_w_outproj_h[DMODEL*DINNER];
__device__ __half g_w_ff1_h    [DFF*DMODEL];
__device__ __half g_w_ff2_h    [DMODEL*DFF];

// ---------------- helpers ----------------
__device__ __forceinline__ uint32_t sptr(const void* p) {
    return (uint32_t)__cvta_generic_to_shared(p);
}
__device__ __forceinline__ void ldsm4(uint32_t* r, uint32_t addr) {
    asm volatile("ldmatrix.sync.aligned.m8n8.x4.shared.b16 {%0,%1,%2,%3}, [%4];"
                 : "=r"(r[0]), "=r"(r[1]), "=r"(r[2]), "=r"(r[3]) : "r"(addr));
}
__device__ __forceinline__ void mma16816(float* c, const uint32_t* a, const uint32_t* b) {
    asm volatile("mma.sync.aligned.m16n8k16.row.col.f32.f16.f16.f32 "
                 "{%0,%1,%2,%3}, {%4,%5,%6,%7}, {%8,%9}, {%0,%1,%2,%3};"
                 : "+f"(c[0]), "+f"(c[1]), "+f"(c[2]), "+f"(c[3])
                 : "r"(a[0]), "r"(a[1]), "r"(a[2]), "r"(a[3]), "r"(b[0]), "r"(b[1]));
}
// packed fp32x2 math (FFMA2 — only reachable via PTX)
__device__ __forceinline__ ull pack2(float x, float y) {
    ull r; asm("mov.b64 %0,{%1,%2};" : "=l"(r) : "f"(x), "f"(y)); return r;
}
__device__ __forceinline__ void unpack2(ull v, float& x, float& y) {
    asm("mov.b64 {%0,%1},%2;" : "=f"(x), "=f"(y) : "l"(v));
}
__device__ __forceinline__ ull fma2(ull a, ull b, ull c) {
    ull d; asm("fma.rn.f32x2 %0,%1,%2,%3;" : "=l"(d) : "l"(a), "l"(b), "l"(c)); return d;
}
__device__ __forceinline__ ull mul2(ull a, ull b) {
    ull d; asm("mul.rn.f32x2 %0,%1,%2;" : "=l"(d) : "l"(a), "l"(b)); return d;
}
__device__ __forceinline__ ull add2(ull a, ull b) {
    ull d; asm("add.rn.f32x2 %0,%1,%2;" : "=l"(d) : "l"(a), "l"(b)); return d;
}

// ---------------- fp32 -> fp16 convert, 8 elems/thread ----------------
__global__ void f2h_kernel(const float* __restrict__ in, __half* __restrict__ out, int n8) {
    int i = blockIdx.x * blockDim.x + threadIdx.x;
    if (i < n8) {
        float4 a = ((const float4*)in)[2 * i];
        float4 b = ((const float4*)in)[2 * i + 1];
        __half2 h[4];
        h[0] = __floats2half2_rn(a.x, a.y);
        h[1] = __floats2half2_rn(a.z, a.w);
        h[2] = __floats2half2_rn(b.x, b.y);
        h[3] = __floats2half2_rn(b.z, b.w);
        *(uint4*)&out[8 * i] = *(uint4*)h;
    }
}

// ---------------- block reduce (256 threads, two values) ----------------
__device__ __forceinline__ void blockReduce2_256(float& a, float& b) {
    __shared__ float sa[8], sb[8];
    #pragma unroll
    for (int o = 16; o > 0; o >>= 1) {
        a += __shfl_xor_sync(0xffffffffu, a, o);
        b += __shfl_xor_sync(0xffffffffu, b, o);
    }
    int w = threadIdx.x >> 5, l = threadIdx.x & 31;
    if (l == 0) { sa[w] = a; sb[w] = b; }
    __syncthreads();
    if (w == 0) {
        a = (l < 8) ? sa[l] : 0.f;
        b = (l < 8) ? sb[l] : 0.f;
        #pragma unroll
        for (int o = 4; o > 0; o >>= 1) {
            a += __shfl_xor_sync(0xffffffffu, a, o);
            b += __shfl_xor_sync(0xffffffffu, b, o);
        }
        if (l == 0) { sa[0] = a; sb[0] = b; }
    }
    __syncthreads();
    a = sa[0]; b = sb[0];
}

// ---------------- layernorm (fp32 in, fp16 out) ----------------
__global__ void ln_kernel(const float* __restrict__ x, const float* __restrict__ w,
                          const float* __restrict__ b, __half* __restrict__ out, int D) {
    int row = blockIdx.x;
    const float* xr = x + (size_t)row * D;
    float s = 0.f, ss = 0.f;
    for (int c = threadIdx.x; c < D; c += 256) { float v = xr[c]; s += v; ss += v * v; }
    blockReduce2_256(s, ss);
    float mean = s / D;
    float var  = ss / D - mean * mean;
    float r = rsqrtf(var + LN_EPS);
    __half* orow = out + (size_t)row * D;
    for (int c = threadIdx.x; c < D; c += 256)
        orow[c] = __float2half((xr[c] - mean) * r * w[c] + b[c]);
}

// ---------------- fp16 tensor-core GEMM: C[M,N] = A[M,K] @ B[N,K]^T ----------------
#define SSTR 40   // padded half stride per smem row
__global__ __launch_bounds__(256) void hgemm(
    const __half* __restrict__ A, const __half* __restrict__ B,
    int M, int N, int K,
    float* __restrict__ Cf, __half* __restrict__ Ch,
    const float* __restrict__ bias, const float* __restrict__ resid, int act)
{
    __shared__ __half As[2][128 * SSTR];
    __shared__ __half Bs[2][128 * SSTR];

    int tid = threadIdx.x;
    int m0 = blockIdx.y * 128, n0 = blockIdx.x * 128;
    int lane = tid & 31, wid = tid >> 5;
    int wm = wid >> 2, wn = wid & 3;

    float c[4][4][4];
    #pragma unroll
    for (int mi = 0; mi < 4; mi++)
        #pragma unroll
        for (int ni = 0; ni < 4; ni++)
            #pragma unroll
            for (int r = 0; r < 4; r++) c[mi][ni][r] = 0.f;

    int KT = K / 32;

    auto load_stage = [&](int kt, int buf) {
        int k0 = kt * 32;
        #pragma unroll
        for (int i = 0; i < 2; i++) {
            int ch = tid + i * 256;
            int row = ch >> 2, cx = ch & 3;
            uint32_t da = sptr(&As[buf][row * SSTR + cx * 8]);
            const __half* sa = A + (size_t)(m0 + row) * K + k0 + cx * 8;
            asm volatile("cp.async.cg.shared.global [%0], [%1], 16;\n"
                         :: "r"(da), "l"(sa));
            int gn = n0 + row;
            int valid = gn < N;
            uint32_t db = sptr(&Bs[buf][row * SSTR + cx * 8]);
            const __half* sb = B + (size_t)(valid ? gn : 0) * K + k0 + cx * 8;
            int sz = valid ? 16 : 0;
            asm volatile("cp.async.cg.shared.global [%0], [%1], 16, %2;\n"
                         :: "r"(db), "l"(sb), "r"(sz));
        }
    };

    load_stage(0, 0);
    asm volatile("cp.async.commit_group;\n");

    for (int kt = 0; kt < KT; kt++) {
        int buf = kt & 1;
        if (kt + 1 < KT) load_stage(kt + 1, (kt + 1) & 1);
        asm volatile("cp.async.commit_group;\n");
        asm volatile("cp.async.wait_group 1;\n");
        __syncthreads();

        #pragma unroll
        for (int ks = 0; ks < 2; ks++) {
            uint32_t a[4][4];
            #pragma unroll
            for (int mi = 0; mi < 4; mi++) {
                int row = wm * 64 + mi * 16 + (lane & 15);
                int ko  = ks * 16 + (lane >> 4) * 8;
                ldsm4(a[mi], sptr(&As[buf][row * SSTR + ko]));
            }
            uint32_t b[4][2];
            #pragma unroll
            for (int np = 0; np < 2; np++) {
                uint32_t t[4];
                int row = wn * 32 + np * 16 + (lane & 7) + ((lane >> 4) & 1) * 8;
                int ko  = ks * 16 + ((lane >> 3) & 1) * 8;
                ldsm4(t, sptr(&Bs[buf][row * SSTR + ko]));
                b[np * 2][0] = t[0]; b[np * 2][1] = t[1];
                b[np * 2 + 1][0] = t[2]; b[np * 2 + 1][1] = t[3];
            }
            #pragma unroll
            for (int mi = 0; mi < 4; mi++)
                #pragma unroll
                for (int ni = 0; ni < 4; ni++)
                    mma16816(c[mi][ni], a[mi], b[ni]);
        }
        __syncthreads();
    }

    int gr = lane >> 2, tc = (lane & 3) * 2;
    #pragma unroll
    for (int mi = 0; mi < 4; mi++) {
        #pragma unroll
        for (int ni = 0; ni < 4; ni++) {
            int n = n0 + wn * 32 + ni * 8 + tc;
            if (n < N) {
                #pragma unroll
                for (int h = 0; h < 2; h++) {
                    int m = m0 + wm * 64 + mi * 16 + gr + h * 8;
                    float v0 = c[mi][ni][h * 2];
                    float v1 = c[mi][ni][h * 2 + 1];
                    if (bias) { v0 += bias[n]; v1 += bias[n + 1]; }
                    if (act == 1) {
                        v0 = 0.5f * v0 * (1.f + erff(v0 * 0.70710678118654752f));
                        v1 = 0.5f * v1 * (1.f + erff(v1 * 0.70710678118654752f));
                    }
                    if (resid) {
                        v0 += resid[(size_t)m * N + n];
                        v1 += resid[(size_t)m * N + n + 1];
                    }
                    if (Cf) { float2 o = make_float2(v0, v1); *(float2*)&Cf[(size_t)m * N + n] = o; }
                    if (Ch) { *(__half2*)&Ch[(size_t)m * N + n] = __floats2half2_rn(v0, v1); }
                }
            }
        }
    }
}

// ---------------- dt / dA ----------------
__global__ void dtproc_kernel(const float* __restrict__ dt_bias,
                              const float* __restrict__ A_log) {
    int idx = blockIdx.x * blockDim.x + threadIdx.x;
    if (idx >= NTOK * NHEADS) return;
    int row = idx / NHEADS, h = idx % NHEADS;
    float x = g_zx[(size_t)row * DINPROJ + DINNER + CONVDIM + h] + dt_bias[h];
    float sp = (x > 20.f) ? x : log1pf(expf(x));
    g_dt[idx] = sp;
    g_dA[idx] = expf(-expf(A_log[h]) * sp);
}

// ---------------- tiled conv (both dirs) + SiLU ----------------
#define CT 32
#define CC 128
__global__ __launch_bounds__(256) void conv_silu_tile(const float* __restrict__ w,
                                                      const float* __restrict__ cb) {
    int cc = blockIdx.x;   // CONVDIM/CC = 13
    int tt = blockIdx.y;   // SEQ/CT = 16
    int b  = blockIdx.z;   // BSZ
    int c0 = cc * CC, t0 = tt * CT;
    __shared__ float tile[CT + 6][CC];
    __shared__ float wsh[4][CC];
    __shared__ float bsh[CC];

    for (int i = threadIdx.x; i < CC * 4; i += 256) {
        int c = i & (CC - 1), k = i >> 7;
        wsh[k][c] = w[(c0 + c) * 4 + k];
    }
    for (int i = threadIdx.x; i < CC; i += 256) bsh[i] = cb[c0 + i];

    const float* base = g_zx + (size_t)(b * SEQ) * DINPROJ + DINNER + c0;
    for (int i = threadIdx.x; i < (CT + 6) * CC; i += 256) {
        int r = i / CC, c = i % CC;
        int t = t0 - 3 + r;
        tile[r][c] = (t >= 0 && t < SEQ) ? base[(size_t)t * DINPROJ + c] : 0.f;
    }
    __syncthreads();

    for (int i = threadIdx.x; i < CT * CC; i += 256) {
        int r = i / CC, c = i % CC;
        int row = b * SEQ + t0 + r;
        float sf = bsh[c], sb2 = bsh[c];
        #pragma unroll
        for (int k = 0; k < 4; k++) {
            sf  = fmaf(wsh[k][c], tile[r + k][c],     sf);   // fwd: t-3+k
            sb2 = fmaf(wsh[k][c], tile[r + 6 - k][c], sb2);  // bwd: t+3-k
        }
        g_xBC[(size_t)row * CONVDIM + c0 + c]          = sf  / (1.f + expf(-sf));
        g_xBC[(size_t)(NTOK + row) * CONVDIM + c0 + c] = sb2 / (1.f + expf(-sb2));
    }
}

// ---------------- selective scan: one block per (h, b, dir) ----------------
__global__ __launch_bounds__(256) void scan_kernel(const float* __restrict__ D_param) {
    int h = blockIdx.x, b = blockIdx.y, dir = blockIdx.z;
    const float* xbc  = g_xBC + (size_t)(dir * NTOK + b * SEQ) * CONVDIM;
    float*       yout = g_y   + (size_t)(dir * NTOK + b * SEQ) * DINNER;
    int tid = threadIdx.x;
    int p = tid >> 2, q = tid & 3, nbase = q * 16;

    __shared__ float sdt[SEQ], sdA[SEQ];
    __shared__ __align__(16) float sbuf[2][192];  // x[64] | B[64] | C[64]

    // preload dt/dA for this (b, h)
    for (int i = tid; i < SEQ; i += 256) {
        sdt[i] = g_dt[(size_t)(b * SEQ + i) * NHEADS + h];
        sdA[i] = g_dA[(size_t)(b * SEQ + i) * NHEADS + h];
    }

    ull hr2[8];
    #pragma unroll
    for (int i = 0; i < 8; i++) hr2[i] = 0ull;
    float Dp = D_param[h];

    auto gload = [&](int t) -> float {
        const float* r = xbc + (size_t)t * CONVDIM;
        if (tid < 64)  return r[h * 64 + tid];
        if (tid < 192) return r[DINNER + (tid - 64)];  // B then C contiguous
        return 0.f;
    };

    float staged = gload(dir ? (SEQ - 1) : 0);

    for (int s = 0; s < SEQ; s++) {
        int t = dir ? (SEQ - 1 - s) : s;
        int buf = s & 1;
        if (tid < 192) sbuf[buf][tid] = staged;
        __syncthreads();
        if (s + 1 < SEQ) staged = gload(dir ? (SEQ - 2 - s) : (s + 1));

        float xp  = sbuf[buf][p];
        float dtv = sdt[t];
        float dAv = sdA[t];
        float bx  = dtv * xp;

        ull B2[8], C2[8];
        const longlong2* Bp = (const longlong2*)&sbuf[buf][64 + nbase];
        const longlong2* Cp = (const longlong2*)&sbuf[buf][128 + nbase];
        #pragma unroll
        for (int i = 0; i < 4; i++) {
            longlong2 v = Bp[i]; B2[2 * i] = (ull)v.x; B2[2 * i + 1] = (ull)v.y;
            longlong2 u = Cp[i]; C2[2 * i] = (ull)u.x; C2[2 * i + 1] = (ull)u.y;
        }
        ull bx2 = pack2(bx, bx);
        ull dA2 = pack2(dAv, dAv);
        ull acca = 0ull, accb = 0ull;
        #pragma unroll
        for (int i = 0; i < 8; i += 2) {
            hr2[i]     = fma2(dA2, hr2[i],     mul2(bx2, B2[i]));
            hr2[i + 1] = fma2(dA2, hr2[i + 1], mul2(bx2, B2[i + 1]));
            acca = fma2(hr2[i],     C2[i],     acca);
            accb = fma2(hr2[i + 1], C2[i + 1], accb);
        }
        ull accp = add2(acca, accb);
        float a0, a1; unpack2(accp, a0, a1);
        float acc = a0 + a1;
        acc += __shfl_xor_sync(0xffffffffu, acc, 1);
        acc += __shfl_xor_sync(0xffffffffu, acc, 2);
        if (q == 0) yout[(size_t)t * DINNER + h * 64 + p] = fmaf(Dp, xp, acc);
    }
}

// ---------------- gate with SiLU(z), per-direction RMSNorm, sum dirs (fp16 out) ----------------
__global__ void gate_rms_kernel(const float* __restrict__ norm_w) {
    int row = blockIdx.x;
    __shared__ float gf[DINNER];
    __shared__ float gb[DINNER];
    const float* zr = g_zx + (size_t)row * DINPROJ;
    const float* yf = g_y  + (size_t)row * DINNER;
    const float* yb = g_y  + (size_t)(NTOK + row) * DINNER;
    float ssf = 0.f, ssb = 0.f;
    for (int c = threadIdx.x; c < DINNER; c += 256) {
        float zc = zr[c];
        float sz = zc / (1.f + expf(-zc));
        float a  = yf[c] * sz;
        float bb = yb[c] * sz;
        gf[c] = a; gb[c] = bb;
        ssf += a * a; ssb += bb * bb;
    }
    blockReduce2_256(ssf, ssb);
    float rf = rsqrtf(ssf / DINNER + LN_EPS);
    float rb = rsqrtf(ssb / DINNER + LN_EPS);
    __half* orow = g_gsumh + (size_t)row * DINNER;
    for (int c = threadIdx.x; c < DINNER; c += 256)
        orow[c] = __float2half((gf[c] * rf + gb[c] * rb) * norm_w[c]);
}

// ---------------- launch ----------------
extern "C" void kernel_launch(void* const* d_in, const int* in_sizes, int n_in,
                              void* d_out, int out_size) {
    const float* x         = (const float*)d_in[0];
    const float* in_proj_w = (const float*)d_in[1];
    const float* conv_w    = (const float*)d_in[2];
    const float* conv_b    = (const float*)d_in[3];
    const float* dt_bias   = (const float*)d_in[4];
    const float* A_log     = (const float*)d_in[5];
    const float* D_param   = (const float*)d_in[6];
    const float* norm_w    = (const float*)d_in[7];
    const float* out_proj_w= (const float*)d_in[8];
    const float* ln1_w     = (const float*)d_in[9];
    const float* ln1_b     = (const float*)d_in[10];
    const float* ln2_w     = (const float*)d_in[11];
    const float* ln2_b     = (const float*)d_in[12];
    const float* ff_w1     = (const float*)d_in[13];
    const float* ff_b1     = (const float*)d_in[14];
    const float* ff_w2     = (const float*)d_in[15];
    const float* ff_b2     = (const float*)d_in[16];
    float* out = (float*)d_out;

    void *p_zx, *p_s, *p_xnh, *p_gsumh, *p_mh, *p_ff1h;
    void *p_wi, *p_wo, *p_w1, *p_w2;
    cudaGetSymbolAddress(&p_zx,    g_zx);
    cudaGetSymbolAddress(&p_s,     g_s);
    cudaGetSymbolAddress(&p_xnh,   g_xnh);
    cudaGetSymbolAddress(&p_gsumh, g_gsumh);
    cudaGetSymbolAddress(&p_mh,    g_mh);
    cudaGetSymbolAddress(&p_ff1h,  g_ff1h);
    cudaGetSymbolAddress(&p_wi,    g_w_inproj_h);
    cudaGetSymbolAddress(&p_wo,    g_w_outproj_h);
    cudaGetSymbolAddress(&p_w1,    g_w_ff1_h);
    cudaGetSymbolAddress(&p_w2,    g_w_ff2_h);

    // 0) weight conversions to fp16 (8 elems/thread)
    {
        int n8;
        n8 = DINPROJ * DMODEL / 8;
        f2h_kernel<<<(n8 + 255) / 256, 256>>>(in_proj_w, (__half*)p_wi, n8);
        n8 = DMODEL * DINNER / 8;
        f2h_kernel<<<(n8 + 255) / 256, 256>>>(out_proj_w, (__half*)p_wo, n8);
        n8 = DFF * DMODEL / 8;
        f2h_kernel<<<(n8 + 255) / 256, 256>>>(ff_w1, (__half*)p_w1, n8);
        n8 = DMODEL * DFF / 8;
        f2h_kernel<<<(n8 + 255) / 256, 256>>>(ff_w2, (__half*)p_w2, n8);
    }

    // 1) LN1 -> fp16 xn
    ln_kernel<<<NTOK, 256>>>(x, ln1_w, ln1_b, (__half*)p_xnh, DMODEL);

    // 2) in_proj GEMM: (1024,768)x(3224,768)^T -> fp32
    hgemm<<<dim3((DINPROJ + 127) / 128, NTOK / 128), 256>>>(
        (const __half*)p_xnh, (const __half*)p_wi,
        NTOK, DINPROJ, DMODEL, (float*)p_zx, nullptr, nullptr, nullptr, 0);

    // 3) dt / dA
    dtproc_kernel<<<(NTOK * NHEADS + 255) / 256, 256>>>(dt_bias, A_log);

    // 4) tiled conv + SiLU (both directions)
    conv_silu_tile<<<dim3(CONVDIM / CC, SEQ / CT, BSZ), 256>>>(conv_w, conv_b);

    // 5) selective scan (both directions)
    scan_kernel<<<dim3(NHEADS, BSZ, 2), 256>>>(D_param);

    // 6) gate + RMSNorm + direction-sum -> fp16
    gate_rms_kernel<<<NTOK, 256>>>(norm_w);

    // 7) out_proj GEMM: (1024,1536)x(768,1536)^T -> fp32 g_s
    hgemm<<<dim3(DMODEL / 128, NTOK / 128), 256>>>(
        (const __half*)p_gsumh, (const __half*)p_wo,
        NTOK, DMODEL, DINNER, (float*)p_s, nullptr, nullptr, nullptr, 0);

    // 8) LN2 -> fp16 m
    ln_kernel<<<NTOK, 256>>>((const float*)p_s, ln2_w, ln2_b, (__half*)p_mh, DMODEL);

    // 9) FF1 + bias + GELU -> fp16
    hgemm<<<dim3(DFF / 128, NTOK / 128), 256>>>(
        (const __half*)p_mh, (const __half*)p_w1,
        NTOK, DFF, DMODEL, nullptr, (__half*)p_ff1h, ff_b1, nullptr, 1);

    // 10) FF2 + bias + residual -> fp32 out
    hgemm<<<dim3(DMODEL / 128, NTOK / 128), 256>>>(
        (const __half*)p_ff1h, (const __half*)p_w2,
        NTOK, DMODEL, DFF, out, nullptr, ff_b2, x, 0);
}

// round 4
// speedup vs baseline: 3.9514x; 1.1658x over previous
#include <cuda_runtime.h>
#include <cuda_fp16.h>
#include <math.h>
#include <stdint.h>

#define BSZ     2
#define SEQ     512
#define DMODEL  768
#define DINNER  1536
#define DSTATE  64
#define NHEADS  24
#define HEADDIM 64
#define CONVDIM 1664            // DINNER + 2*DSTATE
#define DINPROJ 3224            // 2*DINNER + 2*DSTATE + NHEADS
#define NTOK    (BSZ*SEQ)       // 1024
#define DFF     3072
#define LN_EPS  1e-5f

typedef unsigned long long ull;

// ---------------- scratch (static device globals; no allocation) ----------------
__device__ float  g_zx  [NTOK*DINPROJ];
__device__ float  g_xBC [2*NTOK*CONVDIM];
__device__ float  g_dt  [NTOK*NHEADS];
__device__ float  g_dA  [NTOK*NHEADS];
__device__ float  g_y   [2*NTOK*DINNER];
__device__ float  g_s   [NTOK*DMODEL];
// fp16 activations / weights
__device__ __half g_xnh   [NTOK*DMODEL];
__device__ __half g_gsumh [NTOK*DINNER];
__device__ __half g_mh    [NTOK*DMODEL];
__device__ __half g_ff1h  [NTOK*DFF];
__device__ __half g_w_inproj_h [DINPROJ*DMODEL];
__device__ __half g_w_outproj_h[DMODEL*DINNER];
__device__ __half g_w_ff1_h    [DFF*DMODEL];
__device__ __half g_w_ff2_h    [DMODEL*DFF];

// ---------------- helpers ----------------
__device__ __forceinline__ uint32_t sptr(const void* p) {
    return (uint32_t)__cvta_generic_to_shared(p);
}
__device__ __forceinline__ void ldsm4(uint32_t* r, uint32_t addr) {
    asm volatile("ldmatrix.sync.aligned.m8n8.x4.shared.b16 {%0,%1,%2,%3}, [%4];"
                 : "=r"(r[0]), "=r"(r[1]), "=r"(r[2]), "=r"(r[3]) : "r"(addr));
}
__device__ __forceinline__ void mma16816(float* c, const uint32_t* a, const uint32_t* b) {
    asm volatile("mma.sync.aligned.m16n8k16.row.col.f32.f16.f16.f32 "
                 "{%0,%1,%2,%3}, {%4,%5,%6,%7}, {%8,%9}, {%0,%1,%2,%3};"
                 : "+f"(c[0]), "+f"(c[1]), "+f"(c[2]), "+f"(c[3])
                 : "r"(a[0]), "r"(a[1]), "r"(a[2]), "r"(a[3]), "r"(b[0]), "r"(b[1]));
}
// packed fp32x2 math (FFMA2 — only reachable via PTX)
__device__ __forceinline__ ull pack2(float x, float y) {
    ull r; asm("mov.b64 %0,{%1,%2};" : "=l"(r) : "f"(x), "f"(y)); return r;
}
__device__ __forceinline__ void unpack2(ull v, float& x, float& y) {
    asm("mov.b64 {%0,%1},%2;" : "=f"(x), "=f"(y) : "l"(v));
}
__device__ __forceinline__ ull fma2(ull a, ull b, ull c) {
    ull d; asm("fma.rn.f32x2 %0,%1,%2,%3;" : "=l"(d) : "l"(a), "l"(b), "l"(c)); return d;
}
__device__ __forceinline__ ull mul2(ull a, ull b) {
    ull d; asm("mul.rn.f32x2 %0,%1,%2;" : "=l"(d) : "l"(a), "l"(b)); return d;
}
__device__ __forceinline__ ull add2(ull a, ull b) {
    ull d; asm("add.rn.f32x2 %0,%1,%2;" : "=l"(d) : "l"(a), "l"(b)); return d;
}

// swizzled smem offset (in halves): 32-half (64B) rows, 16B chunks XORed so any
// 8 consecutive rows at a fixed logical chunk hit 8 distinct 16B slots of the
// 32-bank crossbar. off = row*32 + (chunk ^ ((row>>1)&3))*8
__device__ __forceinline__ int swz(int row, int chunk) {
    return row * 32 + ((chunk ^ ((row >> 1) & 3)) << 3);
}

// ---------------- fused fp32 -> fp16 convert for all 4 weights ----------------
__global__ void f2h_all_kernel(const float* __restrict__ w0, __half* __restrict__ o0, int n0,
                               const float* __restrict__ w1, __half* __restrict__ o1, int n1,
                               const float* __restrict__ w2, __half* __restrict__ o2, int n2,
                               const float* __restrict__ w3, __half* __restrict__ o3, int n3) {
    int i = blockIdx.x * blockDim.x + threadIdx.x;  // index in 8-elem units
    const float* in; __half* out; int local;
    if (i < n0)                { in = w0; out = o0; local = i; }
    else if (i < n0 + n1)      { in = w1; out = o1; local = i - n0; }
    else if (i < n0 + n1 + n2) { in = w2; out = o2; local = i - n0 - n1; }
    else if (i < n0 + n1 + n2 + n3) { in = w3; out = o3; local = i - n0 - n1 - n2; }
    else return;
    float4 a = ((const float4*)in)[2 * local];
    float4 b = ((const float4*)in)[2 * local + 1];
    __half2 h[4];
    h[0] = __floats2half2_rn(a.x, a.y);
    h[1] = __floats2half2_rn(a.z, a.w);
    h[2] = __floats2half2_rn(b.x, b.y);
    h[3] = __floats2half2_rn(b.z, b.w);
    *(uint4*)&out[8 * local] = *(uint4*)h;
}

// ---------------- block reduce (256 threads, two values) ----------------
__device__ __forceinline__ void blockReduce2_256(float& a, float& b) {
    __shared__ float sa[8], sb[8];
    #pragma unroll
    for (int o = 16; o > 0; o >>= 1) {
        a += __shfl_xor_sync(0xffffffffu, a, o);
        b += __shfl_xor_sync(0xffffffffu, b, o);
    }
    int w = threadIdx.x >> 5, l = threadIdx.x & 31;
    if (l == 0) { sa[w] = a; sb[w] = b; }
    __syncthreads();
    if (w == 0) {
        a = (l < 8) ? sa[l] : 0.f;
        b = (l < 8) ? sb[l] : 0.f;
        #pragma unroll
        for (int o = 4; o > 0; o >>= 1) {
            a += __shfl_xor_sync(0xffffffffu, a, o);
            b += __shfl_xor_sync(0xffffffffu, b, o);
        }
        if (l == 0) { sa[0] = a; sb[0] = b; }
    }
    __syncthreads();
    a = sa[0]; b = sb[0];
}

// ---------------- layernorm (fp32 in, fp16 out) ----------------
__global__ void ln_kernel(const float* __restrict__ x, const float* __restrict__ w,
                          const float* __restrict__ b, __half* __restrict__ out, int D) {
    int row = blockIdx.x;
    const float* xr = x + (size_t)row * D;
    float s = 0.f, ss = 0.f;
    for (int c = threadIdx.x; c < D; c += 256) { float v = xr[c]; s += v; ss += v * v; }
    blockReduce2_256(s, ss);
    float mean = s / D;
    float var  = ss / D - mean * mean;
    float r = rsqrtf(var + LN_EPS);
    __half* orow = out + (size_t)row * D;
    for (int c = threadIdx.x; c < D; c += 256)
        orow[c] = __float2half((xr[c] - mean) * r * w[c] + b[c]);
}

// ---------------- fp16 tensor-core GEMM: C[M,N] = A[M,K] @ B[N,K]^T ----------------
// Block tile 128 x BN, BK=32, 8 warps. BN=128: warps 2x4 (64x32 tiles);
// BN=64: warps 4x2 (32x32 tiles). Swizzled smem, conflict-free ldmatrix.
template<int BN, int WGN>
__global__ __launch_bounds__(256) void hgemm(
    const __half* __restrict__ A, const __half* __restrict__ B,
    int M, int N, int K,
    float* __restrict__ Cf, __half* __restrict__ Ch,
    const float* __restrict__ bias, const float* __restrict__ resid, int act)
{
    constexpr int WGM = 8 / WGN;        // warps along M
    constexpr int WTM = 128 / WGM;      // warp tile M
    constexpr int MI  = WTM / 16;       // 16-row frags per warp

    __shared__ __half As[2][128 * 32];
    __shared__ __half Bs[2][BN * 32];

    int tid = threadIdx.x;
    int m0 = blockIdx.y * 128, n0 = blockIdx.x * BN;
    int lane = tid & 31, wid = tid >> 5;
    int wm = wid / WGN, wn = wid % WGN;

    float c[MI][4][4];
    #pragma unroll
    for (int mi = 0; mi < MI; mi++)
        #pragma unroll
        for (int ni = 0; ni < 4; ni++)
            #pragma unroll
            for (int r = 0; r < 4; r++) c[mi][ni][r] = 0.f;

    int KT = K / 32;

    auto load_stage = [&](int kt, int buf) {
        int k0 = kt * 32;
        #pragma unroll
        for (int i = 0; i < 2; i++) {
            int ch = tid + i * 256;
            int row = ch >> 2, cx = ch & 3;
            uint32_t da = sptr(&As[buf][swz(row, cx)]);
            const __half* sa = A + (size_t)(m0 + row) * K + k0 + cx * 8;
            asm volatile("cp.async.cg.shared.global [%0], [%1], 16;\n"
                         :: "r"(da), "l"(sa));
        }
        #pragma unroll
        for (int ch0 = 0; ch0 < BN * 4; ch0 += 256) {
            int ch = ch0 + tid;
            int row = ch >> 2, cx = ch & 3;
            int gn = n0 + row;
            int valid = gn < N;
            uint32_t db = sptr(&Bs[buf][swz(row, cx)]);
            const __half* sb = B + (size_t)(valid ? gn : 0) * K + k0 + cx * 8;
            int sz = valid ? 16 : 0;
            asm volatile("cp.async.cg.shared.global [%0], [%1], 16, %2;\n"
                         :: "r"(db), "l"(sb), "r"(sz));
        }
    };

    load_stage(0, 0);
    asm volatile("cp.async.commit_group;\n");

    for (int kt = 0; kt < KT; kt++) {
        int buf = kt & 1;
        if (kt + 1 < KT) load_stage(kt + 1, (kt + 1) & 1);
        asm volatile("cp.async.commit_group;\n");
        asm volatile("cp.async.wait_group 1;\n");
        __syncthreads();

        #pragma unroll
        for (int ks = 0; ks < 2; ks++) {
            uint32_t a[MI][4];
            #pragma unroll
            for (int mi = 0; mi < MI; mi++) {
                int row = wm * WTM + mi * 16 + (lane & 15);
                int chunk = ks * 2 + (lane >> 4);
                ldsm4(a[mi], sptr(&As[buf][swz(row, chunk)]));
            }
            uint32_t b[4][2];
            #pragma unroll
            for (int np = 0; np < 2; np++) {
                uint32_t t[4];
                int row = wn * 32 + np * 16 + (lane & 7) + ((lane >> 4) & 1) * 8;
                int chunk = ks * 2 + ((lane >> 3) & 1);
                ldsm4(t, sptr(&Bs[buf][swz(row, chunk)]));
                b[np * 2][0] = t[0]; b[np * 2][1] = t[1];
                b[np * 2 + 1][0] = t[2]; b[np * 2 + 1][1] = t[3];
            }
            #pragma unroll
            for (int mi = 0; mi < MI; mi++)
                #pragma unroll
                for (int ni = 0; ni < 4; ni++)
                    mma16816(c[mi][ni], a[mi], b[ni]);
        }
        __syncthreads();
    }

    int gr = lane >> 2, tc = (lane & 3) * 2;
    #pragma unroll
    for (int mi = 0; mi < MI; mi++) {
        #pragma unroll
        for (int ni = 0; ni < 4; ni++) {
            int n = n0 + wn * 32 + ni * 8 + tc;
            if (n < N) {
                #pragma unroll
                for (int h = 0; h < 2; h++) {
                    int m = m0 + wm * WTM + mi * 16 + gr + h * 8;
                    float v0 = c[mi][ni][h * 2];
                    float v1 = c[mi][ni][h * 2 + 1];
                    if (bias) { v0 += bias[n]; v1 += bias[n + 1]; }
                    if (act == 1) {
                        v0 = 0.5f * v0 * (1.f + erff(v0 * 0.70710678118654752f));
                        v1 = 0.5f * v1 * (1.f + erff(v1 * 0.70710678118654752f));
                    }
                    if (resid) {
                        v0 += resid[(size_t)m * N + n];
                        v1 += resid[(size_t)m * N + n + 1];
                    }
                    if (Cf) { float2 o = make_float2(v0, v1); *(float2*)&Cf[(size_t)m * N + n] = o; }
                    if (Ch) { *(__half2*)&Ch[(size_t)m * N + n] = __floats2half2_rn(v0, v1); }
                }
            }
        }
    }
}

// ---------------- dt / dA ----------------
__global__ void dtproc_kernel(const float* __restrict__ dt_bias,
                              const float* __restrict__ A_log) {
    int idx = blockIdx.x * blockDim.x + threadIdx.x;
    if (idx >= NTOK * NHEADS) return;
    int row = idx / NHEADS, h = idx % NHEADS;
    float x = g_zx[(size_t)row * DINPROJ + DINNER + CONVDIM + h] + dt_bias[h];
    float sp = (x > 20.f) ? x : log1pf(expf(x));
    g_dt[idx] = sp;
    g_dA[idx] = expf(-expf(A_log[h]) * sp);
}

// ---------------- tiled conv (both dirs) + SiLU ----------------
#define CT 32
#define CC 128
__global__ __launch_bounds__(256) void conv_silu_tile(const float* __restrict__ w,
                                                      const float* __restrict__ cb) {
    int cc = blockIdx.x;
    int tt = blockIdx.y;
    int b  = blockIdx.z;
    int c0 = cc * CC, t0 = tt * CT;
    __shared__ float tile[CT + 6][CC];
    __shared__ float wsh[4][CC];
    __shared__ float bsh[CC];

    for (int i = threadIdx.x; i < CC * 4; i += 256) {
        int c = i & (CC - 1), k = i >> 7;
        wsh[k][c] = w[(c0 + c) * 4 + k];
    }
    for (int i = threadIdx.x; i < CC; i += 256) bsh[i] = cb[c0 + i];

    const float* base = g_zx + (size_t)(b * SEQ) * DINPROJ + DINNER + c0;
    for (int i = threadIdx.x; i < (CT + 6) * CC; i += 256) {
        int r = i / CC, c = i % CC;
        int t = t0 - 3 + r;
        tile[r][c] = (t >= 0 && t < SEQ) ? base[(size_t)t * DINPROJ + c] : 0.f;
    }
    __syncthreads();

    for (int i = threadIdx.x; i < CT * CC; i += 256) {
        int r = i / CC, c = i % CC;
        int row = b * SEQ + t0 + r;
        float sf = bsh[c], sb2 = bsh[c];
        #pragma unroll
        for (int k = 0; k < 4; k++) {
            sf  = fmaf(wsh[k][c], tile[r + k][c],     sf);
            sb2 = fmaf(wsh[k][c], tile[r + 6 - k][c], sb2);
        }
        g_xBC[(size_t)row * CONVDIM + c0 + c]          = sf  / (1.f + expf(-sf));
        g_xBC[(size_t)(NTOK + row) * CONVDIM + c0 + c] = sb2 / (1.f + expf(-sb2));
    }
}

// ---------------- selective scan: one block per (h, b, dir) ----------------
__global__ __launch_bounds__(256) void scan_kernel(const float* __restrict__ D_param) {
    int h = blockIdx.x, b = blockIdx.y, dir = blockIdx.z;
    const float* xbc  = g_xBC + (size_t)(dir * NTOK + b * SEQ) * CONVDIM;
    float*       yout = g_y   + (size_t)(dir * NTOK + b * SEQ) * DINNER;
    int tid = threadIdx.x;
    int p = tid >> 2, q = tid & 3, nbase = q * 16;

    __shared__ float sdt[SEQ], sdA[SEQ];
    __shared__ __align__(16) float sbuf[2][192];

    for (int i = tid; i < SEQ; i += 256) {
        sdt[i] = g_dt[(size_t)(b * SEQ + i) * NHEADS + h];
        sdA[i] = g_dA[(size_t)(b * SEQ + i) * NHEADS + h];
    }

    ull hr2[8];
    #pragma unroll
    for (int i = 0; i < 8; i++) hr2[i] = 0ull;
    float Dp = D_param[h];

    auto gload = [&](int t) -> float {
        const float* r = xbc + (size_t)t * CONVDIM;
        if (tid < 64)  return r[h * 64 + tid];
        if (tid < 192) return r[DINNER + (tid - 64)];
        return 0.f;
    };

    float staged = gload(dir ? (SEQ - 1) : 0);

    for (int s = 0; s < SEQ; s++) {
        int t = dir ? (SEQ - 1 - s) : s;
        int buf = s & 1;
        if (tid < 192) sbuf[buf][tid] = staged;
        __syncthreads();
        if (s + 1 < SEQ) staged = gload(dir ? (SEQ - 2 - s) : (s + 1));

        float xp  = sbuf[buf][p];
        float dtv = sdt[t];
        float dAv = sdA[t];
        float bx  = dtv * xp;

        ull B2[8], C2[8];
        const longlong2* Bp = (const longlong2*)&sbuf[buf][64 + nbase];
        const longlong2* Cp = (const longlong2*)&sbuf[buf][128 + nbase];
        #pragma unroll
        for (int i = 0; i < 4; i++) {
            longlong2 v = Bp[i]; B2[2 * i] = (ull)v.x; B2[2 * i + 1] = (ull)v.y;
            longlong2 u = Cp[i]; C2[2 * i] = (ull)u.x; C2[2 * i + 1] = (ull)u.y;
        }
        ull bx2 = pack2(bx, bx);
        ull dA2 = pack2(dAv, dAv);
        ull acca = 0ull, accb = 0ull;
        #pragma unroll
        for (int i = 0; i < 8; i += 2) {
            hr2[i]     = fma2(dA2, hr2[i],     mul2(bx2, B2[i]));
            hr2[i + 1] = fma2(dA2, hr2[i + 1], mul2(bx2, B2[i + 1]));
            acca = fma2(hr2[i],     C2[i],     acca);
            accb = fma2(hr2[i + 1], C2[i + 1], accb);
        }
        ull accp = add2(acca, accb);
        float a0, a1; unpack2(accp, a0, a1);
        float acc = a0 + a1;
        acc += __shfl_xor_sync(0xffffffffu, acc, 1);
        acc += __shfl_xor_sync(0xffffffffu, acc, 2);
        if (q == 0) yout[(size_t)t * DINNER + h * 64 + p] = fmaf(Dp, xp, acc);
    }
}

// ---------------- gate with SiLU(z), per-direction RMSNorm, sum dirs (fp16 out) ----------------
__global__ void gate_rms_kernel(const float* __restrict__ norm_w) {
    int row = blockIdx.x;
    __shared__ float gf[DINNER];
    __shared__ float gb[DINNER];
    const float* zr = g_zx + (size_t)row * DINPROJ;
    const float* yf = g_y  + (size_t)row * DINNER;
    const float* yb = g_y  + (size_t)(NTOK + row) * DINNER;
    float ssf = 0.f, ssb = 0.f;
    for (int c = threadIdx.x; c < DINNER; c += 256) {
        float zc = zr[c];
        float sz = zc / (1.f + expf(-zc));
        float a  = yf[c] * sz;
        float bb = yb[c] * sz;
        gf[c] = a; gb[c] = bb;
        ssf += a * a; ssb += bb * bb;
    }
    blockReduce2_256(ssf, ssb);
    float rf = rsqrtf(ssf / DINNER + LN_EPS);
    float rb = rsqrtf(ssb / DINNER + LN_EPS);
    __half* orow = g_gsumh + (size_t)row * DINNER;
    for (int c = threadIdx.x; c < DINNER; c += 256)
        orow[c] = __float2half((gf[c] * rf + gb[c] * rb) * norm_w[c]);
}

// ---------------- launch ----------------
extern "C" void kernel_launch(void* const* d_in, const int* in_sizes, int n_in,
                              void* d_out, int out_size) {
    const float* x         = (const float*)d_in[0];
    const float* in_proj_w = (const float*)d_in[1];
    const float* conv_w    = (const float*)d_in[2];
    const float* conv_b    = (const float*)d_in[3];
    const float* dt_bias   = (const float*)d_in[4];
    const float* A_log     = (const float*)d_in[5];
    const float* D_param   = (const float*)d_in[6];
    const float* norm_w    = (const float*)d_in[7];
    const float* out_proj_w= (const float*)d_in[8];
    const float* ln1_w     = (const float*)d_in[9];
    const float* ln1_b     = (const float*)d_in[10];
    const float* ln2_w     = (const float*)d_in[11];
    const float* ln2_b     = (const float*)d_in[12];
    const float* ff_w1     = (const float*)d_in[13];
    const float* ff_b1     = (const float*)d_in[14];
    const float* ff_w2     = (const float*)d_in[15];
    const float* ff_b2     = (const float*)d_in[16];
    float* out = (float*)d_out;

    void *p_zx, *p_s, *p_xnh, *p_gsumh, *p_mh, *p_ff1h;
    void *p_wi, *p_wo, *p_w1, *p_w2;
    cudaGetSymbolAddress(&p_zx,    g_zx);
    cudaGetSymbolAddress(&p_s,     g_s);
    cudaGetSymbolAddress(&p_xnh,   g_xnh);
    cudaGetSymbolAddress(&p_gsumh, g_gsumh);
    cudaGetSymbolAddress(&p_mh,    g_mh);
    cudaGetSymbolAddress(&p_ff1h,  g_ff1h);
    cudaGetSymbolAddress(&p_wi,    g_w_inproj_h);
    cudaGetSymbolAddress(&p_wo,    g_w_outproj_h);
    cudaGetSymbolAddress(&p_w1,    g_w_ff1_h);
    cudaGetSymbolAddress(&p_w2,    g_w_ff2_h);

    // 0) all weight conversions in one launch
    {
        int n0 = DINPROJ * DMODEL / 8;
        int n1 = DMODEL * DINNER / 8;
        int n2 = DFF * DMODEL / 8;
        int n3 = DMODEL * DFF / 8;
        int tot = n0 + n1 + n2 + n3;
        f2h_all_kernel<<<(tot + 255) / 256, 256>>>(
            in_proj_w, (__half*)p_wi, n0,
            out_proj_w, (__half*)p_wo, n1,
            ff_w1, (__half*)p_w1, n2,
            ff_w2, (__half*)p_w2, n3);
    }

    // 1) LN1 -> fp16 xn
    ln_kernel<<<NTOK, 256>>>(x, ln1_w, ln1_b, (__half*)p_xnh, DMODEL);

    // 2) in_proj GEMM: (1024,768)x(3224,768)^T -> fp32
    hgemm<128,4><<<dim3((DINPROJ + 127) / 128, NTOK / 128), 256>>>(
        (const __half*)p_xnh, (const __half*)p_wi,
        NTOK, DINPROJ, DMODEL, (float*)p_zx, nullptr, nullptr, nullptr, 0);

    // 3) dt / dA
    dtproc_kernel<<<(NTOK * NHEADS + 255) / 256, 256>>>(dt_bias, A_log);

    // 4) tiled conv + SiLU (both directions)
    conv_silu_tile<<<dim3(CONVDIM / CC, SEQ / CT, BSZ), 256>>>(conv_w, conv_b);

    // 5) selective scan (both directions)
    scan_kernel<<<dim3(NHEADS, BSZ, 2), 256>>>(D_param);

    // 6) gate + RMSNorm + direction-sum -> fp16
    gate_rms_kernel<<<NTOK, 256>>>(norm_w);

    // 7) out_proj GEMM: (1024,1536)x(768,1536)^T -> fp32 g_s  (BN=64 for occupancy)
    hgemm<64,2><<<dim3(DMODEL / 64, NTOK / 128), 256>>>(
        (const __half*)p_gsumh, (const __half*)p_wo,
        NTOK, DMODEL, DINNER, (float*)p_s, nullptr, nullptr, nullptr, 0);

    // 8) LN2 -> fp16 m
    ln_kernel<<<NTOK, 256>>>((const float*)p_s, ln2_w, ln2_b, (__half*)p_mh, DMODEL);

    // 9) FF1 + bias + GELU -> fp16
    hgemm<128,4><<<dim3(DFF / 128, NTOK / 128), 256>>>(
        (const __half*)p_mh, (const __half*)p_w1,
        NTOK, DFF, DMODEL, nullptr, (__half*)p_ff1h, ff_b1, nullptr, 1);

    // 10) FF2 + bias + residual -> fp32 out  (BN=64 for occupancy)
    hgemm<64,2><<<dim3(DMODEL / 64, NTOK / 128), 256>>>(
        (const __half*)p_ff1h, (const __half*)p_w2,
        NTOK, DMODEL, DFF, out, nullptr, ff_b2, x, 0);
}

// round 7
// speedup vs baseline: 4.1689x; 1.0550x over previous
#include <cuda_runtime.h>
#include <cuda_fp16.h>
#include <math.h>
#include <stdint.h>

#define BSZ     2
#define SEQ     512
#define DMODEL  768
#define DINNER  1536
#define DSTATE  64
#define NHEADS  24
#define HEADDIM 64
#define CONVDIM 1664            // DINNER + 2*DSTATE
#define DINPROJ 3224            // 2*DINNER + 2*DSTATE + NHEADS
#define NTOK    (BSZ*SEQ)       // 1024
#define DFF     3072
#define LN_EPS  1e-5f

typedef unsigned long long ull;

// ---------------- scratch (static device globals; no allocation) ----------------
__device__ float  g_zx  [NTOK*DINPROJ];
__device__ float  g_xBC [2*NTOK*CONVDIM];
__device__ float  g_dt  [NTOK*NHEADS];
__device__ float  g_dA  [NTOK*NHEADS];
__device__ float  g_y   [2*NTOK*DINNER];
__device__ float  g_s   [NTOK*DMODEL];
// fp16 activations / weights
__device__ __half g_xnh   [NTOK*DMODEL];
__device__ __half g_gsumh [NTOK*DINNER];
__device__ __half g_mh    [NTOK*DMODEL];
__device__ __half g_ff1h  [NTOK*DFF];
__device__ __half g_w_inproj_h [DINPROJ*DMODEL];
__device__ __half g_w_outproj_h[DMODEL*DINNER];
__device__ __half g_w_ff1_h    [DFF*DMODEL];
__device__ __half g_w_ff2_h    [DMODEL*DFF];

// ---------------- helpers ----------------
__device__ __forceinline__ uint32_t sptr(const void* p) {
    return (uint32_t)__cvta_generic_to_shared(p);
}
__device__ __forceinline__ void ldsm4(uint32_t* r, uint32_t addr) {
    asm volatile("ldmatrix.sync.aligned.m8n8.x4.shared.b16 {%0,%1,%2,%3}, [%4];"
                 : "=r"(r[0]), "=r"(r[1]), "=r"(r[2]), "=r"(r[3]) : "r"(addr));
}
__device__ __forceinline__ void mma16816(float* c, const uint32_t* a, const uint32_t* b) {
    asm volatile("mma.sync.aligned.m16n8k16.row.col.f32.f16.f16.f32 "
                 "{%0,%1,%2,%3}, {%4,%5,%6,%7}, {%8,%9}, {%0,%1,%2,%3};"
                 : "+f"(c[0]), "+f"(c[1]), "+f"(c[2]), "+f"(c[3])
                 : "r"(a[0]), "r"(a[1]), "r"(a[2]), "r"(a[3]), "r"(b[0]), "r"(b[1]));
}
// packed fp32x2 math (FFMA2 — only reachable via PTX)
__device__ __forceinline__ ull pack2(float x, float y) {
    ull r; asm("mov.b64 %0,{%1,%2};" : "=l"(r) : "f"(x), "f"(y)); return r;
}
__device__ __forceinline__ void unpack2(ull v, float& x, float& y) {
    asm("mov.b64 {%0,%1},%2;" : "=f"(x), "=f"(y) : "l"(v));
}
__device__ __forceinline__ ull fma2(ull a, ull b, ull c) {
    ull d; asm("fma.rn.f32x2 %0,%1,%2,%3;" : "=l"(d) : "l"(a), "l"(b), "l"(c)); return d;
}
__device__ __forceinline__ ull mul2(ull a, ull b) {
    ull d; asm("mul.rn.f32x2 %0,%1,%2;" : "=l"(d) : "l"(a), "l"(b)); return d;
}
__device__ __forceinline__ ull add2(ull a, ull b) {
    ull d; asm("add.rn.f32x2 %0,%1,%2;" : "=l"(d) : "l"(a), "l"(b)); return d;
}

// swizzled smem offset (in halves): 32-half (64B) rows, 16B chunks XORed.
__device__ __forceinline__ int swz(int row, int chunk) {
    return row * 32 + ((chunk ^ ((row >> 1) & 3)) << 3);
}

// ---------------- fused fp32 -> fp16 convert for all 4 weights ----------------
__global__ void f2h_all_kernel(const float* __restrict__ w0, __half* __restrict__ o0, int n0,
                               const float* __restrict__ w1, __half* __restrict__ o1, int n1,
                               const float* __restrict__ w2, __half* __restrict__ o2, int n2,
                               const float* __restrict__ w3, __half* __restrict__ o3, int n3) {
    int i = blockIdx.x * blockDim.x + threadIdx.x;
    const float* in; __half* out; int local;
    if (i < n0)                { in = w0; out = o0; local = i; }
    else if (i < n0 + n1)      { in = w1; out = o1; local = i - n0; }
    else if (i < n0 + n1 + n2) { in = w2; out = o2; local = i - n0 - n1; }
    else if (i < n0 + n1 + n2 + n3) { in = w3; out = o3; local = i - n0 - n1 - n2; }
    else return;
    float4 a = ((const float4*)in)[2 * local];
    float4 b = ((const float4*)in)[2 * local + 1];
    __half2 h[4];
    h[0] = __floats2half2_rn(a.x, a.y);
    h[1] = __floats2half2_rn(a.z, a.w);
    h[2] = __floats2half2_rn(b.x, b.y);
    h[3] = __floats2half2_rn(b.z, b.w);
    *(uint4*)&out[8 * local] = *(uint4*)h;
}

// ---------------- block reduce (256 threads, two values) ----------------
__device__ __forceinline__ void blockReduce2_256(float& a, float& b) {
    __shared__ float sa[8], sb[8];
    #pragma unroll
    for (int o = 16; o > 0; o >>= 1) {
        a += __shfl_xor_sync(0xffffffffu, a, o);
        b += __shfl_xor_sync(0xffffffffu, b, o);
    }
    int w = threadIdx.x >> 5, l = threadIdx.x & 31;
    if (l == 0) { sa[w] = a; sb[w] = b; }
    __syncthreads();
    if (w == 0) {
        a = (l < 8) ? sa[l] : 0.f;
        b = (l < 8) ? sb[l] : 0.f;
        #pragma unroll
        for (int o = 4; o > 0; o >>= 1) {
            a += __shfl_xor_sync(0xffffffffu, a, o);
            b += __shfl_xor_sync(0xffffffffu, b, o);
        }
        if (l == 0) { sa[0] = a; sb[0] = b; }
    }
    __syncthreads();
    a = sa[0]; b = sb[0];
}

// ---------------- layernorm (fp32 in, fp16 out) ----------------
__global__ void ln_kernel(const float* __restrict__ x, const float* __restrict__ w,
                          const float* __restrict__ b, __half* __restrict__ out, int D) {
    int row = blockIdx.x;
    const float* xr = x + (size_t)row * D;
    float s = 0.f, ss = 0.f;
    for (int c = threadIdx.x; c < D; c += 256) { float v = xr[c]; s += v; ss += v * v; }
    blockReduce2_256(s, ss);
    float mean = s / D;
    float var  = ss / D - mean * mean;
    float r = rsqrtf(var + LN_EPS);
    __half* orow = out + (size_t)row * D;
    for (int c = threadIdx.x; c < D; c += 256)
        orow[c] = __float2half((xr[c] - mean) * r * w[c] + b[c]);
}

// ---------------- fp16 tensor-core GEMM: C[M,N] = A[M,K] @ B[N,K]^T ----------------
// Block tile 128 x BN, BK=32, 8 warps, 4-stage cp.async pipeline.
// BN=128: warps 2x4 (64x32 tiles); BN=64: warps 4x2 (32x32 tiles).
#define NSTAGE 4
template<int BN, int WGN>
__global__ __launch_bounds__(256) void hgemm(
    const __half* __restrict__ A, const __half* __restrict__ B,
    int M, int N, int K,
    float* __restrict__ Cf, __half* __restrict__ Ch,
    const float* __restrict__ bias, const float* __restrict__ resid, int act)
{
    constexpr int WGM = 8 / WGN;
    constexpr int WTM = 128 / WGM;
    constexpr int MI  = WTM / 16;

    extern __shared__ __half smemh[];
    __half* As = smemh;                      // NSTAGE * 128*32
    __half* Bs = smemh + NSTAGE * 128 * 32;  // NSTAGE * BN*32

    int tid = threadIdx.x;
    int m0 = blockIdx.y * 128, n0 = blockIdx.x * BN;
    int lane = tid & 31, wid = tid >> 5;
    int wm = wid / WGN, wn = wid % WGN;

    float c[MI][4][4];
    #pragma unroll
    for (int mi = 0; mi < MI; mi++)
        #pragma unroll
        for (int ni = 0; ni < 4; ni++)
            #pragma unroll
            for (int r = 0; r < 4; r++) c[mi][ni][r] = 0.f;

    int KT = K / 32;

    auto load_stage = [&](int kt, int buf) {
        int k0 = kt * 32;
        __half* Ab = As + buf * 128 * 32;
        __half* Bb = Bs + buf * BN * 32;
        #pragma unroll
        for (int i = 0; i < 2; i++) {
            int ch = tid + i * 256;
            int row = ch >> 2, cx = ch & 3;
            uint32_t da = sptr(&Ab[swz(row, cx)]);
            const __half* sa = A + (size_t)(m0 + row) * K + k0 + cx * 8;
            asm volatile("cp.async.cg.shared.global [%0], [%1], 16;\n"
                         :: "r"(da), "l"(sa));
        }
        #pragma unroll
        for (int ch0 = 0; ch0 < BN * 4; ch0 += 256) {
            int ch = ch0 + tid;
            int row = ch >> 2, cx = ch & 3;
            int gn = n0 + row;
            int valid = gn < N;
            uint32_t db = sptr(&Bb[swz(row, cx)]);
            const __half* sb = B + (size_t)(valid ? gn : 0) * K + k0 + cx * 8;
            int sz = valid ? 16 : 0;
            asm volatile("cp.async.cg.shared.global [%0], [%1], 16, %2;\n"
                         :: "r"(db), "l"(sb), "r"(sz));
        }
    };

    // prologue: fill NSTAGE-1 stages
    #pragma unroll
    for (int s = 0; s < NSTAGE - 1; s++) {
        if (s < KT) load_stage(s, s);
        asm volatile("cp.async.commit_group;\n");
    }

    for (int kt = 0; kt < KT; kt++) {
        int buf = kt & (NSTAGE - 1);
        asm volatile("cp.async.wait_group %0;\n" :: "n"(NSTAGE - 2));
        __syncthreads();

        __half* Ab = As + buf * 128 * 32;
        __half* Bb = Bs + buf * BN * 32;
        #pragma unroll
        for (int ks = 0; ks < 2; ks++) {
            uint32_t a[MI][4];
            #pragma unroll
            for (int mi = 0; mi < MI; mi++) {
                int row = wm * WTM + mi * 16 + (lane & 15);
                int chunk = ks * 2 + (lane >> 4);
                ldsm4(a[mi], sptr(&Ab[swz(row, chunk)]));
            }
            uint32_t b[4][2];
            #pragma unroll
            for (int np = 0; np < 2; np++) {
                uint32_t t[4];
                int row = wn * 32 + np * 16 + (lane & 7) + ((lane >> 4) & 1) * 8;
                int chunk = ks * 2 + ((lane >> 3) & 1);
                ldsm4(t, sptr(&Bb[swz(row, chunk)]));
                b[np * 2][0] = t[0]; b[np * 2][1] = t[1];
                b[np * 2 + 1][0] = t[2]; b[np * 2 + 1][1] = t[3];
            }
            #pragma unroll
            for (int mi = 0; mi < MI; mi++)
                #pragma unroll
                for (int ni = 0; ni < 4; ni++)
                    mma16816(c[mi][ni], a[mi], b[ni]);
        }

        int nx = kt + NSTAGE - 1;
        if (nx < KT) load_stage(nx, nx & (NSTAGE - 1));
        asm volatile("cp.async.commit_group;\n");
    }

    int gr = lane >> 2, tc = (lane & 3) * 2;
    #pragma unroll
    for (int mi = 0; mi < MI; mi++) {
        #pragma unroll
        for (int ni = 0; ni < 4; ni++) {
            int n = n0 + wn * 32 + ni * 8 + tc;
            if (n < N) {
                #pragma unroll
                for (int h = 0; h < 2; h++) {
                    int m = m0 + wm * WTM + mi * 16 + gr + h * 8;
                    float v0 = c[mi][ni][h * 2];
                    float v1 = c[mi][ni][h * 2 + 1];
                    if (bias) { v0 += bias[n]; v1 += bias[n + 1]; }
                    if (act == 1) {
                        v0 = 0.5f * v0 * (1.f + erff(v0 * 0.70710678118654752f));
                        v1 = 0.5f * v1 * (1.f + erff(v1 * 0.70710678118654752f));
                    }
                    if (resid) {
                        v0 += resid[(size_t)m * N + n];
                        v1 += resid[(size_t)m * N + n + 1];
                    }
                    if (Cf) { float2 o = make_float2(v0, v1); *(float2*)&Cf[(size_t)m * N + n] = o; }
                    if (Ch) { *(__half2*)&Ch[(size_t)m * N + n] = __floats2half2_rn(v0, v1); }
                }
            }
        }
    }
}

// ---------------- dt / dA ----------------
__global__ void dtproc_kernel(const float* __restrict__ dt_bias,
                              const float* __restrict__ A_log) {
    int idx = blockIdx.x * blockDim.x + threadIdx.x;
    if (idx >= NTOK * NHEADS) return;
    int row = idx / NHEADS, h = idx % NHEADS;
    float x = g_zx[(size_t)row * DINPROJ + DINNER + CONVDIM + h] + dt_bias[h];
    float sp = (x > 20.f) ? x : log1pf(expf(x));
    g_dt[idx] = sp;
    g_dA[idx] = expf(-expf(A_log[h]) * sp);
}

// ---------------- tiled conv (both dirs) + SiLU ----------------
#define CT 32
#define CC 128
__global__ __launch_bounds__(256) void conv_silu_tile(const float* __restrict__ w,
                                                      const float* __restrict__ cb) {
    int cc = blockIdx.x;
    int tt = blockIdx.y;
    int b  = blockIdx.z;
    int c0 = cc * CC, t0 = tt * CT;
    __shared__ float tile[CT + 6][CC];
    __shared__ float wsh[4][CC];
    __shared__ float bsh[CC];

    for (int i = threadIdx.x; i < CC * 4; i += 256) {
        int c = i & (CC - 1), k = i >> 7;
        wsh[k][c] = w[(c0 + c) * 4 + k];
    }
    for (int i = threadIdx.x; i < CC; i += 256) bsh[i] = cb[c0 + i];

    const float* base = g_zx + (size_t)(b * SEQ) * DINPROJ + DINNER + c0;
    for (int i = threadIdx.x; i < (CT + 6) * CC; i += 256) {
        int r = i / CC, c = i % CC;
        int t = t0 - 3 + r;
        tile[r][c] = (t >= 0 && t < SEQ) ? base[(size_t)t * DINPROJ + c] : 0.f;
    }
    __syncthreads();

    for (int i = threadIdx.x; i < CT * CC; i += 256) {
        int r = i / CC, c = i % CC;
        int row = b * SEQ + t0 + r;
        float sf = bsh[c], sb2 = bsh[c];
        #pragma unroll
        for (int k = 0; k < 4; k++) {
            sf  = fmaf(wsh[k][c], tile[r + k][c],     sf);
            sb2 = fmaf(wsh[k][c], tile[r + 6 - k][c], sb2);
        }
        g_xBC[(size_t)row * CONVDIM + c0 + c]          = sf  / (1.f + expf(-sf));
        g_xBC[(size_t)(NTOK + row) * CONVDIM + c0 + c] = sb2 / (1.f + expf(-sb2));
    }
}

// ---------------- selective scan: one block per (h, b, dir) ----------------
__global__ __launch_bounds__(256) void scan_kernel(const float* __restrict__ D_param) {
    int h = blockIdx.x, b = blockIdx.y, dir = blockIdx.z;
    const float* xbc  = g_xBC + (size_t)(dir * NTOK + b * SEQ) * CONVDIM;
    float*       yout = g_y   + (size_t)(dir * NTOK + b * SEQ) * DINNER;
    int tid = threadIdx.x;
    int p = tid >> 2, q = tid & 3, nbase = q * 16;

    __shared__ float sdt[SEQ], sdA[SEQ];
    __shared__ __align__(16) float sbuf[2][192];

    for (int i = tid; i < SEQ; i += 256) {
        sdt[i] = g_dt[(size_t)(b * SEQ + i) * NHEADS + h];
        sdA[i] = g_dA[(size_t)(b * SEQ + i) * NHEADS + h];
    }

    ull hr2[8];
    #pragma unroll
    for (int i = 0; i < 8; i++) hr2[i] = 0ull;
    float Dp = D_param[h];

    auto gload = [&](int t) -> float {
        const float* r = xbc + (size_t)t * CONVDIM;
        if (tid < 64)  return r[h * 64 + tid];
        if (tid < 192) return r[DINNER + (tid - 64)];
        return 0.f;
    };

    float staged = gload(dir ? (SEQ - 1) : 0);

    for (int s = 0; s < SEQ; s++) {
        int t = dir ? (SEQ - 1 - s) : s;
        int buf = s & 1;
        if (tid < 192) sbuf[buf][tid] = staged;
        __syncthreads();
        if (s + 1 < SEQ) staged = gload(dir ? (SEQ - 2 - s) : (s + 1));

        float xp  = sbuf[buf][p];
        float dtv = sdt[t];
        float dAv = sdA[t];
        float bx  = dtv * xp;

        ull B2[8], C2[8];
        const longlong2* Bp = (const longlong2*)&sbuf[buf][64 + nbase];
        const longlong2* Cp = (const longlong2*)&sbuf[buf][128 + nbase];
        #pragma unroll
        for (int i = 0; i < 4; i++) {
            longlong2 v = Bp[i]; B2[2 * i] = (ull)v.x; B2[2 * i + 1] = (ull)v.y;
            longlong2 u = Cp[i]; C2[2 * i] = (ull)u.x; C2[2 * i + 1] = (ull)u.y;
        }
        ull bx2 = pack2(bx, bx);
        ull dA2 = pack2(dAv, dAv);
        ull acca = 0ull, accb = 0ull;
        #pragma unroll
        for (int i = 0; i < 8; i += 2) {
            hr2[i]     = fma2(dA2, hr2[i],     mul2(bx2, B2[i]));
            hr2[i + 1] = fma2(dA2, hr2[i + 1], mul2(bx2, B2[i + 1]));
            acca = fma2(hr2[i],     C2[i],     acca);
            accb = fma2(hr2[i + 1], C2[i + 1], accb);
        }
        ull accp = add2(acca, accb);
        float a0, a1; unpack2(accp, a0, a1);
        float acc = a0 + a1;
        acc += __shfl_xor_sync(0xffffffffu, acc, 1);
        acc += __shfl_xor_sync(0xffffffffu, acc, 2);
        if (q == 0) yout[(size_t)t * DINNER + h * 64 + p] = fmaf(Dp, xp, acc);
    }
}

// ---------------- gate with SiLU(z), per-direction RMSNorm, sum dirs (fp16 out) ----------------
__global__ void gate_rms_kernel(const float* __restrict__ norm_w) {
    int row = blockIdx.x;
    __shared__ float gf[DINNER];
    __shared__ float gb[DINNER];
    const float* zr = g_zx + (size_t)row * DINPROJ;
    const float* yf = g_y  + (size_t)row * DINNER;
    const float* yb = g_y  + (size_t)(NTOK + row) * DINNER;
    float ssf = 0.f, ssb = 0.f;
    for (int c = threadIdx.x; c < DINNER; c += 256) {
        float zc = zr[c];
        float sz = zc / (1.f + expf(-zc));
        float a  = yf[c] * sz;
        float bb = yb[c] * sz;
        gf[c] = a; gb[c] = bb;
        ssf += a * a; ssb += bb * bb;
    }
    blockReduce2_256(ssf, ssb);
    float rf = rsqrtf(ssf / DINNER + LN_EPS);
    float rb = rsqrtf(ssb / DINNER + LN_EPS);
    __half* orow = g_gsumh + (size_t)row * DINNER;
    for (int c = threadIdx.x; c < DINNER; c += 256)
        orow[c] = __float2half((gf[c] * rf + gb[c] * rb) * norm_w[c]);
}

// ---------------- launch ----------------
extern "C" void kernel_launch(void* const* d_in, const int* in_sizes, int n_in,
                              void* d_out, int out_size) {
    const float* x         = (const float*)d_in[0];
    const float* in_proj_w = (const float*)d_in[1];
    const float* conv_w    = (const float*)d_in[2];
    const float* conv_b    = (const float*)d_in[3];
    const float* dt_bias   = (const float*)d_in[4];
    const float* A_log     = (const float*)d_in[5];
    const float* D_param   = (const float*)d_in[6];
    const float* norm_w    = (const float*)d_in[7];
    const float* out_proj_w= (const float*)d_in[8];
    const float* ln1_w     = (const float*)d_in[9];
    const float* ln1_b     = (const float*)d_in[10];
    const float* ln2_w     = (const float*)d_in[11];
    const float* ln2_b     = (const float*)d_in[12];
    const float* ff_w1     = (const float*)d_in[13];
    const float* ff_b1     = (const float*)d_in[14];
    const float* ff_w2     = (const float*)d_in[15];
    const float* ff_b2     = (const float*)d_in[16];
    float* out = (float*)d_out;

    void *p_zx, *p_s, *p_xnh, *p_gsumh, *p_mh, *p_ff1h;
    void *p_wi, *p_wo, *p_w1, *p_w2;
    cudaGetSymbolAddress(&p_zx,    g_zx);
    cudaGetSymbolAddress(&p_s,     g_s);
    cudaGetSymbolAddress(&p_xnh,   g_xnh);
    cudaGetSymbolAddress(&p_gsumh, g_gsumh);
    cudaGetSymbolAddress(&p_mh,    g_mh);
    cudaGetSymbolAddress(&p_ff1h,  g_ff1h);
    cudaGetSymbolAddress(&p_wi,    g_w_inproj_h);
    cudaGetSymbolAddress(&p_wo,    g_w_outproj_h);
    cudaGetSymbolAddress(&p_w1,    g_w_ff1_h);
    cudaGetSymbolAddress(&p_w2,    g_w_ff2_h);

    const int smem128 = NSTAGE * (128 + 128) * 32 * sizeof(__half);  // 64 KB
    const int smem64  = NSTAGE * (128 + 64)  * 32 * sizeof(__half);  // 48 KB
    cudaFuncSetAttribute(hgemm<128,4>, cudaFuncAttributeMaxDynamicSharedMemorySize, smem128);
    cudaFuncSetAttribute(hgemm<64,2>,  cudaFuncAttributeMaxDynamicSharedMemorySize, smem64);

    // 0) all weight conversions in one launch
    {
        int n0 = DINPROJ * DMODEL / 8;
        int n1 = DMODEL * DINNER / 8;
        int n2 = DFF * DMODEL / 8;
        int n3 = DMODEL * DFF / 8;
        int tot = n0 + n1 + n2 + n3;
        f2h_all_kernel<<<(tot + 255) / 256, 256>>>(
            in_proj_w, (__half*)p_wi, n0,
            out_proj_w, (__half*)p_wo, n1,
            ff_w1, (__half*)p_w1, n2,
            ff_w2, (__half*)p_w2, n3);
    }

    // 1) LN1 -> fp16 xn
    ln_kernel<<<NTOK, 256>>>(x, ln1_w, ln1_b, (__half*)p_xnh, DMODEL);

    // 2) in_proj GEMM: (1024,768)x(3224,768)^T -> fp32
    hgemm<128,4><<<dim3((DINPROJ + 127) / 128, NTOK / 128), 256, smem128>>>(
        (const __half*)p_xnh, (const __half*)p_wi,
        NTOK, DINPROJ, DMODEL, (float*)p_zx, nullptr, nullptr, nullptr, 0);

    // 3) dt / dA
    dtproc_kernel<<<(NTOK * NHEADS + 255) / 256, 256>>>(dt_bias, A_log);

    // 4) tiled conv + SiLU (both directions)
    conv_silu_tile<<<dim3(CONVDIM / CC, SEQ / CT, BSZ), 256>>>(conv_w, conv_b);

    // 5) selective scan (both directions)
    scan_kernel<<<dim3(NHEADS, BSZ, 2), 256>>>(D_param);

    // 6) gate + RMSNorm + direction-sum -> fp16
    gate_rms_kernel<<<NTOK, 256>>>(norm_w);

    // 7) out_proj GEMM: (1024,1536)x(768,1536)^T -> fp32 g_s
    hgemm<64,2><<<dim3(DMODEL / 64, NTOK / 128), 256, smem64>>>(
        (const __half*)p_gsumh, (const __half*)p_wo,
        NTOK, DMODEL, DINNER, (float*)p_s, nullptr, nullptr, nullptr, 0);

    // 8) LN2 -> fp16 m
    ln_kernel<<<NTOK, 256>>>((const float*)p_s, ln2_w, ln2_b, (__half*)p_mh, DMODEL);

    // 9) FF1 + bias + GELU -> fp16
    hgemm<128,4><<<dim3(DFF / 128, NTOK / 128), 256, smem128>>>(
        (const __half*)p_mh, (const __half*)p_w1,
        NTOK, DFF, DMODEL, nullptr, (__half*)p_ff1h, ff_b1, nullptr, 1);

    // 10) FF2 + bias + residual -> fp32 out
    hgemm<64,2><<<dim3(DMODEL / 64, NTOK / 128), 256, smem64>>>(
        (const __half*)p_ff1h, (const __half*)p_w2,
        NTOK, DMODEL, DFF, out, nullptr, ff_b2, x, 0);
}

// round 8
// speedup vs baseline: 4.4109x; 1.0581x over previous
#include <cuda_runtime.h>
#include <cuda_fp16.h>
#include <math.h>
#include <stdint.h>

#define BSZ     2
#define SEQ     512
#define DMODEL  768
#define DINNER  1536
#define DSTATE  64
#define NHEADS  24
#define HEADDIM 64
#define CONVDIM 1664            // DINNER + 2*DSTATE
#define DINPROJ 3224            // 2*DINNER + 2*DSTATE + NHEADS
#define NTOK    (BSZ*SEQ)       // 1024
#define DFF     3072
#define LN_EPS  1e-5f

typedef unsigned long long ull;

// ---------------- scratch (static device globals; no allocation) ----------------
__device__ float  g_zx  [NTOK*DINPROJ];
__device__ float  g_xBC [2*NTOK*CONVDIM];
__device__ float  g_dt  [NTOK*NHEADS];
__device__ float  g_dA  [NTOK*NHEADS];
__device__ float  g_y   [2*NTOK*DINNER];
__device__ float  g_part[3*NTOK*DMODEL];     // split-K partials
// fp16 activations / weights
__device__ __half g_xnh   [NTOK*DMODEL];
__device__ __half g_gsumh [NTOK*DINNER];
__device__ __half g_mh    [NTOK*DMODEL];
__device__ __half g_ff1h  [NTOK*DFF];
__device__ __half g_w_inproj_h [DINPROJ*DMODEL];
__device__ __half g_w_outproj_h[DMODEL*DINNER];
__device__ __half g_w_ff1_h    [DFF*DMODEL];
__device__ __half g_w_ff2_h    [DMODEL*DFF];

// ---------------- helpers ----------------
__device__ __forceinline__ uint32_t sptr(const void* p) {
    return (uint32_t)__cvta_generic_to_shared(p);
}
__device__ __forceinline__ void ldsm4(uint32_t* r, uint32_t addr) {
    asm volatile("ldmatrix.sync.aligned.m8n8.x4.shared.b16 {%0,%1,%2,%3}, [%4];"
                 : "=r"(r[0]), "=r"(r[1]), "=r"(r[2]), "=r"(r[3]) : "r"(addr));
}
__device__ __forceinline__ void mma16816(float* c, const uint32_t* a, const uint32_t* b) {
    asm volatile("mma.sync.aligned.m16n8k16.row.col.f32.f16.f16.f32 "
                 "{%0,%1,%2,%3}, {%4,%5,%6,%7}, {%8,%9}, {%0,%1,%2,%3};"
                 : "+f"(c[0]), "+f"(c[1]), "+f"(c[2]), "+f"(c[3])
                 : "r"(a[0]), "r"(a[1]), "r"(a[2]), "r"(a[3]), "r"(b[0]), "r"(b[1]));
}
// packed fp32x2 math (FFMA2 — only reachable via PTX)
__device__ __forceinline__ ull pack2(float x, float y) {
    ull r; asm("mov.b64 %0,{%1,%2};" : "=l"(r) : "f"(x), "f"(y)); return r;
}
__device__ __forceinline__ void unpack2(ull v, float& x, float& y) {
    asm("mov.b64 {%0,%1},%2;" : "=f"(x), "=f"(y) : "l"(v));
}
__device__ __forceinline__ ull fma2(ull a, ull b, ull c) {
    ull d; asm("fma.rn.f32x2 %0,%1,%2,%3;" : "=l"(d) : "l"(a), "l"(b), "l"(c)); return d;
}
__device__ __forceinline__ ull mul2(ull a, ull b) {
    ull d; asm("mul.rn.f32x2 %0,%1,%2;" : "=l"(d) : "l"(a), "l"(b)); return d;
}
__device__ __forceinline__ ull add2(ull a, ull b) {
    ull d; asm("add.rn.f32x2 %0,%1,%2;" : "=l"(d) : "l"(a), "l"(b)); return d;
}

// swizzled smem offset (in halves): 32-half (64B) rows, 16B chunks XORed.
__device__ __forceinline__ int swz(int row, int chunk) {
    return row * 32 + ((chunk ^ ((row >> 1) & 3)) << 3);
}

// ---------------- fused fp32 -> fp16 convert for all 4 weights ----------------
__global__ void f2h_all_kernel(const float* __restrict__ w0, __half* __restrict__ o0, int n0,
                               const float* __restrict__ w1, __half* __restrict__ o1, int n1,
                               const float* __restrict__ w2, __half* __restrict__ o2, int n2,
                               const float* __restrict__ w3, __half* __restrict__ o3, int n3) {
    int i = blockIdx.x * blockDim.x + threadIdx.x;
    const float* in; __half* out; int local;
    if (i < n0)                { in = w0; out = o0; local = i; }
    else if (i < n0 + n1)      { in = w1; out = o1; local = i - n0; }
    else if (i < n0 + n1 + n2) { in = w2; out = o2; local = i - n0 - n1; }
    else if (i < n0 + n1 + n2 + n3) { in = w3; out = o3; local = i - n0 - n1 - n2; }
    else return;
    float4 a = ((const float4*)in)[2 * local];
    float4 b = ((const float4*)in)[2 * local + 1];
    __half2 h[4];
    h[0] = __floats2half2_rn(a.x, a.y);
    h[1] = __floats2half2_rn(a.z, a.w);
    h[2] = __floats2half2_rn(b.x, b.y);
    h[3] = __floats2half2_rn(b.z, b.w);
    *(uint4*)&out[8 * local] = *(uint4*)h;
}

// ---------------- block reduce (256 threads, two values) ----------------
__device__ __forceinline__ void blockReduce2_256(float& a, float& b) {
    __shared__ float sa[8], sb[8];
    #pragma unroll
    for (int o = 16; o > 0; o >>= 1) {
        a += __shfl_xor_sync(0xffffffffu, a, o);
        b += __shfl_xor_sync(0xffffffffu, b, o);
    }
    int w = threadIdx.x >> 5, l = threadIdx.x & 31;
    if (l == 0) { sa[w] = a; sb[w] = b; }
    __syncthreads();
    if (w == 0) {
        a = (l < 8) ? sa[l] : 0.f;
        b = (l < 8) ? sb[l] : 0.f;
        #pragma unroll
        for (int o = 4; o > 0; o >>= 1) {
            a += __shfl_xor_sync(0xffffffffu, a, o);
            b += __shfl_xor_sync(0xffffffffu, b, o);
        }
        if (l == 0) { sa[0] = a; sb[0] = b; }
    }
    __syncthreads();
    a = sa[0]; b = sb[0];
}

// ---------------- layernorm (fp32 in, fp16 out) ----------------
__global__ void ln_kernel(const float* __restrict__ x, const float* __restrict__ w,
                          const float* __restrict__ b, __half* __restrict__ out, int D) {
    int row = blockIdx.x;
    const float* xr = x + (size_t)row * D;
    float s = 0.f, ss = 0.f;
    for (int c = threadIdx.x; c < D; c += 256) { float v = xr[c]; s += v; ss += v * v; }
    blockReduce2_256(s, ss);
    float mean = s / D;
    float var  = ss / D - mean * mean;
    float r = rsqrtf(var + LN_EPS);
    __half* orow = out + (size_t)row * D;
    for (int c = threadIdx.x; c < D; c += 256)
        orow[c] = __float2half((xr[c] - mean) * r * w[c] + b[c]);
}

// ---------------- sum 3 split-K partials + LN2 -> fp16 ----------------
__global__ void reduce_ln2_kernel(const float* __restrict__ ln2_w,
                                  const float* __restrict__ ln2_b) {
    int row = blockIdx.x;
    __shared__ float v[DMODEL];
    const float* p0 = g_part + (size_t)row * DMODEL;
    const float* p1 = p0 + (size_t)NTOK * DMODEL;
    const float* p2 = p1 + (size_t)NTOK * DMODEL;
    float s = 0.f, ss = 0.f;
    for (int c = threadIdx.x; c < DMODEL; c += 256) {
        float t = p0[c] + p1[c] + p2[c];
        v[c] = t; s += t; ss += t * t;
    }
    blockReduce2_256(s, ss);
    float mean = s / DMODEL;
    float var  = ss / DMODEL - mean * mean;
    float r = rsqrtf(var + LN_EPS);
    __half* orow = g_mh + (size_t)row * DMODEL;
    for (int c = threadIdx.x; c < DMODEL; c += 256)
        orow[c] = __float2half((v[c] - mean) * r * ln2_w[c] + ln2_b[c]);
}

// ---------------- sum 3 split-K partials + bias + residual -> out ----------------
__global__ void reduce_out_kernel(const float* __restrict__ bias,
                                  const float* __restrict__ resid,
                                  float* __restrict__ out) {
    int i = blockIdx.x * blockDim.x + threadIdx.x;    // in float4 units
    if (i >= NTOK * DMODEL / 4) return;
    const float4* p0 = (const float4*)g_part + i;
    const float4* p1 = (const float4*)(g_part + (size_t)NTOK * DMODEL) + i;
    const float4* p2 = (const float4*)(g_part + 2 * (size_t)NTOK * DMODEL) + i;
    float4 a = *p0, b = *p1, c = *p2;
    int n4 = i % (DMODEL / 4);
    float4 bs = ((const float4*)bias)[n4];
    float4 rs = ((const float4*)resid)[i];
    float4 o;
    o.x = a.x + b.x + c.x + bs.x + rs.x;
    o.y = a.y + b.y + c.y + bs.y + rs.y;
    o.z = a.z + b.z + c.z + bs.z + rs.z;
    o.w = a.w + b.w + c.w + bs.w + rs.w;
    ((float4*)out)[i] = o;
}

// ---------------- fp16 tensor-core GEMM: C[M,N] = A[M,K] @ B[N,K]^T ----------------
// Block tile BM x BN, BK=32, 8 warps (WGM x WGN), warp tile (BM/WGM) x 32.
// 4-stage cp.async pipeline. gridDim.z = ksplit: each z handles K/ksplit,
// writing a partial to Cf + z*M*N (no bias/act/resid on split path).
#define NSTAGE 4
template<int BM, int BN, int WGN>
__global__ __launch_bounds__(256) void hgemm(
    const __half* __restrict__ A, const __half* __restrict__ B,
    int M, int N, int K,
    float* __restrict__ Cf, __half* __restrict__ Ch,
    const float* __restrict__ bias, const float* __restrict__ resid, int act)
{
    constexpr int WGM = 8 / WGN;
    constexpr int WTM = BM / WGM;
    constexpr int MI  = WTM / 16;

    extern __shared__ __half smemh[];
    __half* As = smemh;                      // NSTAGE * BM*32
    __half* Bs = smemh + NSTAGE * BM * 32;   // NSTAGE * BN*32

    int tid = threadIdx.x;
    int m0 = blockIdx.y * BM, n0 = blockIdx.x * BN;
    int lane = tid & 31, wid = tid >> 5;
    int wm = wid / WGN, wn = wid % WGN;

    int nsplit = gridDim.z;
    int kc = K / nsplit;                     // K per split (divisible)
    int kbase = blockIdx.z * kc;
    bool is_split = nsplit > 1;
    if (is_split) Cf += (size_t)blockIdx.z * M * N;

    float c[MI][4][4];
    #pragma unroll
    for (int mi = 0; mi < MI; mi++)
        #pragma unroll
        for (int ni = 0; ni < 4; ni++)
            #pragma unroll
            for (int r = 0; r < 4; r++) c[mi][ni][r] = 0.f;

    int KT = kc / 32;

    auto load_stage = [&](int kt, int buf) {
        int k0 = kbase + kt * 32;
        __half* Ab = As + buf * BM * 32;
        __half* Bb = Bs + buf * BN * 32;
        #pragma unroll
        for (int i = 0; i < BM / 64; i++) {
            int ch = tid + i * 256;
            int row = ch >> 2, cx = ch & 3;
            uint32_t da = sptr(&Ab[swz(row, cx)]);
            const __half* sa = A + (size_t)(m0 + row) * K + k0 + cx * 8;
            asm volatile("cp.async.cg.shared.global [%0], [%1], 16;\n"
                         :: "r"(da), "l"(sa));
        }
        #pragma unroll
        for (int i = 0; i < BN / 64; i++) {
            int ch = tid + i * 256;
            int row = ch >> 2, cx = ch & 3;
            int gn = n0 + row;
            int valid = gn < N;
            uint32_t db = sptr(&Bb[swz(row, cx)]);
            const __half* sb = B + (size_t)(valid ? gn : 0) * K + k0 + cx * 8;
            int sz = valid ? 16 : 0;
            asm volatile("cp.async.cg.shared.global [%0], [%1], 16, %2;\n"
                         :: "r"(db), "l"(sb), "r"(sz));
        }
    };

    #pragma unroll
    for (int s = 0; s < NSTAGE - 1; s++) {
        if (s < KT) load_stage(s, s);
        asm volatile("cp.async.commit_group;\n");
    }

    for (int kt = 0; kt < KT; kt++) {
        int buf = kt & (NSTAGE - 1);
        asm volatile("cp.async.wait_group %0;\n" :: "n"(NSTAGE - 2));
        __syncthreads();

        __half* Ab = As + buf * BM * 32;
        __half* Bb = Bs + buf * BN * 32;
        #pragma unroll
        for (int ks = 0; ks < 2; ks++) {
            uint32_t a[MI][4];
            #pragma unroll
            for (int mi = 0; mi < MI; mi++) {
                int row = wm * WTM + mi * 16 + (lane & 15);
                int chunk = ks * 2 + (lane >> 4);
                ldsm4(a[mi], sptr(&Ab[swz(row, chunk)]));
            }
            uint32_t b[4][2];
            #pragma unroll
            for (int np = 0; np < 2; np++) {
                uint32_t t[4];
                int row = wn * 32 + np * 16 + (lane & 7) + ((lane >> 4) & 1) * 8;
                int chunk = ks * 2 + ((lane >> 3) & 1);
                ldsm4(t, sptr(&Bb[swz(row, chunk)]));
                b[np * 2][0] = t[0]; b[np * 2][1] = t[1];
                b[np * 2 + 1][0] = t[2]; b[np * 2 + 1][1] = t[3];
            }
            #pragma unroll
            for (int mi = 0; mi < MI; mi++)
                #pragma unroll
                for (int ni = 0; ni < 4; ni++)
                    mma16816(c[mi][ni], a[mi], b[ni]);
        }

        int nx = kt + NSTAGE - 1;
        if (nx < KT) load_stage(nx, nx & (NSTAGE - 1));
        asm volatile("cp.async.commit_group;\n");
    }

    int gr = lane >> 2, tc = (lane & 3) * 2;
    #pragma unroll
    for (int mi = 0; mi < MI; mi++) {
        #pragma unroll
        for (int ni = 0; ni < 4; ni++) {
            int n = n0 + wn * 32 + ni * 8 + tc;
            if (n < N) {
                #pragma unroll
                for (int h = 0; h < 2; h++) {
                    int m = m0 + wm * WTM + mi * 16 + gr + h * 8;
                    float v0 = c[mi][ni][h * 2];
                    float v1 = c[mi][ni][h * 2 + 1];
                    if (!is_split) {
                        if (bias) { v0 += bias[n]; v1 += bias[n + 1]; }
                        if (act == 1) {
                            v0 = 0.5f * v0 * (1.f + erff(v0 * 0.70710678118654752f));
                            v1 = 0.5f * v1 * (1.f + erff(v1 * 0.70710678118654752f));
                        }
                        if (resid) {
                            v0 += resid[(size_t)m * N + n];
                            v1 += resid[(size_t)m * N + n + 1];
                        }
                        if (Ch) *(__half2*)&Ch[(size_t)m * N + n] = __floats2half2_rn(v0, v1);
                        if (Cf) { float2 o = make_float2(v0, v1); *(float2*)&Cf[(size_t)m * N + n] = o; }
                    } else {
                        float2 o = make_float2(v0, v1);
                        *(float2*)&Cf[(size_t)m * N + n] = o;
                    }
                }
            }
        }
    }
}

// ---------------- tiled conv (both dirs) + SiLU, with fused dt/dA ----------------
#define CT 32
#define CC 128
__global__ __launch_bounds__(256) void conv_silu_tile(const float* __restrict__ w,
                                                      const float* __restrict__ cb,
                                                      const float* __restrict__ dt_bias,
                                                      const float* __restrict__ A_log) {
    int cc = blockIdx.x;
    int tt = blockIdx.y;
    int b  = blockIdx.z;
    int c0 = cc * CC, t0 = tt * CT;
    __shared__ float tile[CT + 6][CC];
    __shared__ float wsh[4][CC];
    __shared__ float bsh[CC];

    // fused dt/dA for this time-tile (cc==0 blocks only)
    if (cc == 0) {
        for (int i = threadIdx.x; i < CT * NHEADS; i += 256) {
            int r = i / NHEADS, h = i % NHEADS;
            int row = b * SEQ + t0 + r;
            float xv = g_zx[(size_t)row * DINPROJ + DINNER + CONVDIM + h] + dt_bias[h];
            float sp = (xv > 20.f) ? xv : log1pf(expf(xv));
            g_dt[(size_t)row * NHEADS + h] = sp;
            g_dA[(size_t)row * NHEADS + h] = expf(-expf(A_log[h]) * sp);
        }
    }

    for (int i = threadIdx.x; i < CC * 4; i += 256) {
        int c = i & (CC - 1), k = i >> 7;
        wsh[k][c] = w[(c0 + c) * 4 + k];
    }
    for (int i = threadIdx.x; i < CC; i += 256) bsh[i] = cb[c0 + i];

    const float* base = g_zx + (size_t)(b * SEQ) * DINPROJ + DINNER + c0;
    for (int i = threadIdx.x; i < (CT + 6) * CC; i += 256) {
        int r = i / CC, c = i % CC;
        int t = t0 - 3 + r;
        tile[r][c] = (t >= 0 && t < SEQ) ? base[(size_t)t * DINPROJ + c] : 0.f;
    }
    __syncthreads();

    for (int i = threadIdx.x; i < CT * CC; i += 256) {
        int r = i / CC, c = i % CC;
        int row = b * SEQ + t0 + r;
        float sf = bsh[c], sb2 = bsh[c];
        #pragma unroll
        for (int k = 0; k < 4; k++) {
            sf  = fmaf(wsh[k][c], tile[r + k][c],     sf);
            sb2 = fmaf(wsh[k][c], tile[r + 6 - k][c], sb2);
        }
        g_xBC[(size_t)row * CONVDIM + c0 + c]          = sf  / (1.f + expf(-sf));
        g_xBC[(size_t)(NTOK + row) * CONVDIM + c0 + c] = sb2 / (1.f + expf(-sb2));
    }
}

// ---------------- selective scan: one block per (h, b, dir) ----------------
__global__ __launch_bounds__(256) void scan_kernel(const float* __restrict__ D_param) {
    int h = blockIdx.x, b = blockIdx.y, dir = blockIdx.z;
    const float* xbc  = g_xBC + (size_t)(dir * NTOK + b * SEQ) * CONVDIM;
    float*       yout = g_y   + (size_t)(dir * NTOK + b * SEQ) * DINNER;
    int tid = threadIdx.x;
    int p = tid >> 2, q = tid & 3, nbase = q * 16;

    __shared__ float sdt[SEQ], sdA[SEQ];
    __shared__ __align__(16) float sbuf[2][192];

    for (int i = tid; i < SEQ; i += 256) {
        sdt[i] = g_dt[(size_t)(b * SEQ + i) * NHEADS + h];
        sdA[i] = g_dA[(size_t)(b * SEQ + i) * NHEADS + h];
    }

    ull hr2[8];
    #pragma unroll
    for (int i = 0; i < 8; i++) hr2[i] = 0ull;
    float Dp = D_param[h];

    auto gload = [&](int t) -> float {
        const float* r = xbc + (size_t)t * CONVDIM;
        if (tid < 64)  return r[h * 64 + tid];
        if (tid < 192) return r[DINNER + (tid - 64)];
        return 0.f;
    };

    float staged = gload(dir ? (SEQ - 1) : 0);

    for (int s = 0; s < SEQ; s++) {
        int t = dir ? (SEQ - 1 - s) : s;
        int buf = s & 1;
        if (tid < 192) sbuf[buf][tid] = staged;
        __syncthreads();
        if (s + 1 < SEQ) staged = gload(dir ? (SEQ - 2 - s) : (s + 1));

        float xp  = sbuf[buf][p];
        float dtv = sdt[t];
        float dAv = sdA[t];
        float bx  = dtv * xp;

        ull B2[8], C2[8];
        const longlong2* Bp = (const longlong2*)&sbuf[buf][64 + nbase];
        const longlong2* Cp = (const longlong2*)&sbuf[buf][128 + nbase];
        #pragma unroll
        for (int i = 0; i < 4; i++) {
            longlong2 v = Bp[i]; B2[2 * i] = (ull)v.x; B2[2 * i + 1] = (ull)v.y;
            longlong2 u = Cp[i]; C2[2 * i] = (ull)u.x; C2[2 * i + 1] = (ull)u.y;
        }
        ull bx2 = pack2(bx, bx);
        ull dA2 = pack2(dAv, dAv);
        ull acca = 0ull, accb = 0ull;
        #pragma unroll
        for (int i = 0; i < 8; i += 2) {
            hr2[i]     = fma2(dA2, hr2[i],     mul2(bx2, B2[i]));
            hr2[i + 1] = fma2(dA2, hr2[i + 1], mul2(bx2, B2[i + 1]));
            acca = fma2(hr2[i],     C2[i],     acca);
            accb = fma2(hr2[i + 1], C2[i + 1], accb);
        }
        ull accp = add2(acca, accb);
        float a0, a1; unpack2(accp, a0, a1);
        float acc = a0 + a1;
        acc += __shfl_xor_sync(0xffffffffu, acc, 1);
        acc += __shfl_xor_sync(0xffffffffu, acc, 2);
        if (q == 0) yout[(size_t)t * DINNER + h * 64 + p] = fmaf(Dp, xp, acc);
    }
}

// ---------------- gate with SiLU(z), per-direction RMSNorm, sum dirs (fp16 out) ----------------
__global__ void gate_rms_kernel(const float* __restrict__ norm_w) {
    int row = blockIdx.x;
    __shared__ float gf[DINNER];
    __shared__ float gb[DINNER];
    const float* zr = g_zx + (size_t)row * DINPROJ;
    const float* yf = g_y  + (size_t)row * DINNER;
    const float* yb = g_y  + (size_t)(NTOK + row) * DINNER;
    float ssf = 0.f, ssb = 0.f;
    for (int c = threadIdx.x; c < DINNER; c += 256) {
        float zc = zr[c];
        float sz = zc / (1.f + expf(-zc));
        float a  = yf[c] * sz;
        float bb = yb[c] * sz;
        gf[c] = a; gb[c] = bb;
        ssf += a * a; ssb += bb * bb;
    }
    blockReduce2_256(ssf, ssb);
    float rf = rsqrtf(ssf / DINNER + LN_EPS);
    float rb = rsqrtf(ssb / DINNER + LN_EPS);
    __half* orow = g_gsumh + (size_t)row * DINNER;
    for (int c = threadIdx.x; c < DINNER; c += 256)
        orow[c] = __float2half((gf[c] * rf + gb[c] * rb) * norm_w[c]);
}

// ---------------- launch ----------------
extern "C" void kernel_launch(void* const* d_in, const int* in_sizes, int n_in,
                              void* d_out, int out_size) {
    const float* x         = (const float*)d_in[0];
    const float* in_proj_w = (const float*)d_in[1];
    const float* conv_w    = (const float*)d_in[2];
    const float* conv_b    = (const float*)d_in[3];
    const float* dt_bias   = (const float*)d_in[4];
    const float* A_log     = (const float*)d_in[5];
    const float* D_param   = (const float*)d_in[6];
    const float* norm_w    = (const float*)d_in[7];
    const float* out_proj_w= (const float*)d_in[8];
    const float* ln1_w     = (const float*)d_in[9];
    const float* ln1_b     = (const float*)d_in[10];
    const float* ln2_w     = (const float*)d_in[11];
    const float* ln2_b     = (const float*)d_in[12];
    const float* ff_w1     = (const float*)d_in[13];
    const float* ff_b1     = (const float*)d_in[14];
    const float* ff_w2     = (const float*)d_in[15];
    const float* ff_b2     = (const float*)d_in[16];
    float* out = (float*)d_out;

    void *p_zx, *p_part, *p_xnh, *p_gsumh, *p_mh, *p_ff1h;
    void *p_wi, *p_wo, *p_w1, *p_w2;
    cudaGetSymbolAddress(&p_zx,    g_zx);
    cudaGetSymbolAddress(&p_part,  g_part);
    cudaGetSymbolAddress(&p_xnh,   g_xnh);
    cudaGetSymbolAddress(&p_gsumh, g_gsumh);
    cudaGetSymbolAddress(&p_mh,    g_mh);
    cudaGetSymbolAddress(&p_ff1h,  g_ff1h);
    cudaGetSymbolAddress(&p_wi,    g_w_inproj_h);
    cudaGetSymbolAddress(&p_wo,    g_w_outproj_h);
    cudaGetSymbolAddress(&p_w1,    g_w_ff1_h);
    cudaGetSymbolAddress(&p_w2,    g_w_ff2_h);

    const int smemA = NSTAGE * (64 + 128) * 32 * sizeof(__half);   // BM=64,BN=128: 48 KB
    const int smemB = NSTAGE * (128 + 64) * 32 * sizeof(__half);   // BM=128,BN=64: 48 KB
    cudaFuncSetAttribute(hgemm<64,128,4>, cudaFuncAttributeMaxDynamicSharedMemorySize, smemA);
    cudaFuncSetAttribute(hgemm<128,64,2>, cudaFuncAttributeMaxDynamicSharedMemorySize, smemB);

    // 0) all weight conversions in one launch
    {
        int n0 = DINPROJ * DMODEL / 8;
        int n1 = DMODEL * DINNER / 8;
        int n2 = DFF * DMODEL / 8;
        int n3 = DMODEL * DFF / 8;
        int tot = n0 + n1 + n2 + n3;
        f2h_all_kernel<<<(tot + 255) / 256, 256>>>(
            in_proj_w, (__half*)p_wi, n0,
            out_proj_w, (__half*)p_wo, n1,
            ff_w1, (__half*)p_w1, n2,
            ff_w2, (__half*)p_w2, n3);
    }

    // 1) LN1 -> fp16 xn
    ln_kernel<<<NTOK, 256>>>(x, ln1_w, ln1_b, (__half*)p_xnh, DMODEL);

    // 2) in_proj GEMM: (1024,768)x(3224,768)^T -> fp32  [BM=64 for wave balance]
    hgemm<64,128,4><<<dim3((DINPROJ + 127) / 128, NTOK / 64), 256, smemA>>>(
        (const __half*)p_xnh, (const __half*)p_wi,
        NTOK, DINPROJ, DMODEL, (float*)p_zx, nullptr, nullptr, nullptr, 0);

    // 3) conv + SiLU (both directions) with fused dt/dA
    conv_silu_tile<<<dim3(CONVDIM / CC, SEQ / CT, BSZ), 256>>>(conv_w, conv_b, dt_bias, A_log);

    // 4) selective scan (both directions)
    scan_kernel<<<dim3(NHEADS, BSZ, 2), 256>>>(D_param);

    // 5) gate + RMSNorm + direction-sum -> fp16
    gate_rms_kernel<<<NTOK, 256>>>(norm_w);

    // 6) out_proj GEMM split-K x3: (1024,1536)x(768,1536)^T -> partials
    hgemm<128,64,2><<<dim3(DMODEL / 64, NTOK / 128, 3), 256, smemB>>>(
        (const __half*)p_gsumh, (const __half*)p_wo,
        NTOK, DMODEL, DINNER, (float*)p_part, nullptr, nullptr, nullptr, 0);

    // 7) reduce partials + LN2 -> fp16 m
    reduce_ln2_kernel<<<NTOK, 256>>>(ln2_w, ln2_b);

    // 8) FF1 + bias + GELU -> fp16  [BM=64]
    hgemm<64,128,4><<<dim3(DFF / 128, NTOK / 64), 256, smemA>>>(
        (const __half*)p_mh, (const __half*)p_w1,
        NTOK, DFF, DMODEL, nullptr, (__half*)p_ff1h, ff_b1, nullptr, 1);

    // 9) FF2 split-K x3 -> partials
    hgemm<128,64,2><<<dim3(DMODEL / 64, NTOK / 128, 3), 256, smemB>>>(
        (const __half*)p_ff1h, (const __half*)p_w2,
        NTOK, DMODEL, DFF, (float*)p_part, nullptr, nullptr, nullptr, 0);

    // 10) reduce partials + bias + residual -> out
    reduce_out_kernel<<<(NTOK * DMODEL / 4 + 255) / 256, 256>>>(ff_b2, x, out);
}

// round 9
// speedup vs baseline: 4.6377x; 1.0514x over previous
#include <cuda_runtime.h>
#include <cuda_fp16.h>
#include <math.h>
#include <stdint.h>

#define BSZ     2
#define SEQ     512
#define DMODEL  768
#define DINNER  1536
#define DSTATE  64
#define NHEADS  24
#define HEADDIM 64
#define CONVDIM 1664            // DINNER + 2*DSTATE
#define DINPROJ 3224            // 2*DINNER + 2*DSTATE + NHEADS
#define NTOK    (BSZ*SEQ)       // 1024
#define DFF     3072
#define LN_EPS  1e-5f
#define LC      64              // scan chunk length
#define NC      (SEQ/LC)        // 8 chunks
#define NSCAN   (2*BSZ*NHEADS)  // 96 (dir x batch x head)

typedef unsigned long long ull;

// ---------------- scratch (static device globals; no allocation) ----------------
__device__ float  g_zx  [NTOK*DINPROJ];
__device__ float  g_xBC [2*NTOK*CONVDIM];
__device__ float  g_dt  [NTOK*NHEADS];
__device__ float  g_dA  [NTOK*NHEADS];
__device__ float  g_y   [2*NTOK*DINNER];
__device__ float  g_part[3*NTOK*DMODEL];       // split-K partials
__device__ float  g_state[NSCAN*NC*4096];      // per-chunk local final states
__device__ float  g_init [NSCAN*NC*4096];      // per-chunk initial states
__device__ float  g_cum  [NSCAN*SEQ];          // in-chunk cumulative dA products
// fp16 activations / weights
__device__ __half g_xnh   [NTOK*DMODEL];
__device__ __half g_gsumh [NTOK*DINNER];
__device__ __half g_mh    [NTOK*DMODEL];
__device__ __half g_ff1h  [NTOK*DFF];
__device__ __half g_w_inproj_h [DINPROJ*DMODEL];
__device__ __half g_w_outproj_h[DMODEL*DINNER];
__device__ __half g_w_ff1_h    [DFF*DMODEL];
__device__ __half g_w_ff2_h    [DMODEL*DFF];

// ---------------- helpers ----------------
__device__ __forceinline__ uint32_t sptr(const void* p) {
    return (uint32_t)__cvta_generic_to_shared(p);
}
__device__ __forceinline__ void ldsm4(uint32_t* r, uint32_t addr) {
    asm volatile("ldmatrix.sync.aligned.m8n8.x4.shared.b16 {%0,%1,%2,%3}, [%4];"
                 : "=r"(r[0]), "=r"(r[1]), "=r"(r[2]), "=r"(r[3]) : "r"(addr));
}
__device__ __forceinline__ void mma16816(float* c, const uint32_t* a, const uint32_t* b) {
    asm volatile("mma.sync.aligned.m16n8k16.row.col.f32.f16.f16.f32 "
                 "{%0,%1,%2,%3}, {%4,%5,%6,%7}, {%8,%9}, {%0,%1,%2,%3};"
                 : "+f"(c[0]), "+f"(c[1]), "+f"(c[2]), "+f"(c[3])
                 : "r"(a[0]), "r"(a[1]), "r"(a[2]), "r"(a[3]), "r"(b[0]), "r"(b[1]));
}
// packed fp32x2 math (FFMA2 — only reachable via PTX)
__device__ __forceinline__ ull pack2(float x, float y) {
    ull r; asm("mov.b64 %0,{%1,%2};" : "=l"(r) : "f"(x), "f"(y)); return r;
}
__device__ __forceinline__ void unpack2(ull v, float& x, float& y) {
    asm("mov.b64 {%0,%1},%2;" : "=f"(x), "=f"(y) : "l"(v));
}
__device__ __forceinline__ ull fma2(ull a, ull b, ull c) {
    ull d; asm("fma.rn.f32x2 %0,%1,%2,%3;" : "=l"(d) : "l"(a), "l"(b), "l"(c)); return d;
}
__device__ __forceinline__ ull mul2(ull a, ull b) {
    ull d; asm("mul.rn.f32x2 %0,%1,%2;" : "=l"(d) : "l"(a), "l"(b)); return d;
}
__device__ __forceinline__ ull add2(ull a, ull b) {
    ull d; asm("add.rn.f32x2 %0,%1,%2;" : "=l"(d) : "l"(a), "l"(b)); return d;
}

// swizzled smem offset (in halves): 32-half (64B) rows, 16B chunks XORed.
__device__ __forceinline__ int swz(int row, int chunk) {
    return row * 32 + ((chunk ^ ((row >> 1) & 3)) << 3);
}

// ---------------- fused fp32 -> fp16 convert for all 4 weights ----------------
__global__ void f2h_all_kernel(const float* __restrict__ w0, __half* __restrict__ o0, int n0,
                               const float* __restrict__ w1, __half* __restrict__ o1, int n1,
                               const float* __restrict__ w2, __half* __restrict__ o2, int n2,
                               const float* __restrict__ w3, __half* __restrict__ o3, int n3) {
    int i = blockIdx.x * blockDim.x + threadIdx.x;
    const float* in; __half* out; int local;
    if (i < n0)                { in = w0; out = o0; local = i; }
    else if (i < n0 + n1)      { in = w1; out = o1; local = i - n0; }
    else if (i < n0 + n1 + n2) { in = w2; out = o2; local = i - n0 - n1; }
    else if (i < n0 + n1 + n2 + n3) { in = w3; out = o3; local = i - n0 - n1 - n2; }
    else return;
    float4 a = ((const float4*)in)[2 * local];
    float4 b = ((const float4*)in)[2 * local + 1];
    __half2 h[4];
    h[0] = __floats2half2_rn(a.x, a.y);
    h[1] = __floats2half2_rn(a.z, a.w);
    h[2] = __floats2half2_rn(b.x, b.y);
    h[3] = __floats2half2_rn(b.z, b.w);
    *(uint4*)&out[8 * local] = *(uint4*)h;
}

// ---------------- block reduce (256 threads, two values) ----------------
__device__ __forceinline__ void blockReduce2_256(float& a, float& b) {
    __shared__ float sa[8], sb[8];
    #pragma unroll
    for (int o = 16; o > 0; o >>= 1) {
        a += __shfl_xor_sync(0xffffffffu, a, o);
        b += __shfl_xor_sync(0xffffffffu, b, o);
    }
    int w = threadIdx.x >> 5, l = threadIdx.x & 31;
    if (l == 0) { sa[w] = a; sb[w] = b; }
    __syncthreads();
    if (w == 0) {
        a = (l < 8) ? sa[l] : 0.f;
        b = (l < 8) ? sb[l] : 0.f;
        #pragma unroll
        for (int o = 4; o > 0; o >>= 1) {
            a += __shfl_xor_sync(0xffffffffu, a, o);
            b += __shfl_xor_sync(0xffffffffu, b, o);
        }
        if (l == 0) { sa[0] = a; sb[0] = b; }
    }
    __syncthreads();
    a = sa[0]; b = sb[0];
}

// ---------------- layernorm (fp32 in, fp16 out) ----------------
__global__ void ln_kernel(const float* __restrict__ x, const float* __restrict__ w,
                          const float* __restrict__ b, __half* __restrict__ out, int D) {
    int row = blockIdx.x;
    const float* xr = x + (size_t)row * D;
    float s = 0.f, ss = 0.f;
    for (int c = threadIdx.x; c < D; c += 256) { float v = xr[c]; s += v; ss += v * v; }
    blockReduce2_256(s, ss);
    float mean = s / D;
    float var  = ss / D - mean * mean;
    float r = rsqrtf(var + LN_EPS);
    __half* orow = out + (size_t)row * D;
    for (int c = threadIdx.x; c < D; c += 256)
        orow[c] = __float2half((xr[c] - mean) * r * w[c] + b[c]);
}

// ---------------- sum 3 split-K partials + LN2 -> fp16 ----------------
__global__ void reduce_ln2_kernel(const float* __restrict__ ln2_w,
                                  const float* __restrict__ ln2_b) {
    int row = blockIdx.x;
    __shared__ float v[DMODEL];
    const float* p0 = g_part + (size_t)row * DMODEL;
    const float* p1 = p0 + (size_t)NTOK * DMODEL;
    const float* p2 = p1 + (size_t)NTOK * DMODEL;
    float s = 0.f, ss = 0.f;
    for (int c = threadIdx.x; c < DMODEL; c += 256) {
        float t = p0[c] + p1[c] + p2[c];
        v[c] = t; s += t; ss += t * t;
    }
    blockReduce2_256(s, ss);
    float mean = s / DMODEL;
    float var  = ss / DMODEL - mean * mean;
    float r = rsqrtf(var + LN_EPS);
    __half* orow = g_mh + (size_t)row * DMODEL;
    for (int c = threadIdx.x; c < DMODEL; c += 256)
        orow[c] = __float2half((v[c] - mean) * r * ln2_w[c] + ln2_b[c]);
}

// ---------------- sum 3 split-K partials + bias + residual -> out ----------------
__global__ void reduce_out_kernel(const float* __restrict__ bias,
                                  const float* __restrict__ resid,
                                  float* __restrict__ out) {
    int i = blockIdx.x * blockDim.x + threadIdx.x;    // in float4 units
    if (i >= NTOK * DMODEL / 4) return;
    const float4* p0 = (const float4*)g_part + i;
    const float4* p1 = (const float4*)(g_part + (size_t)NTOK * DMODEL) + i;
    const float4* p2 = (const float4*)(g_part + 2 * (size_t)NTOK * DMODEL) + i;
    float4 a = *p0, b = *p1, c = *p2;
    int n4 = i % (DMODEL / 4);
    float4 bs = ((const float4*)bias)[n4];
    float4 rs = ((const float4*)resid)[i];
    float4 o;
    o.x = a.x + b.x + c.x + bs.x + rs.x;
    o.y = a.y + b.y + c.y + bs.y + rs.y;
    o.z = a.z + b.z + c.z + bs.z + rs.z;
    o.w = a.w + b.w + c.w + bs.w + rs.w;
    ((float4*)out)[i] = o;
}

// ---------------- fp16 tensor-core GEMM: C[M,N] = A[M,K] @ B[N,K]^T ----------------
#define NSTAGE 4
template<int BM, int BN, int WGN>
__global__ __launch_bounds__(256) void hgemm(
    const __half* __restrict__ A, const __half* __restrict__ B,
    int M, int N, int K,
    float* __restrict__ Cf, __half* __restrict__ Ch,
    const float* __restrict__ bias, const float* __restrict__ resid, int act)
{
    constexpr int WGM = 8 / WGN;
    constexpr int WTM = BM / WGM;
    constexpr int MI  = WTM / 16;

    extern __shared__ __half smemh[];
    __half* As = smemh;
    __half* Bs = smemh + NSTAGE * BM * 32;

    int tid = threadIdx.x;
    int m0 = blockIdx.y * BM, n0 = blockIdx.x * BN;
    int lane = tid & 31, wid = tid >> 5;
    int wm = wid / WGN, wn = wid % WGN;

    int nsplit = gridDim.z;
    int kc = K / nsplit;
    int kbase = blockIdx.z * kc;
    bool is_split = nsplit > 1;
    if (is_split) Cf += (size_t)blockIdx.z * M * N;

    float c[MI][4][4];
    #pragma unroll
    for (int mi = 0; mi < MI; mi++)
        #pragma unroll
        for (int ni = 0; ni < 4; ni++)
            #pragma unroll
            for (int r = 0; r < 4; r++) c[mi][ni][r] = 0.f;

    int KT = kc / 32;

    auto load_stage = [&](int kt, int buf) {
        int k0 = kbase + kt * 32;
        __half* Ab = As + buf * BM * 32;
        __half* Bb = Bs + buf * BN * 32;
        #pragma unroll
        for (int i = 0; i < BM / 64; i++) {
            int ch = tid + i * 256;
            int row = ch >> 2, cx = ch & 3;
            uint32_t da = sptr(&Ab[swz(row, cx)]);
            const __half* sa = A + (size_t)(m0 + row) * K + k0 + cx * 8;
            asm volatile("cp.async.cg.shared.global [%0], [%1], 16;\n"
                         :: "r"(da), "l"(sa));
        }
        #pragma unroll
        for (int i = 0; i < BN / 64; i++) {
            int ch = tid + i * 256;
            int row = ch >> 2, cx = ch & 3;
            int gn = n0 + row;
            int valid = gn < N;
            uint32_t db = sptr(&Bb[swz(row, cx)]);
            const __half* sb = B + (size_t)(valid ? gn : 0) * K + k0 + cx * 8;
            int sz = valid ? 16 : 0;
            asm volatile("cp.async.cg.shared.global [%0], [%1], 16, %2;\n"
                         :: "r"(db), "l"(sb), "r"(sz));
        }
    };

    #pragma unroll
    for (int s = 0; s < NSTAGE - 1; s++) {
        if (s < KT) load_stage(s, s);
        asm volatile("cp.async.commit_group;\n");
    }

    for (int kt = 0; kt < KT; kt++) {
        int buf = kt & (NSTAGE - 1);
        asm volatile("cp.async.wait_group %0;\n" :: "n"(NSTAGE - 2));
        __syncthreads();

        __half* Ab = As + buf * BM * 32;
        __half* Bb = Bs + buf * BN * 32;
        #pragma unroll
        for (int ks = 0; ks < 2; ks++) {
            uint32_t a[MI][4];
            #pragma unroll
            for (int mi = 0; mi < MI; mi++) {
                int row = wm * WTM + mi * 16 + (lane & 15);
                int chunk = ks * 2 + (lane >> 4);
                ldsm4(a[mi], sptr(&Ab[swz(row, chunk)]));
            }
            uint32_t b[4][2];
            #pragma unroll
            for (int np = 0; np < 2; np++) {
                uint32_t t[4];
                int row = wn * 32 + np * 16 + (lane & 7) + ((lane >> 4) & 1) * 8;
                int chunk = ks * 2 + ((lane >> 3) & 1);
                ldsm4(t, sptr(&Bb[swz(row, chunk)]));
                b[np * 2][0] = t[0]; b[np * 2][1] = t[1];
                b[np * 2 + 1][0] = t[2]; b[np * 2 + 1][1] = t[3];
            }
            #pragma unroll
            for (int mi = 0; mi < MI; mi++)
                #pragma unroll
                for (int ni = 0; ni < 4; ni++)
                    mma16816(c[mi][ni], a[mi], b[ni]);
        }

        int nx = kt + NSTAGE - 1;
        if (nx < KT) load_stage(nx, nx & (NSTAGE - 1));
        asm volatile("cp.async.commit_group;\n");
    }

    int gr = lane >> 2, tc = (lane & 3) * 2;
    #pragma unroll
    for (int mi = 0; mi < MI; mi++) {
        #pragma unroll
        for (int ni = 0; ni < 4; ni++) {
            int n = n0 + wn * 32 + ni * 8 + tc;
            if (n < N) {
                #pragma unroll
                for (int h = 0; h < 2; h++) {
                    int m = m0 + wm * WTM + mi * 16 + gr + h * 8;
                    float v0 = c[mi][ni][h * 2];
                    float v1 = c[mi][ni][h * 2 + 1];
                    if (!is_split) {
                        if (bias) { v0 += bias[n]; v1 += bias[n + 1]; }
                        if (act == 1) {
                            v0 = 0.5f * v0 * (1.f + erff(v0 * 0.70710678118654752f));
                            v1 = 0.5f * v1 * (1.f + erff(v1 * 0.70710678118654752f));
                        }
                        if (resid) {
                            v0 += resid[(size_t)m * N + n];
                            v1 += resid[(size_t)m * N + n + 1];
                        }
                        if (Ch) *(__half2*)&Ch[(size_t)m * N + n] = __floats2half2_rn(v0, v1);
                        if (Cf) { float2 o = make_float2(v0, v1); *(float2*)&Cf[(size_t)m * N + n] = o; }
                    } else {
                        float2 o = make_float2(v0, v1);
                        *(float2*)&Cf[(size_t)m * N + n] = o;
                    }
                }
            }
        }
    }
}

// ---------------- tiled conv (both dirs) + SiLU, with fused dt/dA ----------------
#define CT 32
#define CC 128
__global__ __launch_bounds__(256) void conv_silu_tile(const float* __restrict__ w,
                                                      const float* __restrict__ cb,
                                                      const float* __restrict__ dt_bias,
                                                      const float* __restrict__ A_log) {
    int cc = blockIdx.x;
    int tt = blockIdx.y;
    int b  = blockIdx.z;
    int c0 = cc * CC, t0 = tt * CT;
    __shared__ float tile[CT + 6][CC];
    __shared__ float wsh[4][CC];
    __shared__ float bsh[CC];

    if (cc == 0) {
        for (int i = threadIdx.x; i < CT * NHEADS; i += 256) {
            int r = i / NHEADS, h = i % NHEADS;
            int row = b * SEQ + t0 + r;
            float xv = g_zx[(size_t)row * DINPROJ + DINNER + CONVDIM + h] + dt_bias[h];
            float sp = (xv > 20.f) ? xv : log1pf(expf(xv));
            g_dt[(size_t)row * NHEADS + h] = sp;
            g_dA[(size_t)row * NHEADS + h] = expf(-expf(A_log[h]) * sp);
        }
    }

    for (int i = threadIdx.x; i < CC * 4; i += 256) {
        int c = i & (CC - 1), k = i >> 7;
        wsh[k][c] = w[(c0 + c) * 4 + k];
    }
    for (int i = threadIdx.x; i < CC; i += 256) bsh[i] = cb[c0 + i];

    const float* base = g_zx + (size_t)(b * SEQ) * DINPROJ + DINNER + c0;
    for (int i = threadIdx.x; i < (CT + 6) * CC; i += 256) {
        int r = i / CC, c = i % CC;
        int t = t0 - 3 + r;
        tile[r][c] = (t >= 0 && t < SEQ) ? base[(size_t)t * DINPROJ + c] : 0.f;
    }
    __syncthreads();

    for (int i = threadIdx.x; i < CT * CC; i += 256) {
        int r = i / CC, c = i % CC;
        int row = b * SEQ + t0 + r;
        float sf = bsh[c], sb2 = bsh[c];
        #pragma unroll
        for (int k = 0; k < 4; k++) {
            sf  = fmaf(wsh[k][c], tile[r + k][c],     sf);
            sb2 = fmaf(wsh[k][c], tile[r + 6 - k][c], sb2);
        }
        g_xBC[(size_t)row * CONVDIM + c0 + c]          = sf  / (1.f + expf(-sf));
        g_xBC[(size_t)(NTOK + row) * CONVDIM + c0 + c] = sb2 / (1.f + expf(-sb2));
    }
}

// ---------------- scan pass A: per-chunk local scan (h_init = 0) ----------------
// grid (NHEADS, BSZ, 2*NC): z = dir*NC + chunk. Writes y_local, final state, cumdA.
__global__ __launch_bounds__(256) void scanA_kernel(const float* __restrict__ D_param) {
    int h = blockIdx.x, b = blockIdx.y;
    int dir = blockIdx.z / NC, chunk = blockIdx.z % NC;
    int idx = (dir * BSZ + b) * NHEADS + h;
    const float* xbc  = g_xBC + (size_t)(dir * NTOK + b * SEQ) * CONVDIM;
    float*       yout = g_y   + (size_t)(dir * NTOK + b * SEQ) * DINNER;
    int tid = threadIdx.x;
    int p = tid >> 2, q = tid & 3, nbase = q * 16;
    int s0 = chunk * LC;

    __shared__ float sdt[LC], sdA[LC];
    __shared__ __align__(16) float sbuf[2][192];

    for (int i = tid; i < LC; i += 256) {
        int t = dir ? (SEQ - 1 - (s0 + i)) : (s0 + i);
        sdt[i] = g_dt[(size_t)(b * SEQ + t) * NHEADS + h];
        sdA[i] = g_dA[(size_t)(b * SEQ + t) * NHEADS + h];
    }

    ull hr2[8];
    #pragma unroll
    for (int i = 0; i < 8; i++) hr2[i] = 0ull;
    float Dp = D_param[h];
    float cum = 1.f;

    auto gload = [&](int s) -> float {
        int t = dir ? (SEQ - 1 - s) : s;
        const float* r = xbc + (size_t)t * CONVDIM;
        if (tid < 64)  return r[h * 64 + tid];
        if (tid < 192) return r[DINNER + (tid - 64)];
        return 0.f;
    };

    float staged = gload(s0);

    for (int sl = 0; sl < LC; sl++) {
        int s = s0 + sl;
        int t = dir ? (SEQ - 1 - s) : s;
        int buf = sl & 1;
        if (tid < 192) sbuf[buf][tid] = staged;
        __syncthreads();
        if (sl + 1 < LC) staged = gload(s + 1);

        float xp  = sbuf[buf][p];
        float dtv = sdt[sl];
        float dAv = sdA[sl];
        float bx  = dtv * xp;
        cum *= dAv;

        ull B2[8], C2[8];
        const longlong2* Bp = (const longlong2*)&sbuf[buf][64 + nbase];
        const longlong2* Cp = (const longlong2*)&sbuf[buf][128 + nbase];
        #pragma unroll
        for (int i = 0; i < 4; i++) {
            longlong2 v = Bp[i]; B2[2 * i] = (ull)v.x; B2[2 * i + 1] = (ull)v.y;
            longlong2 u = Cp[i]; C2[2 * i] = (ull)u.x; C2[2 * i + 1] = (ull)u.y;
        }
        ull bx2 = pack2(bx, bx);
        ull dA2 = pack2(dAv, dAv);
        ull acca = 0ull, accb = 0ull;
        #pragma unroll
        for (int i = 0; i < 8; i += 2) {
            hr2[i]     = fma2(dA2, hr2[i],     mul2(bx2, B2[i]));
            hr2[i + 1] = fma2(dA2, hr2[i + 1], mul2(bx2, B2[i + 1]));
            acca = fma2(hr2[i],     C2[i],     acca);
            accb = fma2(hr2[i + 1], C2[i + 1], accb);
        }
        ull accp = add2(acca, accb);
        float a0, a1; unpack2(accp, a0, a1);
        float acc = a0 + a1;
        acc += __shfl_xor_sync(0xffffffffu, acc, 1);
        acc += __shfl_xor_sync(0xffffffffu, acc, 2);
        if (q == 0) yout[(size_t)t * DINNER + h * 64 + p] = fmaf(Dp, xp, acc);
        if (tid == 0) g_cum[(size_t)idx * SEQ + s] = cum;
    }

    // store final local state (16 floats per thread, thread-contiguous layout)
    float* st = g_state + ((size_t)idx * NC + chunk) * 4096 + tid * 16;
    #pragma unroll
    for (int i = 0; i < 8; i++) {
        float x0, x1; unpack2(hr2[i], x0, x1);
        st[2 * i] = x0; st[2 * i + 1] = x1;
    }
}

// ---------------- scan pass B: sequential chunk combine ----------------
// grid (NHEADS, BSZ, 2). h_init(c) = P_{c-1} * h_init(c-1) + L_{c-1}, c = 1..NC-1.
__global__ __launch_bounds__(256) void scanB_kernel() {
    int h = blockIdx.x, b = blockIdx.y, dir = blockIdx.z;
    int idx = (dir * BSZ + b) * NHEADS + h;
    int tid = threadIdx.x;
    float hin[16];
    #pragma unroll
    for (int i = 0; i < 16; i++) hin[i] = 0.f;
    for (int c = 1; c < NC; c++) {
        float P = g_cum[(size_t)idx * SEQ + c * LC - 1];
        const float4* L = (const float4*)(g_state + ((size_t)idx * NC + (c - 1)) * 4096 + tid * 16);
        float4* O = (float4*)(g_init + ((size_t)idx * NC + c) * 4096 + tid * 16);
        #pragma unroll
        for (int i = 0; i < 4; i++) {
            float4 l = L[i];
            float4 o;
            o.x = fmaf(P, hin[4 * i],     l.x);
            o.y = fmaf(P, hin[4 * i + 1], l.y);
            o.z = fmaf(P, hin[4 * i + 2], l.z);
            o.w = fmaf(P, hin[4 * i + 3], l.w);
            hin[4 * i] = o.x; hin[4 * i + 1] = o.y; hin[4 * i + 2] = o.z; hin[4 * i + 3] = o.w;
            O[i] = o;
        }
    }
}

// ---------------- scan pass C: correction y += cumdA * (C . h_init) ----------------
// grid (NHEADS, BSZ, 2*(NC-1)): z = dir*(NC-1) + (chunk-1).
__global__ __launch_bounds__(256) void scanC_kernel() {
    int h = blockIdx.x, b = blockIdx.y;
    int dir = blockIdx.z / (NC - 1), chunk = blockIdx.z % (NC - 1) + 1;
    int idx = (dir * BSZ + b) * NHEADS + h;
    const float* xbc  = g_xBC + (size_t)(dir * NTOK + b * SEQ) * CONVDIM;
    float*       yout = g_y   + (size_t)(dir * NTOK + b * SEQ) * DINNER;
    int tid = threadIdx.x;
    int p = tid >> 2, q = tid & 3, nbase = q * 16;
    int s0 = chunk * LC;

    __shared__ float scum[LC];
    __shared__ __align__(16) float sC[2][64];

    for (int i = tid; i < LC; i += 256)
        scum[i] = g_cum[(size_t)idx * SEQ + s0 + i];

    // h_init slice for this thread: p row, nbase..nbase+15
    float hin[16];
    {
        const float4* H = (const float4*)(g_init + ((size_t)idx * NC + chunk) * 4096 + tid * 16);
        #pragma unroll
        for (int i = 0; i < 4; i++) {
            float4 v = H[i];
            hin[4 * i] = v.x; hin[4 * i + 1] = v.y; hin[4 * i + 2] = v.z; hin[4 * i + 3] = v.w;
        }
    }

    auto gloadC = [&](int s) -> float {
        int t = dir ? (SEQ - 1 - s) : s;
        if (tid < 64) return xbc[(size_t)t * CONVDIM + DINNER + DSTATE + tid];
        return 0.f;
    };

    float staged = gloadC(s0);

    for (int sl = 0; sl < LC; sl++) {
        int s = s0 + sl;
        int t = dir ? (SEQ - 1 - s) : s;
        int buf = sl & 1;
        if (tid < 64) sC[buf][tid] = staged;
        __syncthreads();
        if (sl + 1 < LC) staged = gloadC(s + 1);

        const float* Cv = &sC[buf][nbase];
        float acc = 0.f;
        #pragma unroll
        for (int i = 0; i < 16; i++) acc = fmaf(Cv[i], hin[i], acc);
        acc += __shfl_xor_sync(0xffffffffu, acc, 1);
        acc += __shfl_xor_sync(0xffffffffu, acc, 2);
        if (q == 0) {
            float* yp = &yout[(size_t)t * DINNER + h * 64 + p];
            *yp = fmaf(scum[sl], acc, *yp);
        }
    }
}

// ---------------- gate with SiLU(z), per-direction RMSNorm, sum dirs (fp16 out) ----------------
__global__ void gate_rms_kernel(const float* __restrict__ norm_w) {
    int row = blockIdx.x;
    __shared__ float gf[DINNER];
    __shared__ float gb[DINNER];
    const float* zr = g_zx + (size_t)row * DINPROJ;
    const float* yf = g_y  + (size_t)row * DINNER;
    const float* yb = g_y  + (size_t)(NTOK + row) * DINNER;
    float ssf = 0.f, ssb = 0.f;
    for (int c = threadIdx.x; c < DINNER; c += 256) {
        float zc = zr[c];
        float sz = zc / (1.f + expf(-zc));
        float a  = yf[c] * sz;
        float bb = yb[c] * sz;
        gf[c] = a; gb[c] = bb;
        ssf += a * a; ssb += bb * bb;
    }
    blockReduce2_256(ssf, ssb);
    float rf = rsqrtf(ssf / DINNER + LN_EPS);
    float rb = rsqrtf(ssb / DINNER + LN_EPS);
    __half* orow = g_gsumh + (size_t)row * DINNER;
    for (int c = threadIdx.x; c < DINNER; c += 256)
        orow[c] = __float2half((gf[c] * rf + gb[c] * rb) * norm_w[c]);
}

// ---------------- launch ----------------
extern "C" void kernel_launch(void* const* d_in, const int* in_sizes, int n_in,
                              void* d_out, int out_size) {
    const float* x         = (const float*)d_in[0];
    const float* in_proj_w = (const float*)d_in[1];
    const float* conv_w    = (const float*)d_in[2];
    const float* conv_b    = (const float*)d_in[3];
    const float* dt_bias   = (const float*)d_in[4];
    const float* A_log     = (const float*)d_in[5];
    const float* D_param   = (const float*)d_in[6];
    const float* norm_w    = (const float*)d_in[7];
    const float* out_proj_w= (const float*)d_in[8];
    const float* ln1_w     = (const float*)d_in[9];
    const float* ln1_b     = (const float*)d_in[10];
    const float* ln2_w     = (const float*)d_in[11];
    const float* ln2_b     = (const float*)d_in[12];
    const float* ff_w1     = (const float*)d_in[13];
    const float* ff_b1     = (const float*)d_in[14];
    const float* ff_w2     = (const float*)d_in[15];
    const float* ff_b2     = (const float*)d_in[16];
    float* out = (float*)d_out;

    void *p_zx, *p_part, *p_xnh, *p_gsumh, *p_mh, *p_ff1h;
    void *p_wi, *p_wo, *p_w1, *p_w2;
    cudaGetSymbolAddress(&p_zx,    g_zx);
    cudaGetSymbolAddress(&p_part,  g_part);
    cudaGetSymbolAddress(&p_xnh,   g_xnh);
    cudaGetSymbolAddress(&p_gsumh, g_gsumh);
    cudaGetSymbolAddress(&p_mh,    g_mh);
    cudaGetSymbolAddress(&p_ff1h,  g_ff1h);
    cudaGetSymbolAddress(&p_wi,    g_w_inproj_h);
    cudaGetSymbolAddress(&p_wo,    g_w_outproj_h);
    cudaGetSymbolAddress(&p_w1,    g_w_ff1_h);
    cudaGetSymbolAddress(&p_w2,    g_w_ff2_h);

    const int smemA = NSTAGE * (64 + 128) * 32 * sizeof(__half);   // 48 KB
    const int smemB = NSTAGE * (128 + 64) * 32 * sizeof(__half);   // 48 KB
    cudaFuncSetAttribute(hgemm<64,128,4>, cudaFuncAttributeMaxDynamicSharedMemorySize, smemA);
    cudaFuncSetAttribute(hgemm<128,64,2>, cudaFuncAttributeMaxDynamicSharedMemorySize, smemB);

    // 0) all weight conversions in one launch
    {
        int n0 = DINPROJ * DMODEL / 8;
        int n1 = DMODEL * DINNER / 8;
        int n2 = DFF * DMODEL / 8;
        int n3 = DMODEL * DFF / 8;
        int tot = n0 + n1 + n2 + n3;
        f2h_all_kernel<<<(tot + 255) / 256, 256>>>(
            in_proj_w, (__half*)p_wi, n0,
            out_proj_w, (__half*)p_wo, n1,
            ff_w1, (__half*)p_w1, n2,
            ff_w2, (__half*)p_w2, n3);
    }

    // 1) LN1 -> fp16 xn
    ln_kernel<<<NTOK, 256>>>(x, ln1_w, ln1_b, (__half*)p_xnh, DMODEL);

    // 2) in_proj GEMM: (1024,768)x(3224,768)^T -> fp32
    hgemm<64,128,4><<<dim3((DINPROJ + 127) / 128, NTOK / 64), 256, smemA>>>(
        (const __half*)p_xnh, (const __half*)p_wi,
        NTOK, DINPROJ, DMODEL, (float*)p_zx, nullptr, nullptr, nullptr, 0);

    // 3) conv + SiLU (both directions) with fused dt/dA
    conv_silu_tile<<<dim3(CONVDIM / CC, SEQ / CT, BSZ), 256>>>(conv_w, conv_b, dt_bias, A_log);

    // 4) chunked selective scan: local scans, combine, correction
    scanA_kernel<<<dim3(NHEADS, BSZ, 2 * NC), 256>>>(D_param);
    scanB_kernel<<<dim3(NHEADS, BSZ, 2), 256>>>();
    scanC_kernel<<<dim3(NHEADS, BSZ, 2 * (NC - 1)), 256>>>();

    // 5) gate + RMSNorm + direction-sum -> fp16
    gate_rms_kernel<<<NTOK, 256>>>(norm_w);

    // 6) out_proj GEMM split-K x3 -> partials
    hgemm<128,64,2><<<dim3(DMODEL / 64, NTOK / 128, 3), 256, smemB>>>(
        (const __half*)p_gsumh, (const __half*)p_wo,
        NTOK, DMODEL, DINNER, (float*)p_part, nullptr, nullptr, nullptr, 0);

    // 7) reduce partials + LN2 -> fp16 m
    reduce_ln2_kernel<<<NTOK, 256>>>(ln2_w, ln2_b);

    // 8) FF1 + bias + GELU -> fp16
    hgemm<64,128,4><<<dim3(DFF / 128, NTOK / 64), 256, smemA>>>(
        (const __half*)p_mh, (const __half*)p_w1,
        NTOK, DFF, DMODEL, nullptr, (__half*)p_ff1h, ff_b1, nullptr, 1);

    // 9) FF2 split-K x3 -> partials
    hgemm<128,64,2><<<dim3(DMODEL / 64, NTOK / 128, 3), 256, smemB>>>(
        (const __half*)p_ff1h, (const __half*)p_w2,
        NTOK, DMODEL, DFF, (float*)p_part, nullptr, nullptr, nullptr, 0);

    // 10) reduce partials + bias + residual -> out
    reduce_out_kernel<<<(NTOK * DMODEL / 4 + 255) / 256, 256>>>(ff_b2, x, out);
}

// round 10
// speedup vs baseline: 4.8093x; 1.0370x over previous
#include <cuda_runtime.h>
#include <cuda_fp16.h>
#include <math.h>
#include <stdint.h>

#define BSZ     2
#define SEQ     512
#define DMODEL  768
#define DINNER  1536
#define DSTATE  64
#define NHEADS  24
#define HEADDIM 64
#define CONVDIM 1664            // DINNER + 2*DSTATE
#define DINPROJ 3224            // 2*DINNER + 2*DSTATE + NHEADS
#define NTOK    (BSZ*SEQ)       // 1024
#define DFF     3072
#define LN_EPS  1e-5f
#define LC      64              // scan chunk length
#define NC      (SEQ/LC)        // 8 chunks
#define NSCAN   (2*BSZ*NHEADS)  // 96
#define KSPLIT  6

typedef unsigned long long ull;

// ---------------- scratch (static device globals; no allocation) ----------------
__device__ float  g_zx  [NTOK*DINPROJ];
__device__ float  g_xBC [2*NTOK*CONVDIM];
__device__ float  g_dt  [NTOK*NHEADS];
__device__ float  g_dA  [NTOK*NHEADS];
__device__ float  g_y   [2*NTOK*DINNER];
__device__ float  g_part[KSPLIT*NTOK*DMODEL];  // split-K partials
__device__ float  g_state[NSCAN*NC*4096];
__device__ float  g_init [NSCAN*NC*4096];
__device__ float  g_cum  [NSCAN*SEQ];
// fp16 activations / weights
__device__ __half g_xnh   [NTOK*DMODEL];
__device__ __half g_gsumh [NTOK*DINNER];
__device__ __half g_mh    [NTOK*DMODEL];
__device__ __half g_ff1h  [NTOK*DFF];
__device__ __half g_w_inproj_h [DINPROJ*DMODEL];
__device__ __half g_w_outproj_h[DMODEL*DINNER];
__device__ __half g_w_ff1_h    [DFF*DMODEL];
__device__ __half g_w_ff2_h    [DMODEL*DFF];

// ---------------- helpers ----------------
__device__ __forceinline__ uint32_t sptr(const void* p) {
    return (uint32_t)__cvta_generic_to_shared(p);
}
__device__ __forceinline__ void ldsm4(uint32_t* r, uint32_t addr) {
    asm volatile("ldmatrix.sync.aligned.m8n8.x4.shared.b16 {%0,%1,%2,%3}, [%4];"
                 : "=r"(r[0]), "=r"(r[1]), "=r"(r[2]), "=r"(r[3]) : "r"(addr));
}
__device__ __forceinline__ void mma16816(float* c, const uint32_t* a, const uint32_t* b) {
    asm volatile("mma.sync.aligned.m16n8k16.row.col.f32.f16.f16.f32 "
                 "{%0,%1,%2,%3}, {%4,%5,%6,%7}, {%8,%9}, {%0,%1,%2,%3};"
                 : "+f"(c[0]), "+f"(c[1]), "+f"(c[2]), "+f"(c[3])
                 : "r"(a[0]), "r"(a[1]), "r"(a[2]), "r"(a[3]), "r"(b[0]), "r"(b[1]));
}
// packed fp32x2 math (FFMA2 — only reachable via PTX)
__device__ __forceinline__ ull pack2(float x, float y) {
    ull r; asm("mov.b64 %0,{%1,%2};" : "=l"(r) : "f"(x), "f"(y)); return r;
}
__device__ __forceinline__ void unpack2(ull v, float& x, float& y) {
    asm("mov.b64 {%0,%1},%2;" : "=f"(x), "=f"(y) : "l"(v));
}
__device__ __forceinline__ ull fma2(ull a, ull b, ull c) {
    ull d; asm("fma.rn.f32x2 %0,%1,%2,%3;" : "=l"(d) : "l"(a), "l"(b), "l"(c)); return d;
}
__device__ __forceinline__ ull mul2(ull a, ull b) {
    ull d; asm("mul.rn.f32x2 %0,%1,%2;" : "=l"(d) : "l"(a), "l"(b)); return d;
}
__device__ __forceinline__ ull add2(ull a, ull b) {
    ull d; asm("add.rn.f32x2 %0,%1,%2;" : "=l"(d) : "l"(a), "l"(b)); return d;
}
__device__ __forceinline__ int swz(int row, int chunk) {
    return row * 32 + ((chunk ^ ((row >> 1) & 3)) << 3);
}

// ---------------- fused fp32 -> fp16 convert for all 4 weights ----------------
__global__ void f2h_all_kernel(const float* __restrict__ w0, __half* __restrict__ o0, int n0,
                               const float* __restrict__ w1, __half* __restrict__ o1, int n1,
                               const float* __restrict__ w2, __half* __restrict__ o2, int n2,
                               const float* __restrict__ w3, __half* __restrict__ o3, int n3) {
    int i = blockIdx.x * blockDim.x + threadIdx.x;
    const float* in; __half* out; int local;
    if (i < n0)                { in = w0; out = o0; local = i; }
    else if (i < n0 + n1)      { in = w1; out = o1; local = i - n0; }
    else if (i < n0 + n1 + n2) { in = w2; out = o2; local = i - n0 - n1; }
    else if (i < n0 + n1 + n2 + n3) { in = w3; out = o3; local = i - n0 - n1 - n2; }
    else return;
    float4 a = ((const float4*)in)[2 * local];
    float4 b = ((const float4*)in)[2 * local + 1];
    __half2 h[4];
    h[0] = __floats2half2_rn(a.x, a.y);
    h[1] = __floats2half2_rn(a.z, a.w);
    h[2] = __floats2half2_rn(b.x, b.y);
    h[3] = __floats2half2_rn(b.z, b.w);
    *(uint4*)&out[8 * local] = *(uint4*)h;
}

// ---------------- block reduce (256 threads, two values) ----------------
__device__ __forceinline__ void blockReduce2_256(float& a, float& b) {
    __shared__ float sa[8], sb[8];
    #pragma unroll
    for (int o = 16; o > 0; o >>= 1) {
        a += __shfl_xor_sync(0xffffffffu, a, o);
        b += __shfl_xor_sync(0xffffffffu, b, o);
    }
    int w = threadIdx.x >> 5, l = threadIdx.x & 31;
    if (l == 0) { sa[w] = a; sb[w] = b; }
    __syncthreads();
    if (w == 0) {
        a = (l < 8) ? sa[l] : 0.f;
        b = (l < 8) ? sb[l] : 0.f;
        #pragma unroll
        for (int o = 4; o > 0; o >>= 1) {
            a += __shfl_xor_sync(0xffffffffu, a, o);
            b += __shfl_xor_sync(0xffffffffu, b, o);
        }
        if (l == 0) { sa[0] = a; sb[0] = b; }
    }
    __syncthreads();
    a = sa[0]; b = sb[0];
}

// ---------------- layernorm (fp32 in, fp16 out) ----------------
__global__ void ln_kernel(const float* __restrict__ x, const float* __restrict__ w,
                          const float* __restrict__ b, __half* __restrict__ out, int D) {
    int row = blockIdx.x;
    const float* xr = x + (size_t)row * D;
    float s = 0.f, ss = 0.f;
    for (int c = threadIdx.x; c < D; c += 256) { float v = xr[c]; s += v; ss += v * v; }
    blockReduce2_256(s, ss);
    float mean = s / D;
    float var  = ss / D - mean * mean;
    float r = rsqrtf(var + LN_EPS);
    __half* orow = out + (size_t)row * D;
    for (int c = threadIdx.x; c < D; c += 256)
        orow[c] = __float2half((xr[c] - mean) * r * w[c] + b[c]);
}

// ---------------- sum split-K partials + LN2 -> fp16 ----------------
__global__ void reduce_ln2_kernel(const float* __restrict__ ln2_w,
                                  const float* __restrict__ ln2_b) {
    int row = blockIdx.x;
    __shared__ float v[DMODEL];
    float s = 0.f, ss = 0.f;
    for (int c = threadIdx.x; c < DMODEL; c += 256) {
        float t = 0.f;
        #pragma unroll
        for (int k = 0; k < KSPLIT; k++)
            t += g_part[(size_t)k * NTOK * DMODEL + (size_t)row * DMODEL + c];
        v[c] = t; s += t; ss += t * t;
    }
    blockReduce2_256(s, ss);
    float mean = s / DMODEL;
    float var  = ss / DMODEL - mean * mean;
    float r = rsqrtf(var + LN_EPS);
    __half* orow = g_mh + (size_t)row * DMODEL;
    for (int c = threadIdx.x; c < DMODEL; c += 256)
        orow[c] = __float2half((v[c] - mean) * r * ln2_w[c] + ln2_b[c]);
}

// ---------------- sum split-K partials + bias + residual -> out ----------------
__global__ void reduce_out_kernel(const float* __restrict__ bias,
                                  const float* __restrict__ resid,
                                  float* __restrict__ out) {
    int i = blockIdx.x * blockDim.x + threadIdx.x;    // float4 units
    if (i >= NTOK * DMODEL / 4) return;
    float4 acc = make_float4(0.f, 0.f, 0.f, 0.f);
    #pragma unroll
    for (int k = 0; k < KSPLIT; k++) {
        float4 p = ((const float4*)(g_part + (size_t)k * NTOK * DMODEL))[i];
        acc.x += p.x; acc.y += p.y; acc.z += p.z; acc.w += p.w;
    }
    int n4 = i % (DMODEL / 4);
    float4 bs = ((const float4*)bias)[n4];
    float4 rs = ((const float4*)resid)[i];
    acc.x += bs.x + rs.x; acc.y += bs.y + rs.y;
    acc.z += bs.z + rs.z; acc.w += bs.w + rs.w;
    ((float4*)out)[i] = acc;
}

// ---------------- fp16 tensor-core GEMM: C[M,N] = A[M,K] @ B[N,K]^T ----------------
// Block tile BM x BN, BK=32, 8 warps (WGM x WGN), warp tile 32 x 64 (MI=2, NI=8).
// 4-stage cp.async pipeline. gridDim.z = ksplit (partials to Cf + z*M*N).
#define NSTAGE 4
template<int BM, int BN, int WGM, int WGN>
__global__ __launch_bounds__(256, 2) void hgemm(
    const __half* __restrict__ A, const __half* __restrict__ B,
    int M, int N, int K,
    float* __restrict__ Cf, __half* __restrict__ Ch,
    const float* __restrict__ bias, const float* __restrict__ resid, int act)
{
    static_assert(WGM * WGN == 8, "8 warps");
    constexpr int WTM = BM / WGM;     // 32
    constexpr int WTN = BN / WGN;     // 64
    constexpr int MI  = WTM / 16;     // 2
    constexpr int NP  = WTN / 16;     // 4
    constexpr int NI  = WTN / 8;      // 8

    extern __shared__ __half smemh[];
    __half* As = smemh;
    __half* Bs = smemh + NSTAGE * BM * 32;

    int tid = threadIdx.x;
    int m0 = blockIdx.y * BM, n0 = blockIdx.x * BN;
    int lane = tid & 31, wid = tid >> 5;
    int wm = wid / WGN, wn = wid % WGN;

    int nsplit = gridDim.z;
    int kc = K / nsplit;
    int kbase = blockIdx.z * kc;
    bool is_split = nsplit > 1;
    if (is_split) Cf += (size_t)blockIdx.z * M * N;

    float c[MI][NI][4];
    #pragma unroll
    for (int mi = 0; mi < MI; mi++)
        #pragma unroll
        for (int ni = 0; ni < NI; ni++)
            #pragma unroll
            for (int r = 0; r < 4; r++) c[mi][ni][r] = 0.f;

    int KT = kc / 32;

    auto load_stage = [&](int kt, int buf) {
        int k0 = kbase + kt * 32;
        __half* Ab = As + buf * BM * 32;
        __half* Bb = Bs + buf * BN * 32;
        #pragma unroll
        for (int i = 0; i < BM / 64; i++) {
            int ch = tid + i * 256;
            int row = ch >> 2, cx = ch & 3;
            uint32_t da = sptr(&Ab[swz(row, cx)]);
            const __half* sa = A + (size_t)(m0 + row) * K + k0 + cx * 8;
            asm volatile("cp.async.cg.shared.global [%0], [%1], 16;\n"
                         :: "r"(da), "l"(sa));
        }
        #pragma unroll
        for (int i = 0; i < BN / 64; i++) {
            int ch = tid + i * 256;
            int row = ch >> 2, cx = ch & 3;
            int gn = n0 + row;
            int valid = gn < N;
            uint32_t db = sptr(&Bb[swz(row, cx)]);
            const __half* sb = B + (size_t)(valid ? gn : 0) * K + k0 + cx * 8;
            int sz = valid ? 16 : 0;
            asm volatile("cp.async.cg.shared.global [%0], [%1], 16, %2;\n"
                         :: "r"(db), "l"(sb), "r"(sz));
        }
    };

    #pragma unroll
    for (int s = 0; s < NSTAGE - 1; s++) {
        if (s < KT) load_stage(s, s);
        asm volatile("cp.async.commit_group;\n");
    }

    for (int kt = 0; kt < KT; kt++) {
        int buf = kt & (NSTAGE - 1);
        asm volatile("cp.async.wait_group %0;\n" :: "n"(NSTAGE - 2));
        __syncthreads();

        __half* Ab = As + buf * BM * 32;
        __half* Bb = Bs + buf * BN * 32;
        #pragma unroll
        for (int ks = 0; ks < 2; ks++) {
            uint32_t a[MI][4];
            #pragma unroll
            for (int mi = 0; mi < MI; mi++) {
                int row = wm * WTM + mi * 16 + (lane & 15);
                int chunk = ks * 2 + (lane >> 4);
                ldsm4(a[mi], sptr(&Ab[swz(row, chunk)]));
            }
            uint32_t b[NI][2];
            #pragma unroll
            for (int np = 0; np < NP; np++) {
                uint32_t t[4];
                int row = wn * WTN + np * 16 + (lane & 7) + ((lane >> 4) & 1) * 8;
                int chunk = ks * 2 + ((lane >> 3) & 1);
                ldsm4(t, sptr(&Bb[swz(row, chunk)]));
                b[np * 2][0] = t[0]; b[np * 2][1] = t[1];
                b[np * 2 + 1][0] = t[2]; b[np * 2 + 1][1] = t[3];
            }
            #pragma unroll
            for (int mi = 0; mi < MI; mi++)
                #pragma unroll
                for (int ni = 0; ni < NI; ni++)
                    mma16816(c[mi][ni], a[mi], b[ni]);
        }

        int nx = kt + NSTAGE - 1;
        if (nx < KT) load_stage(nx, nx & (NSTAGE - 1));
        asm volatile("cp.async.commit_group;\n");
    }

    int gr = lane >> 2, tc = (lane & 3) * 2;
    #pragma unroll
    for (int mi = 0; mi < MI; mi++) {
        #pragma unroll
        for (int ni = 0; ni < NI; ni++) {
            int n = n0 + wn * WTN + ni * 8 + tc;
            if (n < N) {
                #pragma unroll
                for (int h = 0; h < 2; h++) {
                    int m = m0 + wm * WTM + mi * 16 + gr + h * 8;
                    float v0 = c[mi][ni][h * 2];
                    float v1 = c[mi][ni][h * 2 + 1];
                    if (!is_split) {
                        if (bias) { v0 += bias[n]; v1 += bias[n + 1]; }
                        if (act == 1) {
                            v0 = 0.5f * v0 * (1.f + erff(v0 * 0.70710678118654752f));
                            v1 = 0.5f * v1 * (1.f + erff(v1 * 0.70710678118654752f));
                        }
                        if (resid) {
                            v0 += resid[(size_t)m * N + n];
                            v1 += resid[(size_t)m * N + n + 1];
                        }
                        if (Ch) *(__half2*)&Ch[(size_t)m * N + n] = __floats2half2_rn(v0, v1);
                        if (Cf) { float2 o = make_float2(v0, v1); *(float2*)&Cf[(size_t)m * N + n] = o; }
                    } else {
                        float2 o = make_float2(v0, v1);
                        *(float2*)&Cf[(size_t)m * N + n] = o;
                    }
                }
            }
        }
    }
}

// ---------------- tiled conv (both dirs) + SiLU, with fused dt/dA ----------------
#define CT 16
#define CC 128
__global__ __launch_bounds__(256) void conv_silu_tile(const float* __restrict__ w,
                                                      const float* __restrict__ cb,
                                                      const float* __restrict__ dt_bias,
                                                      const float* __restrict__ A_log) {
    int cc = blockIdx.x;
    int tt = blockIdx.y;
    int b  = blockIdx.z;
    int c0 = cc * CC, t0 = tt * CT;
    __shared__ float tile[CT + 6][CC];
    __shared__ float wsh[4][CC];
    __shared__ float bsh[CC];

    if (cc == 0) {
        for (int i = threadIdx.x; i < CT * NHEADS; i += 256) {
            int r = i / NHEADS, h = i % NHEADS;
            int row = b * SEQ + t0 + r;
            float xv = g_zx[(size_t)row * DINPROJ + DINNER + CONVDIM + h] + dt_bias[h];
            float sp = (xv > 20.f) ? xv : log1pf(expf(xv));
            g_dt[(size_t)row * NHEADS + h] = sp;
            g_dA[(size_t)row * NHEADS + h] = expf(-expf(A_log[h]) * sp);
        }
    }

    for (int i = threadIdx.x; i < CC * 4; i += 256) {
        int c = i & (CC - 1), k = i >> 7;
        wsh[k][c] = w[(c0 + c) * 4 + k];
    }
    for (int i = threadIdx.x; i < CC; i += 256) bsh[i] = cb[c0 + i];

    const float* base = g_zx + (size_t)(b * SEQ) * DINPROJ + DINNER + c0;
    for (int i = threadIdx.x; i < (CT + 6) * CC; i += 256) {
        int r = i / CC, c = i % CC;
        int t = t0 - 3 + r;
        tile[r][c] = (t >= 0 && t < SEQ) ? base[(size_t)t * DINPROJ + c] : 0.f;
    }
    __syncthreads();

    for (int i = threadIdx.x; i < CT * CC; i += 256) {
        int r = i / CC, c = i % CC;
        int row = b * SEQ + t0 + r;
        float sf = bsh[c], sb2 = bsh[c];
        #pragma unroll
        for (int k = 0; k < 4; k++) {
            sf  = fmaf(wsh[k][c], tile[r + k][c],     sf);
            sb2 = fmaf(wsh[k][c], tile[r + 6 - k][c], sb2);
        }
        g_xBC[(size_t)row * CONVDIM + c0 + c]          = sf  / (1.f + expf(-sf));
        g_xBC[(size_t)(NTOK + row) * CONVDIM + c0 + c] = sb2 / (1.f + expf(-sb2));
    }
}

// ---------------- scan pass A: per-chunk local scan (h_init = 0) ----------------
__global__ __launch_bounds__(256) void scanA_kernel(const float* __restrict__ D_param) {
    int h = blockIdx.x, b = blockIdx.y;
    int dir = blockIdx.z / NC, chunk = blockIdx.z % NC;
    int idx = (dir * BSZ + b) * NHEADS + h;
    const float* xbc  = g_xBC + (size_t)(dir * NTOK + b * SEQ) * CONVDIM;
    float*       yout = g_y   + (size_t)(dir * NTOK + b * SEQ) * DINNER;
    int tid = threadIdx.x;
    int p = tid >> 2, q = tid & 3, nbase = q * 16;
    int s0 = chunk * LC;

    __shared__ float sdt[LC], sdA[LC];
    __shared__ __align__(16) float sbuf[2][192];

    for (int i = tid; i < LC; i += 256) {
        int t = dir ? (SEQ - 1 - (s0 + i)) : (s0 + i);
        sdt[i] = g_dt[(size_t)(b * SEQ + t) * NHEADS + h];
        sdA[i] = g_dA[(size_t)(b * SEQ + t) * NHEADS + h];
    }

    ull hr2[8];
    #pragma unroll
    for (int i = 0; i < 8; i++) hr2[i] = 0ull;
    float Dp = D_param[h];
    float cum = 1.f;

    auto gload = [&](int s) -> float {
        int t = dir ? (SEQ - 1 - s) : s;
        const float* r = xbc + (size_t)t * CONVDIM;
        if (tid < 64)  return r[h * 64 + tid];
        if (tid < 192) return r[DINNER + (tid - 64)];
        return 0.f;
    };

    float staged = gload(s0);

    for (int sl = 0; sl < LC; sl++) {
        int s = s0 + sl;
        int t = dir ? (SEQ - 1 - s) : s;
        int buf = sl & 1;
        if (tid < 192) sbuf[buf][tid] = staged;
        __syncthreads();
        if (sl + 1 < LC) staged = gload(s + 1);

        float xp  = sbuf[buf][p];
        float dtv = sdt[sl];
        float dAv = sdA[sl];
        float bx  = dtv * xp;
        cum *= dAv;

        ull B2[8], C2[8];
        const longlong2* Bp = (const longlong2*)&sbuf[buf][64 + nbase];
        const longlong2* Cp = (const longlong2*)&sbuf[buf][128 + nbase];
        #pragma unroll
        for (int i = 0; i < 4; i++) {
            longlong2 v = Bp[i]; B2[2 * i] = (ull)v.x; B2[2 * i + 1] = (ull)v.y;
            longlong2 u = Cp[i]; C2[2 * i] = (ull)u.x; C2[2 * i + 1] = (ull)u.y;
        }
        ull bx2 = pack2(bx, bx);
        ull dA2 = pack2(dAv, dAv);
        ull acca = 0ull, accb = 0ull;
        #pragma unroll
        for (int i = 0; i < 8; i += 2) {
            hr2[i]     = fma2(dA2, hr2[i],     mul2(bx2, B2[i]));
            hr2[i + 1] = fma2(dA2, hr2[i + 1], mul2(bx2, B2[i + 1]));
            acca = fma2(hr2[i],     C2[i],     acca);
            accb = fma2(hr2[i + 1], C2[i + 1], accb);
        }
        ull accp = add2(acca, accb);
        float a0, a1; unpack2(accp, a0, a1);
        float acc = a0 + a1;
        acc += __shfl_xor_sync(0xffffffffu, acc, 1);
        acc += __shfl_xor_sync(0xffffffffu, acc, 2);
        if (q == 0) yout[(size_t)t * DINNER + h * 64 + p] = fmaf(Dp, xp, acc);
        if (tid == 0) g_cum[(size_t)idx * SEQ + s] = cum;
    }

    float* st = g_state + ((size_t)idx * NC + chunk) * 4096 + tid * 16;
    #pragma unroll
    for (int i = 0; i < 8; i++) {
        float x0, x1; unpack2(hr2[i], x0, x1);
        st[2 * i] = x0; st[2 * i + 1] = x1;
    }
}

// ---------------- scan pass B: sequential chunk combine ----------------
__global__ __launch_bounds__(256) void scanB_kernel() {
    int h = blockIdx.x, b = blockIdx.y, dir = blockIdx.z;
    int idx = (dir * BSZ + b) * NHEADS + h;
    int tid = threadIdx.x;
    float hin[16];
    #pragma unroll
    for (int i = 0; i < 16; i++) hin[i] = 0.f;
    for (int c = 1; c < NC; c++) {
        float P = g_cum[(size_t)idx * SEQ + c * LC - 1];
        const float4* L = (const float4*)(g_state + ((size_t)idx * NC + (c - 1)) * 4096 + tid * 16);
        float4* O = (float4*)(g_init + ((size_t)idx * NC + c) * 4096 + tid * 16);
        #pragma unroll
        for (int i = 0; i < 4; i++) {
            float4 l = L[i];
            float4 o;
            o.x = fmaf(P, hin[4 * i],     l.x);
            o.y = fmaf(P, hin[4 * i + 1], l.y);
            o.z = fmaf(P, hin[4 * i + 2], l.z);
            o.w = fmaf(P, hin[4 * i + 3], l.w);
            hin[4 * i] = o.x; hin[4 * i + 1] = o.y; hin[4 * i + 2] = o.z; hin[4 * i + 3] = o.w;
            O[i] = o;
        }
    }
}

// ---------------- scan pass C: correction y += cumdA * (C . h_init) ----------------
__global__ __launch_bounds__(256) void scanC_kernel() {
    int h = blockIdx.x, b = blockIdx.y;
    int dir = blockIdx.z / (NC - 1), chunk = blockIdx.z % (NC - 1) + 1;
    int idx = (dir * BSZ + b) * NHEADS + h;
    const float* xbc  = g_xBC + (size_t)(dir * NTOK + b * SEQ) * CONVDIM;
    float*       yout = g_y   + (size_t)(dir * NTOK + b * SEQ) * DINNER;
    int tid = threadIdx.x;
    int p = tid >> 2, q = tid & 3, nbase = q * 16;
    int s0 = chunk * LC;

    __shared__ float scum[LC];
    __shared__ __align__(16) float sC[2][64];

    for (int i = tid; i < LC; i += 256)
        scum[i] = g_cum[(size_t)idx * SEQ + s0 + i];

    float hin[16];
    {
        const float4* H = (const float4*)(g_init + ((size_t)idx * NC + chunk) * 4096 + tid * 16);
        #pragma unroll
        for (int i = 0; i < 4; i++) {
            float4 v = H[i];
            hin[4 * i] = v.x; hin[4 * i + 1] = v.y; hin[4 * i + 2] = v.z; hin[4 * i + 3] = v.w;
        }
    }

    auto gloadC = [&](int s) -> float {
        int t = dir ? (SEQ - 1 - s) : s;
        if (tid < 64) return xbc[(size_t)t * CONVDIM + DINNER + DSTATE + tid];
        return 0.f;
    };

    float staged = gloadC(s0);

    for (int sl = 0; sl < LC; sl++) {
        int s = s0 + sl;
        int t = dir ? (SEQ - 1 - s) : s;
        int buf = sl & 1;
        if (tid < 64) sC[buf][tid] = staged;
        __syncthreads();
        if (sl + 1 < LC) staged = gloadC(s + 1);

        const float* Cv = &sC[buf][nbase];
        float acc = 0.f;
        #pragma unroll
        for (int i = 0; i < 16; i++) acc = fmaf(Cv[i], hin[i], acc);
        acc += __shfl_xor_sync(0xffffffffu, acc, 1);
        acc += __shfl_xor_sync(0xffffffffu, acc, 2);
        if (q == 0) {
            float* yp = &yout[(size_t)t * DINNER + h * 64 + p];
            *yp = fmaf(scum[sl], acc, *yp);
        }
    }
}

// ---------------- gate with SiLU(z), per-direction RMSNorm, sum dirs (fp16 out) ----------------
__global__ void gate_rms_kernel(const float* __restrict__ norm_w) {
    int row = blockIdx.x;
    __shared__ float gf[DINNER];
    __shared__ float gb[DINNER];
    const float* zr = g_zx + (size_t)row * DINPROJ;
    const float* yf = g_y  + (size_t)row * DINNER;
    const float* yb = g_y  + (size_t)(NTOK + row) * DINNER;
    float ssf = 0.f, ssb = 0.f;
    for (int c = threadIdx.x; c < DINNER; c += 256) {
        float zc = zr[c];
        float sz = zc / (1.f + expf(-zc));
        float a  = yf[c] * sz;
        float bb = yb[c] * sz;
        gf[c] = a; gb[c] = bb;
        ssf += a * a; ssb += bb * bb;
    }
    blockReduce2_256(ssf, ssb);
    float rf = rsqrtf(ssf / DINNER + LN_EPS);
    float rb = rsqrtf(ssb / DINNER + LN_EPS);
    __half* orow = g_gsumh + (size_t)row * DINNER;
    for (int c = threadIdx.x; c < DINNER; c += 256)
        orow[c] = __float2half((gf[c] * rf + gb[c] * rb) * norm_w[c]);
}

// ---------------- launch ----------------
extern "C" void kernel_launch(void* const* d_in, const int* in_sizes, int n_in,
                              void* d_out, int out_size) {
    const float* x         = (const float*)d_in[0];
    const float* in_proj_w = (const float*)d_in[1];
    const float* conv_w    = (const float*)d_in[2];
    const float* conv_b    = (const float*)d_in[3];
    const float* dt_bias   = (const float*)d_in[4];
    const float* A_log     = (const float*)d_in[5];
    const float* D_param   = (const float*)d_in[6];
    const float* norm_w    = (const float*)d_in[7];
    const float* out_proj_w= (const float*)d_in[8];
    const float* ln1_w     = (const float*)d_in[9];
    const float* ln1_b     = (const float*)d_in[10];
    const float* ln2_w     = (const float*)d_in[11];
    const float* ln2_b     = (const float*)d_in[12];
    const float* ff_w1     = (const float*)d_in[13];
    const float* ff_b1     = (const float*)d_in[14];
    const float* ff_w2     = (const float*)d_in[15];
    const float* ff_b2     = (const float*)d_in[16];
    float* out = (float*)d_out;

    void *p_zx, *p_xnh, *p_gsumh, *p_mh, *p_ff1h;
    void *p_wi, *p_wo, *p_w1, *p_w2, *p_part;
    cudaGetSymbolAddress(&p_zx,    g_zx);
    cudaGetSymbolAddress(&p_part,  g_part);
    cudaGetSymbolAddress(&p_xnh,   g_xnh);
    cudaGetSymbolAddress(&p_gsumh, g_gsumh);
    cudaGetSymbolAddress(&p_mh,    g_mh);
    cudaGetSymbolAddress(&p_ff1h,  g_ff1h);
    cudaGetSymbolAddress(&p_wi,    g_w_inproj_h);
    cudaGetSymbolAddress(&p_wo,    g_w_outproj_h);
    cudaGetSymbolAddress(&p_w1,    g_w_ff1_h);
    cudaGetSymbolAddress(&p_w2,    g_w_ff2_h);

    const int smemA = NSTAGE * (64 + 256) * 32 * sizeof(__half);   // 80 KB
    const int smemB = NSTAGE * (128 + 128) * 32 * sizeof(__half);  // 64 KB
    cudaFuncSetAttribute((const void*)hgemm<64,256,2,4>,
                         cudaFuncAttributeMaxDynamicSharedMemorySize, smemA);
    cudaFuncSetAttribute((const void*)hgemm<128,128,4,2>,
                         cudaFuncAttributeMaxDynamicSharedMemorySize, smemB);

    // 0) all weight conversions in one launch
    {
        int n0 = DINPROJ * DMODEL / 8;
        int n1 = DMODEL * DINNER / 8;
        int n2 = DFF * DMODEL / 8;
        int n3 = DMODEL * DFF / 8;
        int tot = n0 + n1 + n2 + n3;
        f2h_all_kernel<<<(tot + 255) / 256, 256>>>(
            in_proj_w, (__half*)p_wi, n0,
            out_proj_w, (__half*)p_wo, n1,
            ff_w1, (__half*)p_w1, n2,
            ff_w2, (__half*)p_w2, n3);
    }

    // 1) LN1 -> fp16 xn
    ln_kernel<<<NTOK, 256>>>(x, ln1_w, ln1_b, (__half*)p_xnh, DMODEL);

    // 2) in_proj GEMM: (1024,768)x(3224,768)^T -> fp32
    hgemm<64,256,2,4><<<dim3((DINPROJ + 255) / 256, NTOK / 64), 256, smemA>>>(
        (const __half*)p_xnh, (const __half*)p_wi,
        NTOK, DINPROJ, DMODEL, (float*)p_zx, nullptr, nullptr, nullptr, 0);

    // 3) conv + SiLU (both directions) with fused dt/dA
    conv_silu_tile<<<dim3(CONVDIM / CC, SEQ / CT, BSZ), 256>>>(conv_w, conv_b, dt_bias, A_log);

    // 4) chunked selective scan
    scanA_kernel<<<dim3(NHEADS, BSZ, 2 * NC), 256>>>(D_param);
    scanB_kernel<<<dim3(NHEADS, BSZ, 2), 256>>>();
    scanC_kernel<<<dim3(NHEADS, BSZ, 2 * (NC - 1)), 256>>>();

    // 5) gate + RMSNorm + direction-sum -> fp16
    gate_rms_kernel<<<NTOK, 256>>>(norm_w);

    // 6) out_proj GEMM split-K x6 -> partials
    hgemm<128,128,4,2><<<dim3(DMODEL / 128, NTOK / 128, KSPLIT), 256, smemB>>>(
        (const __half*)p_gsumh, (const __half*)p_wo,
        NTOK, DMODEL, DINNER, (float*)p_part, nullptr, nullptr, nullptr, 0);

    // 7) reduce partials + LN2 -> fp16 m
    reduce_ln2_kernel<<<NTOK, 256>>>(ln2_w, ln2_b);

    // 8) FF1 + bias + GELU -> fp16
    hgemm<64,256,2,4><<<dim3(DFF / 256, NTOK / 64), 256, smemA>>>(
        (const __half*)p_mh, (const __half*)p_w1,
        NTOK, DFF, DMODEL, nullptr, (__half*)p_ff1h, ff_b1, nullptr, 1);

    // 9) FF2 split-K x6 -> partials
    hgemm<128,128,4,2><<<dim3(DMODEL / 128, NTOK / 128, KSPLIT), 256, smemB>>>(
        (const __half*)p_ff1h, (const __half*)p_w2,
        NTOK, DMODEL, DFF, (float*)p_part, nullptr, nullptr, nullptr, 0);

    // 10) reduce partials + bias + residual -> out
    reduce_out_kernel<<<(NTOK * DMODEL / 4 + 255) / 256, 256>>>(ff_b2, x, out);
}